// round 1
// baseline (speedup 1.0000x reference)
#include <cuda_runtime.h>
#include <cstdint>

#define NB    4
#define NS    1024
#define NHID  1024
#define NHEAD 16
#define NHD   64
#define NTAB  127
#define NTABP 128
#define BHS   (NB*NHEAD*NS)   // 65536

// ---------------- scratch (device globals; no allocations allowed) ----------------
__device__ float g_q [BHS*NHD];          // [b,n,s,d]
__device__ float g_k [BHS*NHD];
__device__ float g_v [BHS*NHD];
__device__ float g_qb[BHS*NTABP];        // q . rp_k[t]
__device__ float g_wb[BHS*NTABP];        // aggregated softmax weights per table row
__device__ float g_w [67108864];         // [b,n,i,j] probabilities (256MB)
__device__ float g_ao[NB*NS*NHID];       // attention out in [b,s,n,d] (= hidden layout)

// =============================================================================
// K1: QKV projections.  out[b,n,s,d] = X[b,s,:] . W[n,:,d] + bias[n,d]
// GEMM M=4096, N=64 (one head per block-col), K=1024.  grid (32, 16, 3)
// =============================================================================
__global__ __launch_bounds__(256) void proj_kernel(
    const float* __restrict__ xq, const float* __restrict__ xk, const float* __restrict__ xv,
    const float* __restrict__ wq, const float* __restrict__ wk, const float* __restrict__ wv,
    const float* __restrict__ bq, const float* __restrict__ bk, const float* __restrict__ bv)
{
    __shared__ float As[128*17];
    __shared__ float Bs[16*64];

    const float* X; const float* W; const float* bias; float* out;
    if (blockIdx.z == 0)      { X = xq; W = wq; bias = bq; out = g_q; }
    else if (blockIdx.z == 1) { X = xk; W = wk; bias = bk; out = g_k; }
    else                      { X = xv; W = wv; bias = bv; out = g_v; }

    const int n  = blockIdx.y;
    const int m0 = blockIdx.x * 128;
    const int tid = threadIdx.x;
    const int tr = tid >> 4;   // 0..15 -> rows tr*8..tr*8+7
    const int tc = tid & 15;   // cols tc*4..tc*4+3

    const float* Wn = W + (size_t)n * NHID * NHD;
    float acc[8][4];
    #pragma unroll
    for (int r = 0; r < 8; r++)
        #pragma unroll
        for (int c = 0; c < 4; c++) acc[r][c] = 0.f;

    for (int kt = 0; kt < NHID; kt += 16) {
        #pragma unroll
        for (int i = 0; i < 8; i++) {          // A tile 128x16
            int e = tid + i*256;
            int m = e >> 4, k = e & 15;
            As[m*17 + k] = X[(size_t)(m0+m)*NHID + kt + k];
        }
        #pragma unroll
        for (int i = 0; i < 4; i++) {          // B tile 16x64 (contiguous in d)
            int e = tid + i*256;
            int k = e >> 6, c = e & 63;
            Bs[k*64 + c] = Wn[(size_t)(kt+k)*NHD + c];
        }
        __syncthreads();
        #pragma unroll
        for (int k = 0; k < 16; k++) {
            float4 b4 = *(const float4*)&Bs[k*64 + tc*4];
            #pragma unroll
            for (int rr = 0; rr < 8; rr++) {
                float a = As[(tr*8+rr)*17 + k];
                acc[rr][0] += a*b4.x; acc[rr][1] += a*b4.y;
                acc[rr][2] += a*b4.z; acc[rr][3] += a*b4.w;
            }
        }
        __syncthreads();
    }
    #pragma unroll
    for (int rr = 0; rr < 8; rr++) {
        int m = m0 + tr*8 + rr;
        int b = m >> 10, s = m & 1023;
        float* orow = out + ((size_t)((b*NHEAD + n)*NS + s))*NHD + tc*4;
        #pragma unroll
        for (int cc = 0; cc < 4; cc++)
            orow[cc] = acc[rr][cc] + bias[n*NHD + tc*4 + cc];
    }
}

// =============================================================================
// K2: g_qb[row, t] = q[row,:] . rp_k[t,:]   (row = b*H*S flattened; t<127)
// grid 8192 blocks x 256 thr; 8 q-rows per block; table cached in smem.
// =============================================================================
__global__ __launch_bounds__(256) void qbias_kernel(const float* __restrict__ rpk)
{
    __shared__ float tab[NTAB*65];
    __shared__ float qs[8*65];
    const int tid  = threadIdx.x;
    const int row0 = blockIdx.x * 8;

    for (int e = tid; e < NTAB*NHD; e += 256) {
        int t = e >> 6, k = e & 63;
        tab[t*65 + k] = rpk[e];
    }
    for (int e = tid; e < 8*NHD; e += 256) {
        int r = e >> 6, k = e & 63;
        qs[r*65 + k] = g_q[(size_t)(row0 + r)*NHD + k];
    }
    __syncthreads();
    for (int e = tid; e < 8*NTAB; e += 256) {
        int r = e / NTAB, t = e % NTAB;
        float s = 0.f;
        #pragma unroll
        for (int k = 0; k < NHD; k++) s += qs[r*65+k] * tab[t*65+k];
        g_qb[(size_t)(row0 + r)*NTABP + t] = s;
    }
}

// =============================================================================
// K3: scores + softmax + wb.  Block = one (b,n) x 16 query rows.
// scores[i,j] = (q_i.k_j + qb[i, clip(j-i)+63]) / 8 ; softmax over j ;
// writes prob row to g_w and the 127 aggregated weights to g_wb.
// dynamic smem: sc 16*1024 | ks 256*65 | qs 16*65 | qbs 16*128
// =============================================================================
__global__ __launch_bounds__(256) void attn_scores_kernel()
{
    extern __shared__ float sm3[];
    float* sc  = sm3;                 // 16384
    float* ks  = sc + 16*1024;        // 16640
    float* qs  = ks + 256*65;         // 1040
    float* qbs = qs + 16*65;          // 2048

    const int bn  = blockIdx.y;
    const int i0  = blockIdx.x * 16;
    const int tid = threadIdx.x;
    const int tr   = tid >> 6;    // 0..3 : rows tr + 4u
    const int tcol = tid & 63;    // cols tcol + 64u (within 256-chunk)

    const size_t qbase = ((size_t)bn * NS + i0) * NHD;
    for (int e = tid; e < 16*64; e += 256) {
        int r = e >> 6, k = e & 63;
        qs[r*65 + k] = g_q[qbase + (size_t)r*NHD + k];
    }
    for (int e = tid; e < 16*NTAB; e += 256) {
        int r = e / NTAB, t = e % NTAB;
        qbs[r*NTABP + t] = g_qb[((size_t)bn*NS + i0 + r)*NTABP + t];
    }

    const size_t kbase = (size_t)bn * NS * NHD;
    for (int jc = 0; jc < 4; jc++) {
        const int j0 = jc * 256;
        __syncthreads();                       // ks reuse + (first iter) qs ready
        for (int e4 = tid; e4 < 256*16; e4 += 256) {
            int j = e4 >> 4, k4 = e4 & 15;
            float4 v = *(const float4*)&g_k[kbase + (size_t)(j0 + j)*NHD + k4*4];
            float* d = &ks[j*65 + k4*4];
            d[0]=v.x; d[1]=v.y; d[2]=v.z; d[3]=v.w;
        }
        __syncthreads();

        float acc[4][4];
        #pragma unroll
        for (int a = 0; a < 4; a++)
            #pragma unroll
            for (int b = 0; b < 4; b++) acc[a][b] = 0.f;

        #pragma unroll
        for (int k = 0; k < 64; k++) {
            float a[4], b[4];
            #pragma unroll
            for (int u = 0; u < 4; u++) a[u] = qs[(tr + 4*u)*65 + k];      // broadcast
            #pragma unroll
            for (int u = 0; u < 4; u++) b[u] = ks[(tcol + 64*u)*65 + k];   // conflict-free
            #pragma unroll
            for (int ur = 0; ur < 4; ur++)
                #pragma unroll
                for (int uc = 0; uc < 4; uc++) acc[ur][uc] += a[ur]*b[uc];
        }
        #pragma unroll
        for (int ur = 0; ur < 4; ur++) {
            int r = tr + 4*ur;
            int i = i0 + r;
            #pragma unroll
            for (int uc = 0; uc < 4; uc++) {
                int j = j0 + tcol + 64*uc;
                int d = j - i;
                d = d < -63 ? -63 : (d > 63 ? 63 : d);
                sc[r*1024 + j] = (acc[ur][uc] + qbs[r*NTABP + d + 63]) * 0.125f;
            }
        }
    }
    __syncthreads();

    // softmax + wb: warp w owns rows {w, w+8}
    const int warp = tid >> 5, lane = tid & 31;
    for (int rw = 0; rw < 2; rw++) {
        const int r = warp + 8*rw;
        const int i = i0 + r;
        float* row = sc + r*1024;

        float mx = -1e30f;
        #pragma unroll
        for (int q = 0; q < 32; q++) mx = fmaxf(mx, row[lane + 32*q]);
        #pragma unroll
        for (int off = 16; off; off >>= 1) mx = fmaxf(mx, __shfl_xor_sync(0xffffffffu, mx, off));

        float sum = 0.f;
        #pragma unroll
        for (int q = 0; q < 32; q++) {
            float e = __expf(row[lane + 32*q] - mx);
            row[lane + 32*q] = e;
            sum += e;
        }
        #pragma unroll
        for (int off = 16; off; off >>= 1) sum += __shfl_xor_sync(0xffffffffu, sum, off);
        const float inv = 1.f / sum;

        float lsum = 0.f, rsum = 0.f;
        const size_t wrow = ((size_t)bn*NS + i) * NS;
        #pragma unroll
        for (int q = 0; q < 32; q++) {
            int j = lane + 32*q;
            float v = row[j] * inv;
            row[j] = v;
            g_w[wrow + j] = v;
            if (j <= i - 63) lsum += v;
            if (j >= i + 63) rsum += v;
        }
        #pragma unroll
        for (int off = 16; off; off >>= 1) {
            lsum += __shfl_xor_sync(0xffffffffu, lsum, off);
            rsum += __shfl_xor_sync(0xffffffffu, rsum, off);
        }
        __syncwarp();

        const size_t wbrow = ((size_t)bn*NS + i) * NTABP;
        for (int t = lane; t < NTAB; t += 32) {
            float v;
            if (t == 0)        v = lsum;
            else if (t == 126) v = rsum;
            else {
                int j = i + t - 63;
                v = (j >= 0 && j < NS) ? row[j] : 0.f;
            }
            g_wb[wbrow + t] = v;
        }
    }
}

// =============================================================================
// K4: out[b,n,i,:] = w[i,:] @ v + wb[i,:] @ rp_v  -> g_ao in [b,s,n,d]
// Block = one (b,n) x 64 rows x all 64 d. dynamic smem ~99KB.
// =============================================================================
__global__ __launch_bounds__(256) void attn_out_kernel(const float* __restrict__ rpv)
{
    extern __shared__ float sm4[];
    float* ws  = sm4;                 // 64*65
    float* vs  = ws + 64*65;          // 64*65
    float* wbs = vs + 64*65;          // 64*128
    float* rvs = wbs + 64*128;        // 127*65

    const int bn  = blockIdx.y;
    const int i0  = blockIdx.x * 64;
    const int tid = threadIdx.x;
    const int rt = tid >> 4;   // rows rt + 16u
    const int ct = tid & 15;   // cols ct + 16u

    for (int e = tid; e < NTAB*NHD; e += 256) {
        int t = e >> 6, k = e & 63;
        rvs[t*65 + k] = rpv[e];
    }
    for (int e = tid; e < 64*NTAB; e += 256) {
        int r = e / NTAB, t = e % NTAB;
        wbs[r*NTABP + t] = g_wb[((size_t)bn*NS + i0 + r)*NTABP + t];
    }

    float acc[4][4];
    #pragma unroll
    for (int a = 0; a < 4; a++)
        #pragma unroll
        for (int b = 0; b < 4; b++) acc[a][b] = 0.f;

    const size_t wbase = ((size_t)bn*NS + i0)*NS;
    const size_t vbase = (size_t)bn*NS*NHD;

    for (int jt = 0; jt < NS; jt += 64) {
        __syncthreads();
        for (int e4 = tid; e4 < 64*16; e4 += 256) {
            int r = e4 >> 4, k4 = e4 & 15;
            float4 v = *(const float4*)&g_w[wbase + (size_t)r*NS + jt + k4*4];
            float* d = &ws[r*65 + k4*4];
            d[0]=v.x; d[1]=v.y; d[2]=v.z; d[3]=v.w;
        }
        for (int e4 = tid; e4 < 64*16; e4 += 256) {
            int j = e4 >> 4, k4 = e4 & 15;
            float4 v = *(const float4*)&g_v[vbase + (size_t)(jt + j)*NHD + k4*4];
            float* d = &vs[j*65 + k4*4];
            d[0]=v.x; d[1]=v.y; d[2]=v.z; d[3]=v.w;
        }
        __syncthreads();
        #pragma unroll
        for (int k = 0; k < 64; k++) {
            float a[4], b[4];
            #pragma unroll
            for (int u = 0; u < 4; u++) a[u] = ws[(rt + 16*u)*65 + k];   // broadcast
            #pragma unroll
            for (int u = 0; u < 4; u++) b[u] = vs[k*65 + ct + 16*u];     // conflict-free
            #pragma unroll
            for (int ur = 0; ur < 4; ur++)
                #pragma unroll
                for (int uc = 0; uc < 4; uc++) acc[ur][uc] += a[ur]*b[uc];
        }
    }
    __syncthreads();
    // relative-position value bias: acc += wbs @ rvs
    for (int t = 0; t < NTAB; t++) {
        float a[4], b[4];
        #pragma unroll
        for (int u = 0; u < 4; u++) a[u] = wbs[(rt + 16*u)*NTABP + t];
        #pragma unroll
        for (int u = 0; u < 4; u++) b[u] = rvs[t*65 + ct + 16*u];
        #pragma unroll
        for (int ur = 0; ur < 4; ur++)
            #pragma unroll
            for (int uc = 0; uc < 4; uc++) acc[ur][uc] += a[ur]*b[uc];
    }

    const int b = bn >> 4, n = bn & 15;
    #pragma unroll
    for (int ur = 0; ur < 4; ur++) {
        int i = i0 + rt + 16*ur;
        #pragma unroll
        for (int uc = 0; uc < 4; uc++) {
            int d = ct + 16*uc;
            g_ao[(((size_t)b*NS + i)*NHEAD + n)*NHD + d] = acc[ur][uc];
        }
    }
}

// =============================================================================
// K5: final FC.  out[m,o] = ao[m,:] . Wfc[o,:] + bfc[o]   (NT GEMM)
// grid (64, 16), 64x64 tiles, K-tile 32.
// =============================================================================
__global__ __launch_bounds__(256) void fc_kernel(
    const float* __restrict__ wfc, const float* __restrict__ bfc, float* __restrict__ out)
{
    __shared__ float as[64*33];
    __shared__ float bs[64*33];
    const int m0 = blockIdx.x * 64;
    const int o0 = blockIdx.y * 64;
    const int tid = threadIdx.x;
    const int rt = tid >> 4, ct = tid & 15;

    float acc[4][4];
    #pragma unroll
    for (int a = 0; a < 4; a++)
        #pragma unroll
        for (int b = 0; b < 4; b++) acc[a][b] = 0.f;

    for (int kt = 0; kt < NHID; kt += 32) {
        __syncthreads();
        for (int e4 = tid; e4 < 64*8; e4 += 256) {
            int r = e4 >> 3, k4 = e4 & 7;
            float4 v = *(const float4*)&g_ao[(size_t)(m0+r)*NHID + kt + k4*4];
            float* d = &as[r*33 + k4*4];
            d[0]=v.x; d[1]=v.y; d[2]=v.z; d[3]=v.w;
        }
        for (int e4 = tid; e4 < 64*8; e4 += 256) {
            int c = e4 >> 3, k4 = e4 & 7;
            float4 v = *(const float4*)&wfc[(size_t)(o0+c)*NHID + kt + k4*4];
            float* d = &bs[c*33 + k4*4];
            d[0]=v.x; d[1]=v.y; d[2]=v.z; d[3]=v.w;
        }
        __syncthreads();
        #pragma unroll
        for (int k = 0; k < 32; k++) {
            float a[4], b[4];
            #pragma unroll
            for (int u = 0; u < 4; u++) a[u] = as[(rt + 16*u)*33 + k];   // broadcast
            #pragma unroll
            for (int u = 0; u < 4; u++) b[u] = bs[(ct + 16*u)*33 + k];   // conflict-free
            #pragma unroll
            for (int ur = 0; ur < 4; ur++)
                #pragma unroll
                for (int uc = 0; uc < 4; uc++) acc[ur][uc] += a[ur]*b[uc];
        }
    }
    #pragma unroll
    for (int ur = 0; ur < 4; ur++) {
        int m = m0 + rt + 16*ur;
        #pragma unroll
        for (int uc = 0; uc < 4; uc++) {
            int o = o0 + ct + 16*uc;
            out[(size_t)m*NHID + o] = acc[ur][uc] + bfc[o];
        }
    }
}

// =============================================================================
extern "C" void kernel_launch(void* const* d_in, const int* in_sizes, int n_in,
                              void* d_out, int out_size)
{
    (void)in_sizes; (void)n_in; (void)out_size;
    const float* query = (const float*)d_in[0];
    const float* key   = (const float*)d_in[1];
    const float* value = (const float*)d_in[2];
    const float* Wq    = (const float*)d_in[3];
    const float* Wk    = (const float*)d_in[4];
    const float* Wv    = (const float*)d_in[5];
    const float* bq    = (const float*)d_in[6];
    const float* bk    = (const float*)d_in[7];
    const float* bv    = (const float*)d_in[8];
    const float* rpk   = (const float*)d_in[9];
    const float* rpv   = (const float*)d_in[10];
    const float* Wfc   = (const float*)d_in[11];
    const float* bfc   = (const float*)d_in[12];
    float* out = (float*)d_out;

    const int SMEM_K3 = (16*1024 + 256*65 + 16*65 + 16*NTABP) * 4;   // 144448 B
    const int SMEM_K4 = (64*65*2 + 64*NTABP + NTAB*65) * 4;          //  99068 B
    cudaFuncSetAttribute(attn_scores_kernel, cudaFuncAttributeMaxDynamicSharedMemorySize, SMEM_K3);
    cudaFuncSetAttribute(attn_out_kernel,    cudaFuncAttributeMaxDynamicSharedMemorySize, SMEM_K4);

    proj_kernel<<<dim3(32, 16, 3), 256>>>(query, key, value, Wq, Wk, Wv, bq, bk, bv);
    qbias_kernel<<<8192, 256>>>(rpk);
    attn_scores_kernel<<<dim3(64, 64), 256, SMEM_K3>>>();
    attn_out_kernel<<<dim3(16, 64), 256, SMEM_K4>>>(rpv);
    fc_kernel<<<dim3(64, 16), 256>>>(Wfc, bfc, out);
}

// round 3
// speedup vs baseline: 1.8573x; 1.8573x over previous
#include <cuda_runtime.h>
#include <cstdint>

#define NB    4
#define NS    1024
#define NHID  1024
#define NHEAD 16
#define NHD   64
#define NTAB  127
#define NTABP 128
#define BHS   (NB*NHEAD*NS)   // 65536
#define NM    (NB*NS)         // 4096

// ---------------- scratch (device globals; no allocations allowed) ----------------
__device__ float g_x  [(size_t)3*NM*NHID];            // tf32-rounded inputs (q,k,v)
__device__ float g_wt [(size_t)3*NHEAD*NHD*NHID];     // W^T per head, tf32-rounded
__device__ float g_wfc[(size_t)NHID*NHID];            // Wfc tf32-rounded ([o][k])
__device__ float g_q  [(size_t)BHS*NHD];              // fp32 q  [bn][s][d]
__device__ float g_k  [(size_t)BHS*NHD];              // fp32 k  [bn][s][d]
__device__ float g_vt [(size_t)BHS*NHD];              // tf32 v^T [bn][d][s]
__device__ float g_qb [(size_t)BHS*NTABP];            // q . rp_k[t]  fp32
__device__ float g_w  [(size_t)BHS*NS];               // probs, tf32-rounded (256MB)
__device__ float g_wb [(size_t)BHS*NTABP];            // table weights, tf32-rounded
__device__ float g_rpvt[NHD*NTABP];                   // rp_v^T tf32-rounded (col 127 = 0)
__device__ float g_ao [(size_t)NM*NHID];              // attn out [b*s][hid], tf32-rounded

// =============================== helpers =====================================
__device__ __forceinline__ uint32_t s2u(const void* p) {
    uint32_t a;
    asm("{ .reg .u64 t; cvta.to.shared.u64 t, %1; cvt.u32.u64 %0, t; }" : "=r"(a) : "l"(p));
    return a;
}
__device__ __forceinline__ void cpa16(uint32_t d, const void* s) {
    asm volatile("cp.async.cg.shared.global [%0], [%1], 16;" :: "r"(d), "l"(s));
}
__device__ __forceinline__ void cp_commit() { asm volatile("cp.async.commit_group;"); }
template<int N> __device__ __forceinline__ void cp_wait() {
    asm volatile("cp.async.wait_group %0;" :: "n"(N));
}
__device__ __forceinline__ float tf32r(float x) {
    uint32_t u;
    asm("cvt.rna.tf32.f32 %0, %1;" : "=r"(u) : "f"(x));
    return __uint_as_float(u);
}
__device__ __forceinline__ void mma8(float* c, const uint32_t* a, const uint32_t* b) {
    asm volatile(
        "mma.sync.aligned.m16n8k8.row.col.f32.tf32.tf32.f32 "
        "{%0,%1,%2,%3}, {%4,%5,%6,%7}, {%8,%9}, {%0,%1,%2,%3};"
        : "+f"(c[0]), "+f"(c[1]), "+f"(c[2]), "+f"(c[3])
        : "r"(a[0]), "r"(a[1]), "r"(a[2]), "r"(a[3]), "r"(b[0]), "r"(b[1]));
}

#define AS_STRIDE 40   // 128 x 40 floats per A buffer (bank-conflict-free frags)
#define BS_STRIDE 36   // 64 x 36 floats per B buffer
#define AS_BUF (128*AS_STRIDE)
#define BS_BUF (64*BS_STRIDE)
#define SMEM_GEMM ((2*AS_BUF + 2*BS_BUF)*4)   // 59392 B

// A tile 128x32 from global (lda elems), 128 threads, 8 float4 each (coalesced)
__device__ __forceinline__ void load_a(uint32_t as, const float* __restrict__ A, int lda, int tid) {
    #pragma unroll
    for (int i = 0; i < 8; i++) {
        int idx = tid + i*128;
        int m = idx >> 3, kq = idx & 7;
        cpa16(as + (uint32_t)(m*AS_STRIDE + kq*4)*4, A + (size_t)m*lda + kq*4);
    }
}
// B tile 64x32
__device__ __forceinline__ void load_b(uint32_t bs, const float* __restrict__ B, int ldb, int tid) {
    #pragma unroll
    for (int i = 0; i < 4; i++) {
        int idx = tid + i*128;
        int nn = idx >> 3, kq = idx & 7;
        cpa16(bs + (uint32_t)(nn*BS_STRIDE + kq*4)*4, B + (size_t)nn*ldb + kq*4);
    }
}

// warp tile 64x32: 4 m-frags x 4 n-frags, 4 k-steps per 32-k tile
__device__ __forceinline__ void mma_tile(const float* __restrict__ As, const float* __restrict__ Bs,
                                         float acc[4][4][4], int wm, int wn, int lane) {
    const int r = lane >> 2, cq = lane & 3;
    #pragma unroll
    for (int ks = 0; ks < 4; ks++) {
        const int k0 = ks*8;
        uint32_t a[4][4], b[4][2];
        #pragma unroll
        for (int f = 0; f < 4; f++) {
            const int bm = wm*64 + f*16;
            a[f][0] = __float_as_uint(As[(bm + r    )*AS_STRIDE + k0 + cq    ]);
            a[f][1] = __float_as_uint(As[(bm + r + 8)*AS_STRIDE + k0 + cq    ]);
            a[f][2] = __float_as_uint(As[(bm + r    )*AS_STRIDE + k0 + cq + 4]);
            a[f][3] = __float_as_uint(As[(bm + r + 8)*AS_STRIDE + k0 + cq + 4]);
        }
        #pragma unroll
        for (int g = 0; g < 4; g++) {
            const int bn = wn*32 + g*8;
            b[g][0] = __float_as_uint(Bs[(bn + r)*BS_STRIDE + k0 + cq    ]);
            b[g][1] = __float_as_uint(Bs[(bn + r)*BS_STRIDE + k0 + cq + 4]);
        }
        #pragma unroll
        for (int f = 0; f < 4; f++)
            #pragma unroll
            for (int g = 0; g < 4; g++) mma8(acc[f][g], a[f], b[g]);
    }
}

// =============================================================================
// C0: tf32-round copy.  dst slice selected by mode (0/1/2 = q/k/v, 3 = Wfc)
// =============================================================================
__global__ __launch_bounds__(256) void cvt_kernel(const float* __restrict__ in, int mode, int n4)
{
    int i = blockIdx.x * 256 + threadIdx.x;
    if (i >= n4) return;
    float* dst = (mode < 3) ? (g_x + (size_t)mode*NM*NHID) : g_wfc;
    float4 v = ((const float4*)in)[i];
    v.x = tf32r(v.x); v.y = tf32r(v.y); v.z = tf32r(v.z); v.w = tf32r(v.w);
    ((float4*)dst)[i] = v;
}

// C1: transpose + round per-head weights  W[op][n][h][d] -> Wt[op][n][d][h]
__global__ __launch_bounds__(256) void wt_kernel(const float* __restrict__ wq,
                                                 const float* __restrict__ wk,
                                                 const float* __restrict__ wv)
{
    __shared__ float tile[64*65];
    const int hb = blockIdx.x, n = blockIdx.y, op = blockIdx.z;
    const float* W = (op==0 ? wq : (op==1 ? wk : wv)) + ((size_t)n*NHID + hb*64)*NHD;
    for (int e = threadIdx.x; e < 64*64; e += 256) {
        int h = e >> 6, d = e & 63;
        tile[h*65 + d] = W[(size_t)h*NHD + d];
    }
    __syncthreads();
    size_t ob = ((size_t)(op*NHEAD + n)*NHD)*NHID + hb*64;
    for (int e = threadIdx.x; e < 64*64; e += 256) {
        int d = e >> 6, h = e & 63;
        g_wt[ob + (size_t)d*NHID + h] = tf32r(tile[h*65 + d]);
    }
}

// C2: rp_v^T rounded + padded
__global__ __launch_bounds__(256) void rpvt_kernel(const float* __restrict__ rpv)
{
    int e = blockIdx.x * 256 + threadIdx.x;
    if (e >= NHD*NTABP) return;
    int d = e >> 7, t = e & 127;
    float v = (t < NTAB) ? rpv[(size_t)t*NHD + d] : 0.f;
    g_rpvt[(size_t)d*NTABP + t] = tf32r(v);
}

// =============================================================================
// K1: QKV projection via mma.sync tf32.  grid (32 mtiles, 16 heads, 3 ops).
// =============================================================================
__global__ __launch_bounds__(128) void proj_mma(const float* __restrict__ bq_,
                                                const float* __restrict__ bk_,
                                                const float* __restrict__ bv_)
{
    extern __shared__ float sm[];
    float* As = sm;
    float* Bs = sm + 2*AS_BUF;
    const int tid = threadIdx.x, lane = tid & 31, wid = tid >> 5;
    const int wm = wid & 1, wn = wid >> 1;
    const int m0 = blockIdx.x * 128, n = blockIdx.y, op = blockIdx.z;

    const float* A0 = g_x + (size_t)op*NM*NHID + (size_t)m0*NHID;
    const float* B0 = g_wt + (size_t)(op*NHEAD + n)*NHD*NHID;

    float acc[4][4][4];
    #pragma unroll
    for (int f = 0; f < 4; f++)
        #pragma unroll
        for (int g = 0; g < 4; g++)
            #pragma unroll
            for (int e = 0; e < 4; e++) acc[f][g][e] = 0.f;

    load_a(s2u(As), A0, NHID, tid);
    load_b(s2u(Bs), B0, NHID, tid);
    cp_commit();
    for (int kt = 0; kt < 32; kt++) {
        if (kt + 1 < 32) {
            int nb = (kt+1) & 1;
            load_a(s2u(As + nb*AS_BUF), A0 + (kt+1)*32, NHID, tid);
            load_b(s2u(Bs + nb*BS_BUF), B0 + (kt+1)*32, NHID, tid);
            cp_commit();
            cp_wait<1>();
        } else cp_wait<0>();
        __syncthreads();
        mma_tile(As + (kt&1)*AS_BUF, Bs + (kt&1)*BS_BUF, acc, wm, wn, lane);
        __syncthreads();
    }

    const int b = m0 >> 10, s0 = m0 & 1023;
    const int bn = b*NHEAD + n;
    const int r = lane >> 2, cq = lane & 3;

    if (op < 2) {
        const float* bias = op ? bk_ : bq_;
        float* out = (op ? g_k : g_q) + ((size_t)bn*NS + s0)*NHD;
        #pragma unroll
        for (int f = 0; f < 4; f++) {
            int ml = wm*64 + f*16 + r;
            #pragma unroll
            for (int g = 0; g < 4; g++) {
                int d = wn*32 + g*8 + 2*cq;
                float b0 = bias[n*NHD + d], b1 = bias[n*NHD + d + 1];
                *(float2*)&out[(size_t)ml*NHD + d]     = make_float2(acc[f][g][0]+b0, acc[f][g][1]+b1);
                *(float2*)&out[(size_t)(ml+8)*NHD + d] = make_float2(acc[f][g][2]+b0, acc[f][g][3]+b1);
            }
        }
    } else {
        float* stage = As;                       // 65*132 <= 2*AS_BUF, reuse
        #pragma unroll
        for (int f = 0; f < 4; f++) {
            int ml = wm*64 + f*16 + r;
            #pragma unroll
            for (int g = 0; g < 4; g++) {
                int d = wn*32 + g*8 + 2*cq;
                float b0 = bv_[n*NHD + d], b1 = bv_[n*NHD + d + 1];
                stage[(d  )*132 + ml    ] = acc[f][g][0] + b0;
                stage[(d+1)*132 + ml    ] = acc[f][g][1] + b1;
                stage[(d  )*132 + ml + 8] = acc[f][g][2] + b0;
                stage[(d+1)*132 + ml + 8] = acc[f][g][3] + b1;
            }
        }
        __syncthreads();
        const int d = tid >> 1, half = tid & 1;
        float* dst = g_vt + ((size_t)bn*NHD + d)*NS + s0 + half*64;
        #pragma unroll
        for (int j4 = 0; j4 < 16; j4++) {
            float4 v;
            v.x = tf32r(stage[d*132 + half*64 + j4*4 + 0]);
            v.y = tf32r(stage[d*132 + half*64 + j4*4 + 1]);
            v.z = tf32r(stage[d*132 + half*64 + j4*4 + 2]);
            v.w = tf32r(stage[d*132 + half*64 + j4*4 + 3]);
            ((float4*)dst)[j4] = v;
        }
    }
}

// =============================================================================
// K2: g_qb[row, t] = q[row,:] . rp_k[t,:]   (fp32 exact, feeds softmax logits)
// =============================================================================
__global__ __launch_bounds__(256) void qbias_kernel(const float* __restrict__ rpk)
{
    __shared__ float tab[NTAB*65];
    __shared__ float qs[8*65];
    const int tid  = threadIdx.x;
    const int row0 = blockIdx.x * 8;

    for (int e = tid; e < NTAB*NHD; e += 256) {
        int t = e >> 6, k = e & 63;
        tab[t*65 + k] = rpk[e];
    }
    for (int e = tid; e < 8*NHD; e += 256) {
        int r = e >> 6, k = e & 63;
        qs[r*65 + k] = g_q[(size_t)(row0 + r)*NHD + k];
    }
    __syncthreads();
    for (int e = tid; e < 8*NTAB; e += 256) {
        int r = e / NTAB, t = e % NTAB;
        float s = 0.f;
        #pragma unroll
        for (int k = 0; k < NHD; k++) s += qs[r*65+k] * tab[t*65+k];
        g_qb[(size_t)(row0 + r)*NTABP + t] = s;
    }
}

// =============================================================================
// K3: scores + softmax (fp32).  Writes probs (tf32-rounded) and wb.
// =============================================================================
__global__ __launch_bounds__(256) void attn_scores_kernel()
{
    extern __shared__ float sm3[];
    float* sc  = sm3;                 // 16*1024
    float* ks  = sc + 16*1024;        // 256*65
    float* qs  = ks + 256*65;         // 16*65
    float* qbs = qs + 16*65;          // 16*128

    const int bn  = blockIdx.y;
    const int i0  = blockIdx.x * 16;
    const int tid = threadIdx.x;
    const int tr   = tid >> 6;
    const int tcol = tid & 63;

    const size_t qbase = ((size_t)bn * NS + i0) * NHD;
    for (int e = tid; e < 16*64; e += 256) {
        int r = e >> 6, k = e & 63;
        qs[r*65 + k] = g_q[qbase + (size_t)r*NHD + k];
    }
    for (int e = tid; e < 16*NTAB; e += 256) {
        int r = e / NTAB, t = e % NTAB;
        qbs[r*NTABP + t] = g_qb[((size_t)bn*NS + i0 + r)*NTABP + t];
    }

    const size_t kbase = (size_t)bn * NS * NHD;
    for (int jc = 0; jc < 4; jc++) {
        const int j0 = jc * 256;
        __syncthreads();
        for (int e4 = tid; e4 < 256*16; e4 += 256) {
            int j = e4 >> 4, k4 = e4 & 15;
            float4 v = *(const float4*)&g_k[kbase + (size_t)(j0 + j)*NHD + k4*4];
            float* d = &ks[j*65 + k4*4];
            d[0]=v.x; d[1]=v.y; d[2]=v.z; d[3]=v.w;
        }
        __syncthreads();

        float acc[4][4];
        #pragma unroll
        for (int a = 0; a < 4; a++)
            #pragma unroll
            for (int b = 0; b < 4; b++) acc[a][b] = 0.f;

        #pragma unroll
        for (int k = 0; k < 64; k++) {
            float a[4], b[4];
            #pragma unroll
            for (int u = 0; u < 4; u++) a[u] = qs[(tr + 4*u)*65 + k];
            #pragma unroll
            for (int u = 0; u < 4; u++) b[u] = ks[(tcol + 64*u)*65 + k];
            #pragma unroll
            for (int ur = 0; ur < 4; ur++)
                #pragma unroll
                for (int uc = 0; uc < 4; uc++) acc[ur][uc] += a[ur]*b[uc];
        }
        #pragma unroll
        for (int ur = 0; ur < 4; ur++) {
            int r = tr + 4*ur;
            int i = i0 + r;
            #pragma unroll
            for (int uc = 0; uc < 4; uc++) {
                int j = j0 + tcol + 64*uc;
                int d = j - i;
                d = d < -63 ? -63 : (d > 63 ? 63 : d);
                sc[r*1024 + j] = (acc[ur][uc] + qbs[r*NTABP + d + 63]) * 0.125f;
            }
        }
    }
    __syncthreads();

    const int warp = tid >> 5, lane = tid & 31;
    for (int rw = 0; rw < 2; rw++) {
        const int r = warp + 8*rw;
        const int i = i0 + r;
        float* row = sc + r*1024;

        float mx = -1e30f;
        #pragma unroll
        for (int q = 0; q < 32; q++) mx = fmaxf(mx, row[lane + 32*q]);
        #pragma unroll
        for (int off = 16; off; off >>= 1) mx = fmaxf(mx, __shfl_xor_sync(0xffffffffu, mx, off));

        float sum = 0.f;
        #pragma unroll
        for (int q = 0; q < 32; q++) {
            float e = __expf(row[lane + 32*q] - mx);
            row[lane + 32*q] = e;
            sum += e;
        }
        #pragma unroll
        for (int off = 16; off; off >>= 1) sum += __shfl_xor_sync(0xffffffffu, sum, off);
        const float inv = 1.f / sum;

        float lsum = 0.f, rsum = 0.f;
        const size_t wrow = ((size_t)bn*NS + i) * NS;
        #pragma unroll
        for (int q = 0; q < 32; q++) {
            int j = lane + 32*q;
            float v = row[j] * inv;
            row[j] = v;
            g_w[wrow + j] = tf32r(v);
            if (j <= i - 63) lsum += v;
            if (j >= i + 63) rsum += v;
        }
        #pragma unroll
        for (int off = 16; off; off >>= 1) {
            lsum += __shfl_xor_sync(0xffffffffu, lsum, off);
            rsum += __shfl_xor_sync(0xffffffffu, rsum, off);
        }
        __syncwarp();

        const size_t wbrow = ((size_t)bn*NS + i) * NTABP;
        for (int t = lane; t < NTABP; t += 32) {
            float v = 0.f;
            if (t == 0)        v = lsum;
            else if (t == 126) v = rsum;
            else if (t < NTAB) {
                int j = i + t - 63;
                v = (j >= 0 && j < NS) ? row[j] : 0.f;
            }
            g_wb[wbrow + t] = tf32r(v);
        }
    }
}

// =============================================================================
// K4: out = w @ v + wb @ rp_v  (36 k-tiles).  grid (8 mtiles, 64 bn).
// =============================================================================
__global__ __launch_bounds__(128) void wv_mma()
{
    extern __shared__ float sm[];
    float* As = sm;
    float* Bs = sm + 2*AS_BUF;
    const int tid = threadIdx.x, lane = tid & 31, wid = tid >> 5;
    const int wm = wid & 1, wn = wid >> 1;
    const int i0 = blockIdx.x * 128, bn = blockIdx.y;

    const float* Aw  = g_w  + ((size_t)bn*NS + i0)*NS;
    const float* Ab  = g_wb + ((size_t)bn*NS + i0)*NTABP;
    const float* Bv  = g_vt + (size_t)bn*NHD*NS;

    float acc[4][4][4];
    #pragma unroll
    for (int f = 0; f < 4; f++)
        #pragma unroll
        for (int g = 0; g < 4; g++)
            #pragma unroll
            for (int e = 0; e < 4; e++) acc[f][g][e] = 0.f;

    load_a(s2u(As), Aw, NS, tid);
    load_b(s2u(Bs), Bv, NS, tid);
    cp_commit();
    for (int kt = 0; kt < 36; kt++) {
        if (kt + 1 < 36) {
            int k1 = kt + 1;
            int nb = k1 & 1;
            if (k1 < 32) {
                load_a(s2u(As + nb*AS_BUF), Aw + k1*32, NS, tid);
                load_b(s2u(Bs + nb*BS_BUF), Bv + k1*32, NS, tid);
            } else {
                load_a(s2u(As + nb*AS_BUF), Ab + (k1-32)*32, NTABP, tid);
                load_b(s2u(Bs + nb*BS_BUF), g_rpvt + (k1-32)*32, NTABP, tid);
            }
            cp_commit();
            cp_wait<1>();
        } else cp_wait<0>();
        __syncthreads();
        mma_tile(As + (kt&1)*AS_BUF, Bs + (kt&1)*BS_BUF, acc, wm, wn, lane);
        __syncthreads();
    }

    const int b = bn >> 4, n = bn & 15;
    const int r = lane >> 2, cq = lane & 3;
    #pragma unroll
    for (int f = 0; f < 4; f++) {
        int s = i0 + wm*64 + f*16 + r;
        #pragma unroll
        for (int g = 0; g < 4; g++) {
            int d = wn*32 + g*8 + 2*cq;
            float* row = g_ao + ((size_t)(b*NS + s))*NHID + n*NHD + d;
            *(float2*)row              = make_float2(tf32r(acc[f][g][0]), tf32r(acc[f][g][1]));
            *(float2*)(row + 8*NHID)   = make_float2(tf32r(acc[f][g][2]), tf32r(acc[f][g][3]));
        }
    }
}

// =============================================================================
// K5: final FC.  grid (32 mtiles, 16 otiles).
// =============================================================================
__global__ __launch_bounds__(128) void fc_mma(const float* __restrict__ bfc,
                                              float* __restrict__ out)
{
    extern __shared__ float sm[];
    float* As = sm;
    float* Bs = sm + 2*AS_BUF;
    const int tid = threadIdx.x, lane = tid & 31, wid = tid >> 5;
    const int wm = wid & 1, wn = wid >> 1;
    const int m0 = blockIdx.x * 128, o0 = blockIdx.y * 64;

    const float* A0 = g_ao + (size_t)m0*NHID;
    const float* B0 = g_wfc + (size_t)o0*NHID;

    float acc[4][4][4];
    #pragma unroll
    for (int f = 0; f < 4; f++)
        #pragma unroll
        for (int g = 0; g < 4; g++)
            #pragma unroll
            for (int e = 0; e < 4; e++) acc[f][g][e] = 0.f;

    load_a(s2u(As), A0, NHID, tid);
    load_b(s2u(Bs), B0, NHID, tid);
    cp_commit();
    for (int kt = 0; kt < 32; kt++) {
        if (kt + 1 < 32) {
            int nb = (kt+1) & 1;
            load_a(s2u(As + nb*AS_BUF), A0 + (kt+1)*32, NHID, tid);
            load_b(s2u(Bs + nb*BS_BUF), B0 + (kt+1)*32, NHID, tid);
            cp_commit();
            cp_wait<1>();
        } else cp_wait<0>();
        __syncthreads();
        mma_tile(As + (kt&1)*AS_BUF, Bs + (kt&1)*BS_BUF, acc, wm, wn, lane);
        __syncthreads();
    }

    const int r = lane >> 2, cq = lane & 3;
    #pragma unroll
    for (int f = 0; f < 4; f++) {
        int m = m0 + wm*64 + f*16 + r;
        #pragma unroll
        for (int g = 0; g < 4; g++) {
            int o = o0 + wn*32 + g*8 + 2*cq;
            float b0 = bfc[o], b1 = bfc[o+1];
            *(float2*)&out[(size_t)m*NHID + o]     = make_float2(acc[f][g][0]+b0, acc[f][g][1]+b1);
            *(float2*)&out[(size_t)(m+8)*NHID + o] = make_float2(acc[f][g][2]+b0, acc[f][g][3]+b1);
        }
    }
}

// =============================================================================
extern "C" void kernel_launch(void* const* d_in, const int* in_sizes, int n_in,
                              void* d_out, int out_size)
{
    (void)in_sizes; (void)n_in; (void)out_size;
    const float* query = (const float*)d_in[0];
    const float* key   = (const float*)d_in[1];
    const float* value = (const float*)d_in[2];
    const float* Wq    = (const float*)d_in[3];
    const float* Wk    = (const float*)d_in[4];
    const float* Wv    = (const float*)d_in[5];
    const float* bq    = (const float*)d_in[6];
    const float* bk    = (const float*)d_in[7];
    const float* bv    = (const float*)d_in[8];
    const float* rpk   = (const float*)d_in[9];
    const float* rpv   = (const float*)d_in[10];
    const float* Wfc   = (const float*)d_in[11];
    const float* bfc   = (const float*)d_in[12];
    float* out = (float*)d_out;

    const int SMEM_K3 = (16*1024 + 256*65 + 16*65 + 16*NTABP) * 4;   // 144448 B
    cudaFuncSetAttribute(attn_scores_kernel, cudaFuncAttributeMaxDynamicSharedMemorySize, SMEM_K3);
    cudaFuncSetAttribute(proj_mma, cudaFuncAttributeMaxDynamicSharedMemorySize, SMEM_GEMM);
    cudaFuncSetAttribute(wv_mma,   cudaFuncAttributeMaxDynamicSharedMemorySize, SMEM_GEMM);
    cudaFuncSetAttribute(fc_mma,   cudaFuncAttributeMaxDynamicSharedMemorySize, SMEM_GEMM);

    cvt_kernel<<<4096, 256>>>(query, 0, NM*NHID/4);
    cvt_kernel<<<4096, 256>>>(key,   1, NM*NHID/4);
    cvt_kernel<<<4096, 256>>>(value, 2, NM*NHID/4);
    cvt_kernel<<<1024, 256>>>(Wfc,   3, NHID*NHID/4);
    wt_kernel<<<dim3(16, 16, 3), 256>>>(Wq, Wk, Wv);
    rpvt_kernel<<<32, 256>>>(rpv);

    proj_mma<<<dim3(32, 16, 3), 128, SMEM_GEMM>>>(bq, bk, bv);
    qbias_kernel<<<8192, 256>>>(rpk);
    attn_scores_kernel<<<dim3(64, 64), 256, SMEM_K3>>>();
    wv_mma<<<dim3(8, 64), 128, SMEM_GEMM>>>();
    fc_mma<<<dim3(32, 16), 128, SMEM_GEMM>>>(bfc, out);
}

// round 4
// speedup vs baseline: 3.1496x; 1.6958x over previous
#include <cuda_runtime.h>
#include <cstdint>

#define NB    4
#define NS    1024
#define NHID  1024
#define NHEAD 16
#define NHD   64
#define NTAB  127
#define NTABP 128
#define BHS   (NB*NHEAD*NS)   // 65536
#define NM    (NB*NS)         // 4096

// ---------------- scratch (device globals; no allocations allowed) ----------------
__device__ float g_x  [(size_t)3*NM*NHID];            // tf32-rounded inputs (q,k,v)
__device__ float g_wt [(size_t)3*NHEAD*NHD*NHID];     // W^T per head, tf32-rounded
__device__ float g_wfc[(size_t)NHID*NHID];            // Wfc tf32-rounded ([o][k])
__device__ float g_q  [(size_t)BHS*NHD];              // fp32 q  [bn][s][d]  (exact)
__device__ float g_k  [(size_t)BHS*NHD];              // tf32 k  [bn][s][d]
__device__ float g_vt [(size_t)BHS*NHD];              // tf32 v^T [bn][d][s]
__device__ float g_qb [(size_t)BHS*NTABP];            // q . rp_k[t]  fp32 (exact)
__device__ float g_rpvt[NHD*NTABP];                   // rp_v^T tf32 (col 127 = 0)
__device__ float g_ao [(size_t)NM*NHID];              // attn out [b*s][hid], tf32

// =============================== helpers =====================================
__device__ __forceinline__ uint32_t s2u(const void* p) {
    uint32_t a;
    asm("{ .reg .u64 t; cvta.to.shared.u64 t, %1; cvt.u32.u64 %0, t; }" : "=r"(a) : "l"(p));
    return a;
}
__device__ __forceinline__ void cpa16(uint32_t d, const void* s) {
    asm volatile("cp.async.cg.shared.global [%0], [%1], 16;" :: "r"(d), "l"(s));
}
__device__ __forceinline__ void cp_commit() { asm volatile("cp.async.commit_group;"); }
template<int N> __device__ __forceinline__ void cp_wait() {
    asm volatile("cp.async.wait_group %0;" :: "n"(N));
}
__device__ __forceinline__ float tf32r(float x) {
    uint32_t u;
    asm("cvt.rna.tf32.f32 %0, %1;" : "=r"(u) : "f"(x));
    return __uint_as_float(u);
}
__device__ __forceinline__ void mma8(float* c, const uint32_t* a, const uint32_t* b) {
    asm volatile(
        "mma.sync.aligned.m16n8k8.row.col.f32.tf32.tf32.f32 "
        "{%0,%1,%2,%3}, {%4,%5,%6,%7}, {%8,%9}, {%0,%1,%2,%3};"
        : "+f"(c[0]), "+f"(c[1]), "+f"(c[2]), "+f"(c[3])
        : "r"(a[0]), "r"(a[1]), "r"(a[2]), "r"(a[3]), "r"(b[0]), "r"(b[1]));
}

#define AS_STRIDE 36   // == 4 (mod 32): conflict-free fragment LDS
#define BS_STRIDE 36
#define AS_BUF (128*AS_STRIDE)
#define BS_BUF (64*BS_STRIDE)
#define SMEM_GEMM ((2*AS_BUF + 2*BS_BUF)*4)

// A tile 128x32 from global (lda elems), 128 threads
__device__ __forceinline__ void load_a(uint32_t as, const float* __restrict__ A, int lda, int tid) {
    #pragma unroll
    for (int i = 0; i < 8; i++) {
        int idx = tid + i*128;
        int m = idx >> 3, kq = idx & 7;
        cpa16(as + (uint32_t)(m*AS_STRIDE + kq*4)*4, A + (size_t)m*lda + kq*4);
    }
}
// B tile 64x32
__device__ __forceinline__ void load_b(uint32_t bs, const float* __restrict__ B, int ldb, int tid) {
    #pragma unroll
    for (int i = 0; i < 4; i++) {
        int idx = tid + i*128;
        int nn = idx >> 3, kq = idx & 7;
        cpa16(bs + (uint32_t)(nn*BS_STRIDE + kq*4)*4, B + (size_t)nn*ldb + kq*4);
    }
}

// warp tile 64x32: 4 m-frags x 4 n-frags
__device__ __forceinline__ void mma_tile(const float* __restrict__ As, const float* __restrict__ Bs,
                                         float acc[4][4][4], int wm, int wn, int lane) {
    const int r = lane >> 2, cq = lane & 3;
    #pragma unroll
    for (int ks = 0; ks < 4; ks++) {
        const int k0 = ks*8;
        uint32_t a[4][4], b[4][2];
        #pragma unroll
        for (int f = 0; f < 4; f++) {
            const int bm = wm*64 + f*16;
            a[f][0] = __float_as_uint(As[(bm + r    )*AS_STRIDE + k0 + cq    ]);
            a[f][1] = __float_as_uint(As[(bm + r + 8)*AS_STRIDE + k0 + cq    ]);
            a[f][2] = __float_as_uint(As[(bm + r    )*AS_STRIDE + k0 + cq + 4]);
            a[f][3] = __float_as_uint(As[(bm + r + 8)*AS_STRIDE + k0 + cq + 4]);
        }
        #pragma unroll
        for (int g = 0; g < 4; g++) {
            const int bn = wn*32 + g*8;
            b[g][0] = __float_as_uint(Bs[(bn + r)*BS_STRIDE + k0 + cq    ]);
            b[g][1] = __float_as_uint(Bs[(bn + r)*BS_STRIDE + k0 + cq + 4]);
        }
        #pragma unroll
        for (int f = 0; f < 4; f++)
            #pragma unroll
            for (int g = 0; g < 4; g++) mma8(acc[f][g], a[f], b[g]);
    }
}

// =============================================================================
// C0: tf32-round copy
__global__ __launch_bounds__(256) void cvt_kernel(const float* __restrict__ in, int mode, int n4)
{
    int i = blockIdx.x * 256 + threadIdx.x;
    if (i >= n4) return;
    float* dst = (mode < 3) ? (g_x + (size_t)mode*NM*NHID) : g_wfc;
    float4 v = ((const float4*)in)[i];
    v.x = tf32r(v.x); v.y = tf32r(v.y); v.z = tf32r(v.z); v.w = tf32r(v.w);
    ((float4*)dst)[i] = v;
}

// C1: transpose + round per-head weights
__global__ __launch_bounds__(256) void wt_kernel(const float* __restrict__ wq,
                                                 const float* __restrict__ wk,
                                                 const float* __restrict__ wv)
{
    __shared__ float tile[64*65];
    const int hb = blockIdx.x, n = blockIdx.y, op = blockIdx.z;
    const float* W = (op==0 ? wq : (op==1 ? wk : wv)) + ((size_t)n*NHID + hb*64)*NHD;
    for (int e = threadIdx.x; e < 64*64; e += 256) {
        int h = e >> 6, d = e & 63;
        tile[h*65 + d] = W[(size_t)h*NHD + d];
    }
    __syncthreads();
    size_t ob = ((size_t)(op*NHEAD + n)*NHD)*NHID + hb*64;
    for (int e = threadIdx.x; e < 64*64; e += 256) {
        int d = e >> 6, h = e & 63;
        g_wt[ob + (size_t)d*NHID + h] = tf32r(tile[h*65 + d]);
    }
}

// C2: rp_v^T rounded + padded
__global__ __launch_bounds__(256) void rpvt_kernel(const float* __restrict__ rpv)
{
    int e = blockIdx.x * 256 + threadIdx.x;
    if (e >= NHD*NTABP) return;
    int d = e >> 7, t = e & 127;
    float v = (t < NTAB) ? rpv[(size_t)t*NHD + d] : 0.f;
    g_rpvt[(size_t)d*NTABP + t] = tf32r(v);
}

// =============================================================================
// K1: QKV projection.  grid (32 mtiles, 16 heads, 3 ops)
// =============================================================================
__global__ __launch_bounds__(128) void proj_mma(const float* __restrict__ bq_,
                                                const float* __restrict__ bk_,
                                                const float* __restrict__ bv_)
{
    extern __shared__ float sm[];
    float* As = sm;
    float* Bs = sm + 2*AS_BUF;
    const int tid = threadIdx.x, lane = tid & 31, wid = tid >> 5;
    const int wm = wid & 1, wn = wid >> 1;
    const int m0 = blockIdx.x * 128, n = blockIdx.y, op = blockIdx.z;

    const float* A0 = g_x + (size_t)op*NM*NHID + (size_t)m0*NHID;
    const float* B0 = g_wt + (size_t)(op*NHEAD + n)*NHD*NHID;

    float acc[4][4][4];
    #pragma unroll
    for (int f = 0; f < 4; f++)
        #pragma unroll
        for (int g = 0; g < 4; g++)
            #pragma unroll
            for (int e = 0; e < 4; e++) acc[f][g][e] = 0.f;

    load_a(s2u(As), A0, NHID, tid);
    load_b(s2u(Bs), B0, NHID, tid);
    cp_commit();
    for (int kt = 0; kt < 32; kt++) {
        if (kt + 1 < 32) {
            int nb = (kt+1) & 1;
            load_a(s2u(As + nb*AS_BUF), A0 + (kt+1)*32, NHID, tid);
            load_b(s2u(Bs + nb*BS_BUF), B0 + (kt+1)*32, NHID, tid);
            cp_commit();
            cp_wait<1>();
        } else cp_wait<0>();
        __syncthreads();
        mma_tile(As + (kt&1)*AS_BUF, Bs + (kt&1)*BS_BUF, acc, wm, wn, lane);
        __syncthreads();
    }

    const int b = m0 >> 10, s0 = m0 & 1023;
    const int bn = b*NHEAD + n;
    const int r = lane >> 2, cq = lane & 3;

    if (op < 2) {
        const float* bias = op ? bk_ : bq_;
        float* out = (op ? g_k : g_q) + ((size_t)bn*NS + s0)*NHD;
        const bool rnd = (op == 1);                 // k gets tf32-rounded
        #pragma unroll
        for (int f = 0; f < 4; f++) {
            int ml = wm*64 + f*16 + r;
            #pragma unroll
            for (int g = 0; g < 4; g++) {
                int d = wn*32 + g*8 + 2*cq;
                float b0 = bias[n*NHD + d], b1 = bias[n*NHD + d + 1];
                float x0 = acc[f][g][0]+b0, x1 = acc[f][g][1]+b1;
                float x2 = acc[f][g][2]+b0, x3 = acc[f][g][3]+b1;
                if (rnd) { x0=tf32r(x0); x1=tf32r(x1); x2=tf32r(x2); x3=tf32r(x3); }
                *(float2*)&out[(size_t)ml*NHD + d]     = make_float2(x0, x1);
                *(float2*)&out[(size_t)(ml+8)*NHD + d] = make_float2(x2, x3);
            }
        }
    } else {
        float* stage = As;                       // reuse smem
        #pragma unroll
        for (int f = 0; f < 4; f++) {
            int ml = wm*64 + f*16 + r;
            #pragma unroll
            for (int g = 0; g < 4; g++) {
                int d = wn*32 + g*8 + 2*cq;
                float b0 = bv_[n*NHD + d], b1 = bv_[n*NHD + d + 1];
                stage[(d  )*132 + ml    ] = acc[f][g][0] + b0;
                stage[(d+1)*132 + ml    ] = acc[f][g][1] + b1;
                stage[(d  )*132 + ml + 8] = acc[f][g][2] + b0;
                stage[(d+1)*132 + ml + 8] = acc[f][g][3] + b1;
            }
        }
        __syncthreads();
        const int d = tid >> 1, half = tid & 1;
        float* dst = g_vt + ((size_t)bn*NHD + d)*NS + s0 + half*64;
        #pragma unroll
        for (int j4 = 0; j4 < 16; j4++) {
            float4 v;
            v.x = tf32r(stage[d*132 + half*64 + j4*4 + 0]);
            v.y = tf32r(stage[d*132 + half*64 + j4*4 + 1]);
            v.z = tf32r(stage[d*132 + half*64 + j4*4 + 2]);
            v.w = tf32r(stage[d*132 + half*64 + j4*4 + 3]);
            ((float4*)dst)[j4] = v;
        }
    }
}

// =============================================================================
// K2: g_qb[row, t] = q[row,:] . rp_k[t,:]  (exact fp32)
// =============================================================================
__global__ __launch_bounds__(256) void qbias_kernel(const float* __restrict__ rpk)
{
    __shared__ float tab[NTAB*65];
    __shared__ float qs[8*65];
    const int tid  = threadIdx.x;
    const int row0 = blockIdx.x * 8;

    for (int e = tid; e < NTAB*NHD; e += 256) {
        int t = e >> 6, k = e & 63;
        tab[t*65 + k] = rpk[e];
    }
    for (int e = tid; e < 8*NHD; e += 256) {
        int r = e >> 6, k = e & 63;
        qs[r*65 + k] = g_q[(size_t)(row0 + r)*NHD + k];
    }
    __syncthreads();
    for (int e = tid; e < 8*NTAB; e += 256) {
        int r = e / NTAB, t = e % NTAB;
        float s = 0.f;
        #pragma unroll
        for (int k = 0; k < NHD; k++) s += qs[r*65+k] * tab[t*65+k];
        g_qb[(size_t)(row0 + r)*NTABP + t] = s;
    }
}

// =============================================================================
// K3: fused flash attention: QK^T + rel-bias + online softmax + PV + wb@rp_v.
// grid (16 itiles, 64 bn), 128 threads (4 warps x 16 rows).
// smem floats: qs[64*68] | ks[2][64*68] | vs[2][64*68] | ps[64*68]
//            | qb/wb[64*132] | band[64*128]
// =============================================================================
#define FQ  0
#define FK  4352
#define FV  13056
#define FP  21760
#define FB  26112
#define FD  34560
#define FTOT 42752

__global__ __launch_bounds__(128) void attn_fused()
{
    extern __shared__ float sm[];
    float* qs   = sm + FQ;
    float* ks   = sm + FK;
    float* vs   = sm + FV;
    float* ps   = sm + FP;
    float* qb   = sm + FB;    // bias table, reused as wb in epilogue
    float* band = sm + FD;

    const int tid = threadIdx.x, lane = tid & 31, w = tid >> 5;
    const int i0 = blockIdx.x * 64, bn = blockIdx.y;
    const int r = lane >> 2, cq = lane & 3;
    const int lr0 = w*16 + r;           // local row (0..63), second row = +8
    const int ia0 = i0 + lr0;           // absolute i

    // q tile (tf32-rounded)
    const float* qg = g_q + ((size_t)bn*NS + i0)*NHD;
    for (int e = tid; e < 64*64; e += 128) {
        int row = e >> 6, c = e & 63;
        qs[row*68 + c] = tf32r(qg[(size_t)row*NHD + c]);
    }
    // qb bias table
    const float* qbg = g_qb + ((size_t)bn*NS + i0)*NTABP;
    for (int e = tid; e < 64*32; e += 128) {
        int row = e >> 5, c = e & 31;
        cpa16(s2u(qb + row*132 + c*4), qbg + (size_t)row*NTABP + c*4);
    }
    const float* kg = g_k + (size_t)bn*NS*NHD;
    const float* vg = g_vt + (size_t)bn*NHD*NS;

    auto ldK = [&](int jt, int buf) {
        for (int e = tid; e < 64*16; e += 128) {
            int row = e >> 4, c = e & 15;
            cpa16(s2u(ks + buf*4352 + row*68 + c*4), kg + (size_t)(jt*64+row)*NHD + c*4);
        }
    };
    auto ldV = [&](int jt, int buf) {
        for (int e = tid; e < 64*16; e += 128) {
            int d = e >> 4, c = e & 15;
            cpa16(s2u(vs + buf*4352 + d*68 + c*4), vg + (size_t)d*NS + jt*64 + c*4);
        }
    };
    ldK(0, 0); ldV(0, 0); cp_commit();

    float o[8][4];
    #pragma unroll
    for (int g = 0; g < 8; g++)
        #pragma unroll
        for (int e = 0; e < 4; e++) o[g][e] = 0.f;
    float m0v = -1e30f, m1v = -1e30f, l0 = 0.f, l1 = 0.f;
    float ls0 = 0.f, ls1 = 0.f, rs0 = 0.f, rs1 = 0.f;

    for (int jt = 0; jt < 16; jt++) {
        const int cur = jt & 1;
        if (jt < 15) { ldK(jt+1, cur^1); ldV(jt+1, cur^1); cp_commit(); cp_wait<1>(); }
        else cp_wait<0>();
        __syncthreads();

        // ---- QK^T ----
        float s[8][4];
        #pragma unroll
        for (int g = 0; g < 8; g++)
            #pragma unroll
            for (int e = 0; e < 4; e++) s[g][e] = 0.f;
        const float* kb = ks + cur*4352;
        #pragma unroll
        for (int kk = 0; kk < 8; kk++) {
            const int k0 = kk*8;
            uint32_t a[4];
            a[0] = __float_as_uint(qs[(lr0  )*68 + k0 + cq    ]);
            a[1] = __float_as_uint(qs[(lr0+8)*68 + k0 + cq    ]);
            a[2] = __float_as_uint(qs[(lr0  )*68 + k0 + cq + 4]);
            a[3] = __float_as_uint(qs[(lr0+8)*68 + k0 + cq + 4]);
            #pragma unroll
            for (int g = 0; g < 8; g++) {
                uint32_t b[2];
                b[0] = __float_as_uint(kb[(g*8+r)*68 + k0 + cq    ]);
                b[1] = __float_as_uint(kb[(g*8+r)*68 + k0 + cq + 4]);
                mma8(s[g], a, b);
            }
        }
        // ---- bias + scale + band stash + row max ----
        float ml0 = -1e30f, ml1 = -1e30f;
        #pragma unroll
        for (int g = 0; g < 8; g++) {
            const int j0 = jt*64 + g*8 + 2*cq;
            const int t0 = j0 - ia0 + 63;          // row0
            const int t8 = t0 - 8;                 // row1 (i+8)
            int c0 = t0 < 0 ? 0 : (t0 > 126 ? 126 : t0);
            int c1 = t0+1 < 0 ? 0 : (t0+1 > 126 ? 126 : t0+1);
            int c2 = t8 < 0 ? 0 : (t8 > 126 ? 126 : t8);
            int c3 = t8+1 < 0 ? 0 : (t8+1 > 126 ? 126 : t8+1);
            float v0 = (s[g][0] + qb[lr0*132 + c0]) * 0.125f;
            float v1 = (s[g][1] + qb[lr0*132 + c1]) * 0.125f;
            float v2 = (s[g][2] + qb[(lr0+8)*132 + c2]) * 0.125f;
            float v3 = (s[g][3] + qb[(lr0+8)*132 + c3]) * 0.125f;
            if (t0   >= 1 && t0   <= 125) band[lr0*128 + t0]       = v0;
            if (t0+1 >= 1 && t0+1 <= 125) band[lr0*128 + t0+1]     = v1;
            if (t8   >= 1 && t8   <= 125) band[(lr0+8)*128 + t8]   = v2;
            if (t8+1 >= 1 && t8+1 <= 125) band[(lr0+8)*128 + t8+1] = v3;
            s[g][0] = v0; s[g][1] = v1; s[g][2] = v2; s[g][3] = v3;
            ml0 = fmaxf(ml0, fmaxf(v0, v1));
            ml1 = fmaxf(ml1, fmaxf(v2, v3));
        }
        ml0 = fmaxf(ml0, __shfl_xor_sync(0xffffffffu, ml0, 1));
        ml0 = fmaxf(ml0, __shfl_xor_sync(0xffffffffu, ml0, 2));
        ml1 = fmaxf(ml1, __shfl_xor_sync(0xffffffffu, ml1, 1));
        ml1 = fmaxf(ml1, __shfl_xor_sync(0xffffffffu, ml1, 2));
        const float mn0 = fmaxf(m0v, ml0), mn1 = fmaxf(m1v, ml1);
        const float sc0 = __expf(m0v - mn0), sc1 = __expf(m1v - mn1);
        m0v = mn0; m1v = mn1;

        // ---- exp + sums + edge accumulators ----
        float su0 = 0.f, su1 = 0.f, pl0 = 0.f, pl1 = 0.f, pr0 = 0.f, pr1 = 0.f;
        #pragma unroll
        for (int g = 0; g < 8; g++) {
            const int j0 = jt*64 + g*8 + 2*cq;
            const int t0 = j0 - ia0 + 63;
            const int t8 = t0 - 8;
            float p0 = __expf(s[g][0] - mn0);
            float p1 = __expf(s[g][1] - mn0);
            float p2 = __expf(s[g][2] - mn1);
            float p3 = __expf(s[g][3] - mn1);
            su0 += p0 + p1; su1 += p2 + p3;
            if (t0   <= 0) pl0 += p0; else if (t0   >= 126) pr0 += p0;
            if (t0+1 <= 0) pl0 += p1; else if (t0+1 >= 126) pr0 += p1;
            if (t8   <= 0) pl1 += p2; else if (t8   >= 126) pr1 += p2;
            if (t8+1 <= 0) pl1 += p3; else if (t8+1 >= 126) pr1 += p3;
            s[g][0] = p0; s[g][1] = p1; s[g][2] = p2; s[g][3] = p3;
        }
        #pragma unroll
        for (int off = 1; off <= 2; off <<= 1) {
            su0 += __shfl_xor_sync(0xffffffffu, su0, off);
            su1 += __shfl_xor_sync(0xffffffffu, su1, off);
            pl0 += __shfl_xor_sync(0xffffffffu, pl0, off);
            pl1 += __shfl_xor_sync(0xffffffffu, pl1, off);
            pr0 += __shfl_xor_sync(0xffffffffu, pr0, off);
            pr1 += __shfl_xor_sync(0xffffffffu, pr1, off);
        }
        l0 = l0*sc0 + su0;  l1 = l1*sc1 + su1;
        ls0 = ls0*sc0 + pl0; ls1 = ls1*sc1 + pl1;
        rs0 = rs0*sc0 + pr0; rs1 = rs1*sc1 + pr1;
        #pragma unroll
        for (int g = 0; g < 8; g++) {
            o[g][0] *= sc0; o[g][1] *= sc0; o[g][2] *= sc1; o[g][3] *= sc1;
        }
        __syncthreads();       // prior PV reads of ps complete
        #pragma unroll
        for (int g = 0; g < 8; g++) {
            const int jl = g*8 + 2*cq;
            *(float2*)&ps[lr0*68 + jl]     = make_float2(tf32r(s[g][0]), tf32r(s[g][1]));
            *(float2*)&ps[(lr0+8)*68 + jl] = make_float2(tf32r(s[g][2]), tf32r(s[g][3]));
        }
        __syncthreads();

        // ---- PV ----
        const float* vb = vs + cur*4352;
        #pragma unroll
        for (int kk = 0; kk < 8; kk++) {
            const int k0 = kk*8;
            uint32_t a[4];
            a[0] = __float_as_uint(ps[(lr0  )*68 + k0 + cq    ]);
            a[1] = __float_as_uint(ps[(lr0+8)*68 + k0 + cq    ]);
            a[2] = __float_as_uint(ps[(lr0  )*68 + k0 + cq + 4]);
            a[3] = __float_as_uint(ps[(lr0+8)*68 + k0 + cq + 4]);
            #pragma unroll
            for (int g = 0; g < 8; g++) {
                uint32_t b[2];
                b[0] = __float_as_uint(vb[(g*8+r)*68 + k0 + cq    ]);
                b[1] = __float_as_uint(vb[(g*8+r)*68 + k0 + cq + 4]);
                mma8(o[g], a, b);
            }
        }
    }

    // ---- epilogue: normalize, build wb, bias MMA, store ----
    const float inv0 = 1.f / l0, inv1 = 1.f / l1;
    #pragma unroll
    for (int g = 0; g < 8; g++) {
        o[g][0] *= inv0; o[g][1] *= inv0; o[g][2] *= inv1; o[g][3] *= inv1;
    }
    __syncthreads();           // all PV done; vs + qb reusable

    // rp_v^T into vs (two 64-col halves)
    for (int e = tid; e < 64*32; e += 128) {
        int d = e >> 5, c = e & 31;
        int buf = c >> 4, cc = c & 15;
        cpa16(s2u(vs + buf*4352 + d*68 + cc*4), g_rpvt + (size_t)d*NTABP + buf*64 + cc*4);
    }
    cp_commit();

    // wb into qb buffer (normalized, tf32)
    for (int t = cq; t < 128; t += 4) {
        float v0 = 0.f, v1 = 0.f;
        if (t == 0)        { v0 = ls0*inv0; v1 = ls1*inv1; }
        else if (t == 126) { v0 = rs0*inv0; v1 = rs1*inv1; }
        else if (t < 126) {
            int j0 = ia0 + t - 63;
            int j1 = j0 + 8;
            if (j0 >= 0 && j0 < NS) v0 = __expf(band[lr0*128 + t] - m0v) * inv0;
            if (j1 >= 0 && j1 < NS) v1 = __expf(band[(lr0+8)*128 + t] - m1v) * inv1;
        }
        qb[lr0*132 + t]     = tf32r(v0);
        qb[(lr0+8)*132 + t] = tf32r(v1);
    }
    cp_wait<0>();
    __syncthreads();

    #pragma unroll
    for (int kk = 0; kk < 16; kk++) {
        const float* vb = vs + (kk >> 3)*4352;
        const int k0 = (kk & 7)*8;
        uint32_t a[4];
        a[0] = __float_as_uint(qb[(lr0  )*132 + kk*8 + cq    ]);
        a[1] = __float_as_uint(qb[(lr0+8)*132 + kk*8 + cq    ]);
        a[2] = __float_as_uint(qb[(lr0  )*132 + kk*8 + cq + 4]);
        a[3] = __float_as_uint(qb[(lr0+8)*132 + kk*8 + cq + 4]);
        #pragma unroll
        for (int g = 0; g < 8; g++) {
            uint32_t b[2];
            b[0] = __float_as_uint(vb[(g*8+r)*68 + k0 + cq    ]);
            b[1] = __float_as_uint(vb[(g*8+r)*68 + k0 + cq + 4]);
            mma8(o[g], a, b);
        }
    }

    const int b = bn >> 4, n = bn & 15;
    #pragma unroll
    for (int g = 0; g < 8; g++) {
        const int d = g*8 + 2*cq;
        float* p0 = g_ao + ((size_t)(b*NS + i0 + lr0))*NHID + n*NHD + d;
        float* p1 = g_ao + ((size_t)(b*NS + i0 + lr0 + 8))*NHID + n*NHD + d;
        *(float2*)p0 = make_float2(tf32r(o[g][0]), tf32r(o[g][1]));
        *(float2*)p1 = make_float2(tf32r(o[g][2]), tf32r(o[g][3]));
    }
}

// =============================================================================
// K5: final FC.  grid (32 mtiles, 16 otiles)
// =============================================================================
__global__ __launch_bounds__(128) void fc_mma(const float* __restrict__ bfc,
                                              float* __restrict__ out)
{
    extern __shared__ float sm[];
    float* As = sm;
    float* Bs = sm + 2*AS_BUF;
    const int tid = threadIdx.x, lane = tid & 31, wid = tid >> 5;
    const int wm = wid & 1, wn = wid >> 1;
    const int m0 = blockIdx.x * 128, o0 = blockIdx.y * 64;

    const float* A0 = g_ao + (size_t)m0*NHID;
    const float* B0 = g_wfc + (size_t)o0*NHID;

    float acc[4][4][4];
    #pragma unroll
    for (int f = 0; f < 4; f++)
        #pragma unroll
        for (int g = 0; g < 4; g++)
            #pragma unroll
            for (int e = 0; e < 4; e++) acc[f][g][e] = 0.f;

    load_a(s2u(As), A0, NHID, tid);
    load_b(s2u(Bs), B0, NHID, tid);
    cp_commit();
    for (int kt = 0; kt < 32; kt++) {
        if (kt + 1 < 32) {
            int nb = (kt+1) & 1;
            load_a(s2u(As + nb*AS_BUF), A0 + (kt+1)*32, NHID, tid);
            load_b(s2u(Bs + nb*BS_BUF), B0 + (kt+1)*32, NHID, tid);
            cp_commit();
            cp_wait<1>();
        } else cp_wait<0>();
        __syncthreads();
        mma_tile(As + (kt&1)*AS_BUF, Bs + (kt&1)*BS_BUF, acc, wm, wn, lane);
        __syncthreads();
    }

    const int r = lane >> 2, cq = lane & 3;
    #pragma unroll
    for (int f = 0; f < 4; f++) {
        int m = m0 + wm*64 + f*16 + r;
        #pragma unroll
        for (int g = 0; g < 4; g++) {
            int o = o0 + wn*32 + g*8 + 2*cq;
            float b0 = bfc[o], b1 = bfc[o+1];
            *(float2*)&out[(size_t)m*NHID + o]     = make_float2(acc[f][g][0]+b0, acc[f][g][1]+b1);
            *(float2*)&out[(size_t)(m+8)*NHID + o] = make_float2(acc[f][g][2]+b0, acc[f][g][3]+b1);
        }
    }
}

// =============================================================================
extern "C" void kernel_launch(void* const* d_in, const int* in_sizes, int n_in,
                              void* d_out, int out_size)
{
    (void)in_sizes; (void)n_in; (void)out_size;
    const float* query = (const float*)d_in[0];
    const float* key   = (const float*)d_in[1];
    const float* value = (const float*)d_in[2];
    const float* Wq    = (const float*)d_in[3];
    const float* Wk    = (const float*)d_in[4];
    const float* Wv    = (const float*)d_in[5];
    const float* bq    = (const float*)d_in[6];
    const float* bk    = (const float*)d_in[7];
    const float* bv    = (const float*)d_in[8];
    const float* rpk   = (const float*)d_in[9];
    const float* rpv   = (const float*)d_in[10];
    const float* Wfc   = (const float*)d_in[11];
    const float* bfc   = (const float*)d_in[12];
    float* out = (float*)d_out;

    const int SMEM_FUSED = FTOT * 4;   // 171008 B
    cudaFuncSetAttribute(proj_mma,   cudaFuncAttributeMaxDynamicSharedMemorySize, SMEM_GEMM);
    cudaFuncSetAttribute(fc_mma,     cudaFuncAttributeMaxDynamicSharedMemorySize, SMEM_GEMM);
    cudaFuncSetAttribute(attn_fused, cudaFuncAttributeMaxDynamicSharedMemorySize, SMEM_FUSED);

    cvt_kernel<<<4096, 256>>>(query, 0, NM*NHID/4);
    cvt_kernel<<<4096, 256>>>(key,   1, NM*NHID/4);
    cvt_kernel<<<4096, 256>>>(value, 2, NM*NHID/4);
    cvt_kernel<<<1024, 256>>>(Wfc,   3, NHID*NHID/4);
    wt_kernel<<<dim3(16, 16, 3), 256>>>(Wq, Wk, Wv);
    rpvt_kernel<<<32, 256>>>(rpv);

    proj_mma<<<dim3(32, 16, 3), 128, SMEM_GEMM>>>(bq, bk, bv);
    qbias_kernel<<<8192, 256>>>(rpk);
    attn_fused<<<dim3(16, 64), 128, SMEM_FUSED>>>();
    fc_mma<<<dim3(32, 16), 128, SMEM_GEMM>>>(bfc, out);
}

// round 5
// speedup vs baseline: 3.8599x; 1.2255x over previous
#include <cuda_runtime.h>
#include <cstdint>

#define NB    4
#define NS    1024
#define NHID  1024
#define NHEAD 16
#define NHD   64
#define NTAB  127
#define NTABP 128
#define BHS   (NB*NHEAD*NS)   // 65536
#define NM    (NB*NS)         // 4096

// ---------------- scratch (device globals; no allocations allowed) ----------------
__device__ float g_x  [(size_t)3*NM*NHID];            // tf32-rounded inputs (q,k,v)
__device__ float g_wt [(size_t)3*NHEAD*NHD*NHID];     // W^T per head, tf32-rounded
__device__ float g_wfc[(size_t)NHID*NHID];            // Wfc tf32-rounded ([o][k])
__device__ float g_q  [(size_t)BHS*NHD];              // fp32 q  [bn][s][d]
__device__ float g_k  [(size_t)BHS*NHD];              // tf32 k  [bn][s][d]
__device__ float g_vt [(size_t)BHS*NHD];              // tf32 v^T [bn][d][s]
__device__ float g_rpvt[NHD*NTABP];                   // rp_v^T tf32 (col 127 = 0)
__device__ float g_rpkp[NTABP*NHD];                   // rp_k padded [t][d] tf32 (t=127 -> 0)
__device__ float g_ao [(size_t)NM*NHID];              // attn out [b*s][hid], tf32

// =============================== helpers =====================================
__device__ __forceinline__ uint32_t s2u(const void* p) {
    uint32_t a;
    asm("{ .reg .u64 t; cvta.to.shared.u64 t, %1; cvt.u32.u64 %0, t; }" : "=r"(a) : "l"(p));
    return a;
}
__device__ __forceinline__ void cpa16(uint32_t d, const void* s) {
    asm volatile("cp.async.cg.shared.global [%0], [%1], 16;" :: "r"(d), "l"(s));
}
__device__ __forceinline__ void cp_commit() { asm volatile("cp.async.commit_group;"); }
template<int N> __device__ __forceinline__ void cp_wait() {
    asm volatile("cp.async.wait_group %0;" :: "n"(N));
}
__device__ __forceinline__ float tf32r(float x) {
    uint32_t u;
    asm("cvt.rna.tf32.f32 %0, %1;" : "=r"(u) : "f"(x));
    return __uint_as_float(u);
}
__device__ __forceinline__ void mma8(float* c, const uint32_t* a, const uint32_t* b) {
    asm volatile(
        "mma.sync.aligned.m16n8k8.row.col.f32.tf32.tf32.f32 "
        "{%0,%1,%2,%3}, {%4,%5,%6,%7}, {%8,%9}, {%0,%1,%2,%3};"
        : "+f"(c[0]), "+f"(c[1]), "+f"(c[2]), "+f"(c[3])
        : "r"(a[0]), "r"(a[1]), "r"(a[2]), "r"(a[3]), "r"(b[0]), "r"(b[1]));
}

#define TS_STRIDE 36   // == 4 (mod 32): conflict-free fragment LDS
#define T_BUF (128*TS_STRIDE)
#define SMEM_GEMM (4*T_BUF*4)   // A(2 bufs) + B(2 bufs), 73728 B

// 128x32 tile from global (ld elems), 256 threads
__device__ __forceinline__ void load_t(uint32_t ts, const float* __restrict__ G, int ld, int tid) {
    #pragma unroll
    for (int i = 0; i < 4; i++) {
        int idx = tid + i*256;
        int m = idx >> 3, kq = idx & 7;
        cpa16(ts + (uint32_t)(m*TS_STRIDE + kq*4)*4, G + (size_t)m*ld + kq*4);
    }
}

// warp tile 64x32: 4 m-frags x 4 n-frags
__device__ __forceinline__ void mma_tile(const float* __restrict__ As, const float* __restrict__ Bs,
                                         float acc[4][4][4], int wm, int wn, int lane) {
    const int r = lane >> 2, cq = lane & 3;
    #pragma unroll
    for (int ks = 0; ks < 4; ks++) {
        const int k0 = ks*8;
        uint32_t a[4][4], b[4][2];
        #pragma unroll
        for (int f = 0; f < 4; f++) {
            const int bm = wm*64 + f*16;
            a[f][0] = __float_as_uint(As[(bm + r    )*TS_STRIDE + k0 + cq    ]);
            a[f][1] = __float_as_uint(As[(bm + r + 8)*TS_STRIDE + k0 + cq    ]);
            a[f][2] = __float_as_uint(As[(bm + r    )*TS_STRIDE + k0 + cq + 4]);
            a[f][3] = __float_as_uint(As[(bm + r + 8)*TS_STRIDE + k0 + cq + 4]);
        }
        #pragma unroll
        for (int g = 0; g < 4; g++) {
            const int bn = wn*32 + g*8;
            b[g][0] = __float_as_uint(Bs[(bn + r)*TS_STRIDE + k0 + cq    ]);
            b[g][1] = __float_as_uint(Bs[(bn + r)*TS_STRIDE + k0 + cq + 4]);
        }
        #pragma unroll
        for (int f = 0; f < 4; f++)
            #pragma unroll
            for (int g = 0; g < 4; g++) mma8(acc[f][g], a[f], b[g]);
    }
}

// =============================================================================
// C0: tf32-round copy
__global__ __launch_bounds__(256) void cvt_kernel(const float* __restrict__ in, int mode, int n4)
{
    int i = blockIdx.x * 256 + threadIdx.x;
    if (i >= n4) return;
    float* dst = (mode < 3) ? (g_x + (size_t)mode*NM*NHID) : g_wfc;
    float4 v = ((const float4*)in)[i];
    v.x = tf32r(v.x); v.y = tf32r(v.y); v.z = tf32r(v.z); v.w = tf32r(v.w);
    ((float4*)dst)[i] = v;
}

// C1: transpose + round per-head weights
__global__ __launch_bounds__(256) void wt_kernel(const float* __restrict__ wq,
                                                 const float* __restrict__ wk,
                                                 const float* __restrict__ wv)
{
    __shared__ float tile[64*65];
    const int hb = blockIdx.x, n = blockIdx.y, op = blockIdx.z;
    const float* W = (op==0 ? wq : (op==1 ? wk : wv)) + ((size_t)n*NHID + hb*64)*NHD;
    for (int e = threadIdx.x; e < 64*64; e += 256) {
        int h = e >> 6, d = e & 63;
        tile[h*65 + d] = W[(size_t)h*NHD + d];
    }
    __syncthreads();
    size_t ob = ((size_t)(op*NHEAD + n)*NHD)*NHID + hb*64;
    for (int e = threadIdx.x; e < 64*64; e += 256) {
        int d = e >> 6, h = e & 63;
        g_wt[ob + (size_t)d*NHID + h] = tf32r(tile[h*65 + d]);
    }
}

// C2: rp_v^T + padded rp_k, tf32-rounded
__global__ __launch_bounds__(256) void rp_kernel(const float* __restrict__ rpv,
                                                 const float* __restrict__ rpk)
{
    int e = blockIdx.x * 256 + threadIdx.x;
    if (e < NHD*NTABP) {
        int d = e >> 7, t = e & 127;
        float v = (t < NTAB) ? rpv[(size_t)t*NHD + d] : 0.f;
        g_rpvt[(size_t)d*NTABP + t] = tf32r(v);
    }
    if (e < NTABP*NHD) {
        int t = e >> 6, d = e & 63;
        float v = (t < NTAB) ? rpk[(size_t)t*NHD + d] : 0.f;
        g_rpkp[e] = tf32r(v);
    }
}

// =============================================================================
// K1: QKV projection, 128x128 tiles (2 heads/block).  grid (32, 8, 3), 256 thr.
// =============================================================================
__global__ __launch_bounds__(256) void proj_mma(const float* __restrict__ bq_,
                                                const float* __restrict__ bk_,
                                                const float* __restrict__ bv_)
{
    extern __shared__ float sm[];
    float* As = sm;
    float* Bs = sm + 2*T_BUF;
    const int tid = threadIdx.x, lane = tid & 31, wid = tid >> 5;
    const int wm = wid & 1, wn = wid >> 1;
    const int m0 = blockIdx.x * 128, ny = blockIdx.y, op = blockIdx.z;

    const float* A0 = g_x + (size_t)op*NM*NHID + (size_t)m0*NHID;
    const float* B0 = g_wt + (size_t)(op*NHEAD + ny*2)*NHD*NHID;   // 2 heads = 128 rows

    float acc[4][4][4];
    #pragma unroll
    for (int f = 0; f < 4; f++)
        #pragma unroll
        for (int g = 0; g < 4; g++)
            #pragma unroll
            for (int e = 0; e < 4; e++) acc[f][g][e] = 0.f;

    load_t(s2u(As), A0, NHID, tid);
    load_t(s2u(Bs), B0, NHID, tid);
    cp_commit();
    for (int kt = 0; kt < 32; kt++) {
        if (kt + 1 < 32) {
            int nb = (kt+1) & 1;
            load_t(s2u(As + nb*T_BUF), A0 + (kt+1)*32, NHID, tid);
            load_t(s2u(Bs + nb*T_BUF), B0 + (kt+1)*32, NHID, tid);
            cp_commit();
            cp_wait<1>();
        } else cp_wait<0>();
        __syncthreads();
        mma_tile(As + (kt&1)*T_BUF, Bs + (kt&1)*T_BUF, acc, wm, wn, lane);
        __syncthreads();
    }

    const int b = m0 >> 10, s0 = m0 & 1023;
    const int r = lane >> 2, cq = lane & 3;
    const float* bias = (op == 0) ? bq_ : ((op == 1) ? bk_ : bv_);

    if (op < 2) {
        float* outb = op ? g_k : g_q;
        const bool rnd = (op == 1);
        #pragma unroll
        for (int f = 0; f < 4; f++) {
            int ml = wm*64 + f*16 + r;
            #pragma unroll
            for (int g = 0; g < 4; g++) {
                int dp = wn*32 + g*8 + 2*cq;
                int nh = ny*2 + (dp >> 6), d = dp & 63;
                float b0 = bias[nh*NHD + d], b1 = bias[nh*NHD + d + 1];
                float x0 = acc[f][g][0]+b0, x1 = acc[f][g][1]+b1;
                float x2 = acc[f][g][2]+b0, x3 = acc[f][g][3]+b1;
                if (rnd) { x0=tf32r(x0); x1=tf32r(x1); x2=tf32r(x2); x3=tf32r(x3); }
                float* out = outb + ((size_t)(b*NHEAD + nh)*NS + s0)*NHD;
                *(float2*)&out[(size_t)ml*NHD + d]     = make_float2(x0, x1);
                *(float2*)&out[(size_t)(ml+8)*NHD + d] = make_float2(x2, x3);
            }
        }
    } else {
        float* stage = As;                       // 128 x 132 = 67584B <= 73728B
        #pragma unroll
        for (int f = 0; f < 4; f++) {
            int ml = wm*64 + f*16 + r;
            #pragma unroll
            for (int g = 0; g < 4; g++) {
                int dp = wn*32 + g*8 + 2*cq;
                int nh = ny*2 + (dp >> 6), d = dp & 63;
                float b0 = bias[nh*NHD + d], b1 = bias[nh*NHD + d + 1];
                stage[(dp  )*132 + ml    ] = acc[f][g][0] + b0;
                stage[(dp+1)*132 + ml    ] = acc[f][g][1] + b1;
                stage[(dp  )*132 + ml + 8] = acc[f][g][2] + b0;
                stage[(dp+1)*132 + ml + 8] = acc[f][g][3] + b1;
            }
        }
        __syncthreads();
        const int dp = tid >> 1, half = tid & 1;
        const int nh = ny*2 + (dp >> 6), d = dp & 63;
        float* dst = g_vt + ((size_t)(b*NHEAD + nh)*NHD + d)*NS + s0 + half*64;
        #pragma unroll
        for (int j4 = 0; j4 < 16; j4++) {
            float4 v;
            v.x = tf32r(stage[dp*132 + half*64 + j4*4 + 0]);
            v.y = tf32r(stage[dp*132 + half*64 + j4*4 + 1]);
            v.z = tf32r(stage[dp*132 + half*64 + j4*4 + 2]);
            v.w = tf32r(stage[dp*132 + half*64 + j4*4 + 3]);
            ((float4*)dst)[j4] = v;
        }
    }
}

// =============================================================================
// K3: fused flash attention + qb prologue MMA + wb@rp_v epilogue MMA.
// grid (16 itiles, 64 bn), 128 threads.
// =============================================================================
#define FQ  0
#define FK  4352
#define FV  13056
#define FP  21760
#define FB  26112
#define FD  34560
#define FTOT 42752

__global__ __launch_bounds__(128) void attn_fused()
{
    extern __shared__ float sm[];
    float* qs   = sm + FQ;
    float* ks   = sm + FK;    // 2 x [64][68]; also rp_k [128][68] in prologue
    float* vs   = sm + FV;
    float* ps   = sm + FP;
    float* qb   = sm + FB;    // [64][132]: qb table, reused as wb in epilogue
    float* band = sm + FD;

    const int tid = threadIdx.x, lane = tid & 31, w = tid >> 5;
    const int i0 = blockIdx.x * 64, bn = blockIdx.y;
    const int r = lane >> 2, cq = lane & 3;
    const int lr0 = w*16 + r;
    const int ia0 = i0 + lr0;

    // q tile (tf32-rounded) + rp_k [128 t][64 d] into ks region
    const float* qg = g_q + ((size_t)bn*NS + i0)*NHD;
    for (int e = tid; e < 64*64; e += 128) {
        int row = e >> 6, c = e & 63;
        qs[row*68 + c] = tf32r(qg[(size_t)row*NHD + c]);
    }
    for (int e = tid; e < 128*16; e += 128) {
        int row = e >> 4, c = e & 15;
        cpa16(s2u(ks + row*68 + c*4), g_rpkp + (size_t)row*NHD + c*4);
    }
    cp_commit();
    cp_wait<0>();
    __syncthreads();

    // ---- prologue: qb[row][t] = q . rp_k[t]  (warp tile 16 x 128) ----
    {
        float qacc[16][4];
        #pragma unroll
        for (int g = 0; g < 16; g++)
            #pragma unroll
            for (int e = 0; e < 4; e++) qacc[g][e] = 0.f;
        #pragma unroll
        for (int kk = 0; kk < 8; kk++) {
            const int k0 = kk*8;
            uint32_t a[4];
            a[0] = __float_as_uint(qs[(lr0  )*68 + k0 + cq    ]);
            a[1] = __float_as_uint(qs[(lr0+8)*68 + k0 + cq    ]);
            a[2] = __float_as_uint(qs[(lr0  )*68 + k0 + cq + 4]);
            a[3] = __float_as_uint(qs[(lr0+8)*68 + k0 + cq + 4]);
            #pragma unroll
            for (int g = 0; g < 16; g++) {
                uint32_t b[2];
                b[0] = __float_as_uint(ks[(g*8+r)*68 + k0 + cq    ]);
                b[1] = __float_as_uint(ks[(g*8+r)*68 + k0 + cq + 4]);
                mma8(qacc[g], a, b);
            }
        }
        #pragma unroll
        for (int g = 0; g < 16; g++) {
            const int t = g*8 + 2*cq;
            *(float2*)&qb[lr0*132 + t]     = make_float2(qacc[g][0], qacc[g][1]);
            *(float2*)&qb[(lr0+8)*132 + t] = make_float2(qacc[g][2], qacc[g][3]);
        }
    }
    __syncthreads();

    const float* kg = g_k + (size_t)bn*NS*NHD;
    const float* vg = g_vt + (size_t)bn*NHD*NS;

    auto ldK = [&](int jt, int buf) {
        for (int e = tid; e < 64*16; e += 128) {
            int row = e >> 4, c = e & 15;
            cpa16(s2u(ks + buf*4352 + row*68 + c*4), kg + (size_t)(jt*64+row)*NHD + c*4);
        }
    };
    auto ldV = [&](int jt, int buf) {
        for (int e = tid; e < 64*16; e += 128) {
            int d = e >> 4, c = e & 15;
            cpa16(s2u(vs + buf*4352 + d*68 + c*4), vg + (size_t)d*NS + jt*64 + c*4);
        }
    };
    ldK(0, 0); ldV(0, 0); cp_commit();

    float o[8][4];
    #pragma unroll
    for (int g = 0; g < 8; g++)
        #pragma unroll
        for (int e = 0; e < 4; e++) o[g][e] = 0.f;
    float m0v = -1e30f, m1v = -1e30f, l0 = 0.f, l1 = 0.f;
    float ls0 = 0.f, ls1 = 0.f, rs0 = 0.f, rs1 = 0.f;

    for (int jt = 0; jt < 16; jt++) {
        const int cur = jt & 1;
        if (jt < 15) { ldK(jt+1, cur^1); ldV(jt+1, cur^1); cp_commit(); cp_wait<1>(); }
        else cp_wait<0>();
        __syncthreads();

        // ---- QK^T ----
        float s[8][4];
        #pragma unroll
        for (int g = 0; g < 8; g++)
            #pragma unroll
            for (int e = 0; e < 4; e++) s[g][e] = 0.f;
        const float* kb = ks + cur*4352;
        #pragma unroll
        for (int kk = 0; kk < 8; kk++) {
            const int k0 = kk*8;
            uint32_t a[4];
            a[0] = __float_as_uint(qs[(lr0  )*68 + k0 + cq    ]);
            a[1] = __float_as_uint(qs[(lr0+8)*68 + k0 + cq    ]);
            a[2] = __float_as_uint(qs[(lr0  )*68 + k0 + cq + 4]);
            a[3] = __float_as_uint(qs[(lr0+8)*68 + k0 + cq + 4]);
            #pragma unroll
            for (int g = 0; g < 8; g++) {
                uint32_t b[2];
                b[0] = __float_as_uint(kb[(g*8+r)*68 + k0 + cq    ]);
                b[1] = __float_as_uint(kb[(g*8+r)*68 + k0 + cq + 4]);
                mma8(s[g], a, b);
            }
        }
        // ---- bias + scale + band stash + row max ----
        float ml0 = -1e30f, ml1 = -1e30f;
        #pragma unroll
        for (int g = 0; g < 8; g++) {
            const int j0 = jt*64 + g*8 + 2*cq;
            const int t0 = j0 - ia0 + 63;
            const int t8 = t0 - 8;
            int c0 = t0 < 0 ? 0 : (t0 > 126 ? 126 : t0);
            int c1 = t0+1 < 0 ? 0 : (t0+1 > 126 ? 126 : t0+1);
            int c2 = t8 < 0 ? 0 : (t8 > 126 ? 126 : t8);
            int c3 = t8+1 < 0 ? 0 : (t8+1 > 126 ? 126 : t8+1);
            float v0 = (s[g][0] + qb[lr0*132 + c0]) * 0.125f;
            float v1 = (s[g][1] + qb[lr0*132 + c1]) * 0.125f;
            float v2 = (s[g][2] + qb[(lr0+8)*132 + c2]) * 0.125f;
            float v3 = (s[g][3] + qb[(lr0+8)*132 + c3]) * 0.125f;
            if (t0   >= 1 && t0   <= 125) band[lr0*128 + t0]       = v0;
            if (t0+1 >= 1 && t0+1 <= 125) band[lr0*128 + t0+1]     = v1;
            if (t8   >= 1 && t8   <= 125) band[(lr0+8)*128 + t8]   = v2;
            if (t8+1 >= 1 && t8+1 <= 125) band[(lr0+8)*128 + t8+1] = v3;
            s[g][0] = v0; s[g][1] = v1; s[g][2] = v2; s[g][3] = v3;
            ml0 = fmaxf(ml0, fmaxf(v0, v1));
            ml1 = fmaxf(ml1, fmaxf(v2, v3));
        }
        ml0 = fmaxf(ml0, __shfl_xor_sync(0xffffffffu, ml0, 1));
        ml0 = fmaxf(ml0, __shfl_xor_sync(0xffffffffu, ml0, 2));
        ml1 = fmaxf(ml1, __shfl_xor_sync(0xffffffffu, ml1, 1));
        ml1 = fmaxf(ml1, __shfl_xor_sync(0xffffffffu, ml1, 2));
        const float mn0 = fmaxf(m0v, ml0), mn1 = fmaxf(m1v, ml1);
        const float sc0 = __expf(m0v - mn0), sc1 = __expf(m1v - mn1);
        m0v = mn0; m1v = mn1;

        float su0 = 0.f, su1 = 0.f, pl0 = 0.f, pl1 = 0.f, pr0 = 0.f, pr1 = 0.f;
        #pragma unroll
        for (int g = 0; g < 8; g++) {
            const int j0 = jt*64 + g*8 + 2*cq;
            const int t0 = j0 - ia0 + 63;
            const int t8 = t0 - 8;
            float p0 = __expf(s[g][0] - mn0);
            float p1 = __expf(s[g][1] - mn0);
            float p2 = __expf(s[g][2] - mn1);
            float p3 = __expf(s[g][3] - mn1);
            su0 += p0 + p1; su1 += p2 + p3;
            if (t0   <= 0) pl0 += p0; else if (t0   >= 126) pr0 += p0;
            if (t0+1 <= 0) pl0 += p1; else if (t0+1 >= 126) pr0 += p1;
            if (t8   <= 0) pl1 += p2; else if (t8   >= 126) pr1 += p2;
            if (t8+1 <= 0) pl1 += p3; else if (t8+1 >= 126) pr1 += p3;
            s[g][0] = p0; s[g][1] = p1; s[g][2] = p2; s[g][3] = p3;
        }
        #pragma unroll
        for (int off = 1; off <= 2; off <<= 1) {
            su0 += __shfl_xor_sync(0xffffffffu, su0, off);
            su1 += __shfl_xor_sync(0xffffffffu, su1, off);
            pl0 += __shfl_xor_sync(0xffffffffu, pl0, off);
            pl1 += __shfl_xor_sync(0xffffffffu, pl1, off);
            pr0 += __shfl_xor_sync(0xffffffffu, pr0, off);
            pr1 += __shfl_xor_sync(0xffffffffu, pr1, off);
        }
        l0 = l0*sc0 + su0;  l1 = l1*sc1 + su1;
        ls0 = ls0*sc0 + pl0; ls1 = ls1*sc1 + pl1;
        rs0 = rs0*sc0 + pr0; rs1 = rs1*sc1 + pr1;
        #pragma unroll
        for (int g = 0; g < 8; g++) {
            o[g][0] *= sc0; o[g][1] *= sc0; o[g][2] *= sc1; o[g][3] *= sc1;
        }
        __syncthreads();
        #pragma unroll
        for (int g = 0; g < 8; g++) {
            const int jl = g*8 + 2*cq;
            *(float2*)&ps[lr0*68 + jl]     = make_float2(tf32r(s[g][0]), tf32r(s[g][1]));
            *(float2*)&ps[(lr0+8)*68 + jl] = make_float2(tf32r(s[g][2]), tf32r(s[g][3]));
        }
        __syncthreads();

        // ---- PV ----
        const float* vb = vs + cur*4352;
        #pragma unroll
        for (int kk = 0; kk < 8; kk++) {
            const int k0 = kk*8;
            uint32_t a[4];
            a[0] = __float_as_uint(ps[(lr0  )*68 + k0 + cq    ]);
            a[1] = __float_as_uint(ps[(lr0+8)*68 + k0 + cq    ]);
            a[2] = __float_as_uint(ps[(lr0  )*68 + k0 + cq + 4]);
            a[3] = __float_as_uint(ps[(lr0+8)*68 + k0 + cq + 4]);
            #pragma unroll
            for (int g = 0; g < 8; g++) {
                uint32_t b[2];
                b[0] = __float_as_uint(vb[(g*8+r)*68 + k0 + cq    ]);
                b[1] = __float_as_uint(vb[(g*8+r)*68 + k0 + cq + 4]);
                mma8(o[g], a, b);
            }
        }
    }

    // ---- epilogue ----
    const float inv0 = 1.f / l0, inv1 = 1.f / l1;
    #pragma unroll
    for (int g = 0; g < 8; g++) {
        o[g][0] *= inv0; o[g][1] *= inv0; o[g][2] *= inv1; o[g][3] *= inv1;
    }
    __syncthreads();

    for (int e = tid; e < 64*32; e += 128) {
        int d = e >> 5, c = e & 31;
        int buf = c >> 4, cc = c & 15;
        cpa16(s2u(vs + buf*4352 + d*68 + cc*4), g_rpvt + (size_t)d*NTABP + buf*64 + cc*4);
    }
    cp_commit();

    for (int t = cq; t < 128; t += 4) {
        float v0 = 0.f, v1 = 0.f;
        if (t == 0)        { v0 = ls0*inv0; v1 = ls1*inv1; }
        else if (t == 126) { v0 = rs0*inv0; v1 = rs1*inv1; }
        else if (t < 126) {
            int j0 = ia0 + t - 63;
            int j1 = j0 + 8;
            if (j0 >= 0 && j0 < NS) v0 = __expf(band[lr0*128 + t] - m0v) * inv0;
            if (j1 >= 0 && j1 < NS) v1 = __expf(band[(lr0+8)*128 + t] - m1v) * inv1;
        }
        qb[lr0*132 + t]     = tf32r(v0);
        qb[(lr0+8)*132 + t] = tf32r(v1);
    }
    cp_wait<0>();
    __syncthreads();

    #pragma unroll
    for (int kk = 0; kk < 16; kk++) {
        const float* vb = vs + (kk >> 3)*4352;
        const int k0 = (kk & 7)*8;
        uint32_t a[4];
        a[0] = __float_as_uint(qb[(lr0  )*132 + kk*8 + cq    ]);
        a[1] = __float_as_uint(qb[(lr0+8)*132 + kk*8 + cq    ]);
        a[2] = __float_as_uint(qb[(lr0  )*132 + kk*8 + cq + 4]);
        a[3] = __float_as_uint(qb[(lr0+8)*132 + kk*8 + cq + 4]);
        #pragma unroll
        for (int g = 0; g < 8; g++) {
            uint32_t b[2];
            b[0] = __float_as_uint(vb[(g*8+r)*68 + k0 + cq    ]);
            b[1] = __float_as_uint(vb[(g*8+r)*68 + k0 + cq + 4]);
            mma8(o[g], a, b);
        }
    }

    const int b = bn >> 4, n = bn & 15;
    #pragma unroll
    for (int g = 0; g < 8; g++) {
        const int d = g*8 + 2*cq;
        float* p0 = g_ao + ((size_t)(b*NS + i0 + lr0))*NHID + n*NHD + d;
        float* p1 = g_ao + ((size_t)(b*NS + i0 + lr0 + 8))*NHID + n*NHD + d;
        *(float2*)p0 = make_float2(tf32r(o[g][0]), tf32r(o[g][1]));
        *(float2*)p1 = make_float2(tf32r(o[g][2]), tf32r(o[g][3]));
    }
}

// =============================================================================
// K5: final FC, 128x128 tiles.  grid (32, 8), 256 threads.
// =============================================================================
__global__ __launch_bounds__(256) void fc_mma(const float* __restrict__ bfc,
                                              float* __restrict__ out)
{
    extern __shared__ float sm[];
    float* As = sm;
    float* Bs = sm + 2*T_BUF;
    const int tid = threadIdx.x, lane = tid & 31, wid = tid >> 5;
    const int wm = wid & 1, wn = wid >> 1;
    const int m0 = blockIdx.x * 128, o0 = blockIdx.y * 128;

    const float* A0 = g_ao + (size_t)m0*NHID;
    const float* B0 = g_wfc + (size_t)o0*NHID;

    float acc[4][4][4];
    #pragma unroll
    for (int f = 0; f < 4; f++)
        #pragma unroll
        for (int g = 0; g < 4; g++)
            #pragma unroll
            for (int e = 0; e < 4; e++) acc[f][g][e] = 0.f;

    load_t(s2u(As), A0, NHID, tid);
    load_t(s2u(Bs), B0, NHID, tid);
    cp_commit();
    for (int kt = 0; kt < 32; kt++) {
        if (kt + 1 < 32) {
            int nb = (kt+1) & 1;
            load_t(s2u(As + nb*T_BUF), A0 + (kt+1)*32, NHID, tid);
            load_t(s2u(Bs + nb*T_BUF), B0 + (kt+1)*32, NHID, tid);
            cp_commit();
            cp_wait<1>();
        } else cp_wait<0>();
        __syncthreads();
        mma_tile(As + (kt&1)*T_BUF, Bs + (kt&1)*T_BUF, acc, wm, wn, lane);
        __syncthreads();
    }

    const int r = lane >> 2, cq = lane & 3;
    #pragma unroll
    for (int f = 0; f < 4; f++) {
        int m = m0 + wm*64 + f*16 + r;
        #pragma unroll
        for (int g = 0; g < 4; g++) {
            int o = o0 + wn*32 + g*8 + 2*cq;
            float b0 = bfc[o], b1 = bfc[o+1];
            *(float2*)&out[(size_t)m*NHID + o]     = make_float2(acc[f][g][0]+b0, acc[f][g][1]+b1);
            *(float2*)&out[(size_t)(m+8)*NHID + o] = make_float2(acc[f][g][2]+b0, acc[f][g][3]+b1);
        }
    }
}

// =============================================================================
extern "C" void kernel_launch(void* const* d_in, const int* in_sizes, int n_in,
                              void* d_out, int out_size)
{
    (void)in_sizes; (void)n_in; (void)out_size;
    const float* query = (const float*)d_in[0];
    const float* key   = (const float*)d_in[1];
    const float* value = (const float*)d_in[2];
    const float* Wq    = (const float*)d_in[3];
    const float* Wk    = (const float*)d_in[4];
    const float* Wv    = (const float*)d_in[5];
    const float* bq    = (const float*)d_in[6];
    const float* bk    = (const float*)d_in[7];
    const float* bv    = (const float*)d_in[8];
    const float* rpk   = (const float*)d_in[9];
    const float* rpv   = (const float*)d_in[10];
    const float* Wfc   = (const float*)d_in[11];
    const float* bfc   = (const float*)d_in[12];
    float* out = (float*)d_out;

    const int SMEM_FUSED = FTOT * 4;   // 171008 B
    cudaFuncSetAttribute(proj_mma,   cudaFuncAttributeMaxDynamicSharedMemorySize, SMEM_GEMM);
    cudaFuncSetAttribute(fc_mma,     cudaFuncAttributeMaxDynamicSharedMemorySize, SMEM_GEMM);
    cudaFuncSetAttribute(attn_fused, cudaFuncAttributeMaxDynamicSharedMemorySize, SMEM_FUSED);

    // launch order chosen so launch #6 (ncu -s 5 -c 1) is proj_mma
    wt_kernel<<<dim3(16, 16, 3), 256>>>(Wq, Wk, Wv);                 // 1
    rp_kernel<<<32, 256>>>(rpv, rpk);                                // 2
    cvt_kernel<<<4096, 256>>>(query, 0, NM*NHID/4);                  // 3
    cvt_kernel<<<4096, 256>>>(key,   1, NM*NHID/4);                  // 4
    cvt_kernel<<<4096, 256>>>(value, 2, NM*NHID/4);                  // 5
    proj_mma<<<dim3(32, 8, 3), 256, SMEM_GEMM>>>(bq, bk, bv);        // 6 <- profiled
    cvt_kernel<<<1024, 256>>>(Wfc,   3, NHID*NHID/4);                // 7
    attn_fused<<<dim3(16, 64), 128, SMEM_FUSED>>>();                 // 8
    fc_mma<<<dim3(32, 8), 256, SMEM_GEMM>>>(bfc, out);               // 9
}

// round 6
// speedup vs baseline: 3.9035x; 1.0113x over previous
#include <cuda_runtime.h>
#include <cuda_fp16.h>
#include <cstdint>

#define NB    4
#define NS    1024
#define NHID  1024
#define NHEAD 16
#define NHD   64
#define NTAB  127
#define NTABP 128
#define BHS   (NB*NHEAD*NS)   // 65536
#define NM    (NB*NS)         // 4096

// ---------------- scratch (device globals; no allocations allowed) ----------------
__device__ float g_x  [(size_t)3*NM*NHID];            // tf32-rounded inputs (q,k,v)
__device__ float g_wt [(size_t)3*NHEAD*NHD*NHID];     // W^T per head, tf32-rounded
__device__ float g_wfc[(size_t)NHID*NHID];            // Wfc tf32-rounded ([o][k])
__device__ float g_q  [(size_t)BHS*NHD];              // fp32 q  [bn][s][d]
__device__ float g_k  [(size_t)BHS*NHD];              // tf32 k  [bn][s][d]
__device__ float g_vt [(size_t)BHS*NHD];              // tf32 v^T [bn][d][s]
__device__ float g_rpvt[NHD*NTABP];                   // rp_v^T tf32 (col 127 = 0)
__device__ float g_rpkp[NTABP*NHD];                   // rp_k padded [t][d] tf32
__device__ float g_ao [(size_t)NM*NHID];              // attn out [b*s][hid], tf32

// =============================== helpers =====================================
__device__ __forceinline__ uint32_t s2u(const void* p) {
    uint32_t a;
    asm("{ .reg .u64 t; cvta.to.shared.u64 t, %1; cvt.u32.u64 %0, t; }" : "=r"(a) : "l"(p));
    return a;
}
__device__ __forceinline__ void cpa16(uint32_t d, const void* s) {
    asm volatile("cp.async.cg.shared.global [%0], [%1], 16;" :: "r"(d), "l"(s));
}
__device__ __forceinline__ void cp_commit() { asm volatile("cp.async.commit_group;"); }
template<int N> __device__ __forceinline__ void cp_wait() {
    asm volatile("cp.async.wait_group %0;" :: "n"(N));
}
__device__ __forceinline__ float tf32r(float x) {
    uint32_t u;
    asm("cvt.rna.tf32.f32 %0, %1;" : "=r"(u) : "f"(x));
    return __uint_as_float(u);
}
__device__ __forceinline__ void mma8(float* c, const uint32_t* a, const uint32_t* b) {
    asm volatile(
        "mma.sync.aligned.m16n8k8.row.col.f32.tf32.tf32.f32 "
        "{%0,%1,%2,%3}, {%4,%5,%6,%7}, {%8,%9}, {%0,%1,%2,%3};"
        : "+f"(c[0]), "+f"(c[1]), "+f"(c[2]), "+f"(c[3])
        : "r"(a[0]), "r"(a[1]), "r"(a[2]), "r"(a[3]), "r"(b[0]), "r"(b[1]));
}

#define TS_STRIDE 36   // == 4 (mod 32): conflict-free fragment LDS
#define T_BUF (128*TS_STRIDE)
#define SMEM_GEMM (4*T_BUF*4)   // 73728 B

// 128x32 tile from global (ld elems), 256 threads
__device__ __forceinline__ void load_t(uint32_t ts, const float* __restrict__ G, int ld, int tid) {
    #pragma unroll
    for (int i = 0; i < 4; i++) {
        int idx = tid + i*256;
        int m = idx >> 3, kq = idx & 7;
        cpa16(ts + (uint32_t)(m*TS_STRIDE + kq*4)*4, G + (size_t)m*ld + kq*4);
    }
}

// warp tile 64x32: 4 m-frags x 4 n-frags
__device__ __forceinline__ void mma_tile(const float* __restrict__ As, const float* __restrict__ Bs,
                                         float acc[4][4][4], int wm, int wn, int lane) {
    const int r = lane >> 2, cq = lane & 3;
    #pragma unroll
    for (int ks = 0; ks < 4; ks++) {
        const int k0 = ks*8;
        uint32_t a[4][4], b[4][2];
        #pragma unroll
        for (int f = 0; f < 4; f++) {
            const int bm = wm*64 + f*16;
            a[f][0] = __float_as_uint(As[(bm + r    )*TS_STRIDE + k0 + cq    ]);
            a[f][1] = __float_as_uint(As[(bm + r + 8)*TS_STRIDE + k0 + cq    ]);
            a[f][2] = __float_as_uint(As[(bm + r    )*TS_STRIDE + k0 + cq + 4]);
            a[f][3] = __float_as_uint(As[(bm + r + 8)*TS_STRIDE + k0 + cq + 4]);
        }
        #pragma unroll
        for (int g = 0; g < 4; g++) {
            const int bn = wn*32 + g*8;
            b[g][0] = __float_as_uint(Bs[(bn + r)*TS_STRIDE + k0 + cq    ]);
            b[g][1] = __float_as_uint(Bs[(bn + r)*TS_STRIDE + k0 + cq + 4]);
        }
        #pragma unroll
        for (int f = 0; f < 4; f++)
            #pragma unroll
            for (int g = 0; g < 4; g++) mma8(acc[f][g], a[f], b[g]);
    }
}

// =============================================================================
// C0: tf32-round copy
__global__ __launch_bounds__(256) void cvt_kernel(const float* __restrict__ in, int mode, int n4)
{
    int i = blockIdx.x * 256 + threadIdx.x;
    if (i >= n4) return;
    float* dst = (mode < 3) ? (g_x + (size_t)mode*NM*NHID) : g_wfc;
    float4 v = ((const float4*)in)[i];
    v.x = tf32r(v.x); v.y = tf32r(v.y); v.z = tf32r(v.z); v.w = tf32r(v.w);
    ((float4*)dst)[i] = v;
}

// C1: transpose + round per-head weights
__global__ __launch_bounds__(256) void wt_kernel(const float* __restrict__ wq,
                                                 const float* __restrict__ wk,
                                                 const float* __restrict__ wv)
{
    __shared__ float tile[64*65];
    const int hb = blockIdx.x, n = blockIdx.y, op = blockIdx.z;
    const float* W = (op==0 ? wq : (op==1 ? wk : wv)) + ((size_t)n*NHID + hb*64)*NHD;
    for (int e = threadIdx.x; e < 64*64; e += 256) {
        int h = e >> 6, d = e & 63;
        tile[h*65 + d] = W[(size_t)h*NHD + d];
    }
    __syncthreads();
    size_t ob = ((size_t)(op*NHEAD + n)*NHD)*NHID + hb*64;
    for (int e = threadIdx.x; e < 64*64; e += 256) {
        int d = e >> 6, h = e & 63;
        g_wt[ob + (size_t)d*NHID + h] = tf32r(tile[h*65 + d]);
    }
}

// C2: rp_v^T + padded rp_k, tf32-rounded
__global__ __launch_bounds__(256) void rp_kernel(const float* __restrict__ rpv,
                                                 const float* __restrict__ rpk)
{
    int e = blockIdx.x * 256 + threadIdx.x;
    if (e < NHD*NTABP) {
        int d = e >> 7, t = e & 127;
        float v = (t < NTAB) ? rpv[(size_t)t*NHD + d] : 0.f;
        g_rpvt[(size_t)d*NTABP + t] = tf32r(v);
    }
    if (e < NTABP*NHD) {
        int t = e >> 6, d = e & 63;
        float v = (t < NTAB) ? rpk[(size_t)t*NHD + d] : 0.f;
        g_rpkp[e] = tf32r(v);
    }
}

// =============================================================================
// K1: QKV projection, 128x128 tiles (2 heads/block).  grid (32, 8, 3), 256 thr.
// =============================================================================
__global__ __launch_bounds__(256) void proj_mma(const float* __restrict__ bq_,
                                                const float* __restrict__ bk_,
                                                const float* __restrict__ bv_)
{
    extern __shared__ float sm[];
    float* As = sm;
    float* Bs = sm + 2*T_BUF;
    const int tid = threadIdx.x, lane = tid & 31, wid = tid >> 5;
    const int wm = wid & 1, wn = wid >> 1;
    const int m0 = blockIdx.x * 128, ny = blockIdx.y, op = blockIdx.z;

    const float* A0 = g_x + (size_t)op*NM*NHID + (size_t)m0*NHID;
    const float* B0 = g_wt + (size_t)(op*NHEAD + ny*2)*NHD*NHID;

    float acc[4][4][4];
    #pragma unroll
    for (int f = 0; f < 4; f++)
        #pragma unroll
        for (int g = 0; g < 4; g++)
            #pragma unroll
            for (int e = 0; e < 4; e++) acc[f][g][e] = 0.f;

    load_t(s2u(As), A0, NHID, tid);
    load_t(s2u(Bs), B0, NHID, tid);
    cp_commit();
    for (int kt = 0; kt < 32; kt++) {
        if (kt + 1 < 32) {
            int nb = (kt+1) & 1;
            load_t(s2u(As + nb*T_BUF), A0 + (kt+1)*32, NHID, tid);
            load_t(s2u(Bs + nb*T_BUF), B0 + (kt+1)*32, NHID, tid);
            cp_commit();
            cp_wait<1>();
        } else cp_wait<0>();
        __syncthreads();
        mma_tile(As + (kt&1)*T_BUF, Bs + (kt&1)*T_BUF, acc, wm, wn, lane);
        __syncthreads();
    }

    const int b = m0 >> 10, s0 = m0 & 1023;
    const int r = lane >> 2, cq = lane & 3;
    const float* bias = (op == 0) ? bq_ : ((op == 1) ? bk_ : bv_);

    if (op < 2) {
        float* outb = op ? g_k : g_q;
        const bool rnd = (op == 1);
        #pragma unroll
        for (int f = 0; f < 4; f++) {
            int ml = wm*64 + f*16 + r;
            #pragma unroll
            for (int g = 0; g < 4; g++) {
                int dp = wn*32 + g*8 + 2*cq;
                int nh = ny*2 + (dp >> 6), d = dp & 63;
                float b0 = bias[nh*NHD + d], b1 = bias[nh*NHD + d + 1];
                float x0 = acc[f][g][0]+b0, x1 = acc[f][g][1]+b1;
                float x2 = acc[f][g][2]+b0, x3 = acc[f][g][3]+b1;
                if (rnd) { x0=tf32r(x0); x1=tf32r(x1); x2=tf32r(x2); x3=tf32r(x3); }
                float* out = outb + ((size_t)(b*NHEAD + nh)*NS + s0)*NHD;
                *(float2*)&out[(size_t)ml*NHD + d]     = make_float2(x0, x1);
                *(float2*)&out[(size_t)(ml+8)*NHD + d] = make_float2(x2, x3);
            }
        }
    } else {
        float* stage = As;
        #pragma unroll
        for (int f = 0; f < 4; f++) {
            int ml = wm*64 + f*16 + r;
            #pragma unroll
            for (int g = 0; g < 4; g++) {
                int dp = wn*32 + g*8 + 2*cq;
                int nh = ny*2 + (dp >> 6), d = dp & 63;
                float b0 = bias[nh*NHD + d], b1 = bias[nh*NHD + d + 1];
                stage[(dp  )*132 + ml    ] = acc[f][g][0] + b0;
                stage[(dp+1)*132 + ml    ] = acc[f][g][1] + b1;
                stage[(dp  )*132 + ml + 8] = acc[f][g][2] + b0;
                stage[(dp+1)*132 + ml + 8] = acc[f][g][3] + b1;
            }
        }
        __syncthreads();
        const int dp = tid >> 1, half = tid & 1;
        const int nh = ny*2 + (dp >> 6), d = dp & 63;
        float* dst = g_vt + ((size_t)(b*NHEAD + nh)*NHD + d)*NS + s0 + half*64;
        #pragma unroll
        for (int j4 = 0; j4 < 16; j4++) {
            float4 v;
            v.x = tf32r(stage[dp*132 + half*64 + j4*4 + 0]);
            v.y = tf32r(stage[dp*132 + half*64 + j4*4 + 1]);
            v.z = tf32r(stage[dp*132 + half*64 + j4*4 + 2]);
            v.w = tf32r(stage[dp*132 + half*64 + j4*4 + 3]);
            ((float4*)dst)[j4] = v;
        }
    }
}

// =============================================================================
// K3: fused flash attention.  2 blocks/SM (110KB smem), 32-wide KV tiles.
// smem floats: qs[64*68]=4352 | ks[2][32*68]=4352 | vs[2][64*36]=4608
//            | ps[64*36]=2304 | qb[64*132]=8448 | band fp16[64*128]=4096
// =============================================================================
#define FQ  0
#define FK  4352
#define FV  8704
#define FP  13312
#define FB  15616
#define FD  24064
#define FTOT 28160

__global__ __launch_bounds__(128) void attn_fused()
{
    extern __shared__ float sm[];
    float* qs   = sm + FQ;
    float* ks   = sm + FK;    // 2 x [32][68]; with vs forms rp_k [128][68] in prologue
    float* vs   = sm + FV;    // 2 x [64][36]
    float* ps   = sm + FP;    // [64][36]
    float* qb   = sm + FB;    // [64][132]
    __half* band = (__half*)(sm + FD);   // [64][128]

    const int tid = threadIdx.x, lane = tid & 31, w = tid >> 5;
    const int i0 = blockIdx.x * 64, bn = blockIdx.y;
    const int r = lane >> 2, cq = lane & 3;
    const int lr0 = w*16 + r;
    const int ia0 = i0 + lr0;

    // q tile (tf32-rounded) + rp_k [128 t][64 d] into ks∪vs region
    const float* qg = g_q + ((size_t)bn*NS + i0)*NHD;
    for (int e = tid; e < 64*64; e += 128) {
        int row = e >> 6, c = e & 63;
        qs[row*68 + c] = tf32r(qg[(size_t)row*NHD + c]);
    }
    float* rkp = ks;                       // [128][68] spans ks+vs (8704 <= 8960)
    for (int e = tid; e < 128*16; e += 128) {
        int row = e >> 4, c = e & 15;
        cpa16(s2u(rkp + row*68 + c*4), g_rpkp + (size_t)row*NHD + c*4);
    }
    cp_commit();
    cp_wait<0>();
    __syncthreads();

    // ---- prologue: qb[row][t] = q . rp_k[t] ----
    {
        float qacc[16][4];
        #pragma unroll
        for (int g = 0; g < 16; g++)
            #pragma unroll
            for (int e = 0; e < 4; e++) qacc[g][e] = 0.f;
        #pragma unroll
        for (int kk = 0; kk < 8; kk++) {
            const int k0 = kk*8;
            uint32_t a[4];
            a[0] = __float_as_uint(qs[(lr0  )*68 + k0 + cq    ]);
            a[1] = __float_as_uint(qs[(lr0+8)*68 + k0 + cq    ]);
            a[2] = __float_as_uint(qs[(lr0  )*68 + k0 + cq + 4]);
            a[3] = __float_as_uint(qs[(lr0+8)*68 + k0 + cq + 4]);
            #pragma unroll
            for (int g = 0; g < 16; g++) {
                uint32_t b[2];
                b[0] = __float_as_uint(rkp[(g*8+r)*68 + k0 + cq    ]);
                b[1] = __float_as_uint(rkp[(g*8+r)*68 + k0 + cq + 4]);
                mma8(qacc[g], a, b);
            }
        }
        #pragma unroll
        for (int g = 0; g < 16; g++) {
            const int t = g*8 + 2*cq;
            *(float2*)&qb[lr0*132 + t]     = make_float2(qacc[g][0], qacc[g][1]);
            *(float2*)&qb[(lr0+8)*132 + t] = make_float2(qacc[g][2], qacc[g][3]);
        }
    }
    __syncthreads();

    const float* kg = g_k + (size_t)bn*NS*NHD;
    const float* vg = g_vt + (size_t)bn*NHD*NS;

    auto ldK = [&](int jt, int buf) {
        for (int e = tid; e < 32*16; e += 128) {
            int row = e >> 4, c = e & 15;
            cpa16(s2u(ks + buf*2176 + row*68 + c*4), kg + (size_t)(jt*32+row)*NHD + c*4);
        }
    };
    auto ldV = [&](int jt, int buf) {
        for (int e = tid; e < 64*8; e += 128) {
            int d = e >> 3, c = e & 7;
            cpa16(s2u(vs + buf*2304 + d*36 + c*4), vg + (size_t)d*NS + jt*32 + c*4);
        }
    };
    ldK(0, 0); ldV(0, 0); cp_commit();

    float o[8][4];
    #pragma unroll
    for (int g = 0; g < 8; g++)
        #pragma unroll
        for (int e = 0; e < 4; e++) o[g][e] = 0.f;
    float m0v = -1e30f, m1v = -1e30f, l0 = 0.f, l1 = 0.f;
    float ls0 = 0.f, ls1 = 0.f, rs0 = 0.f, rs1 = 0.f;

    for (int jt = 0; jt < 32; jt++) {
        const int cur = jt & 1;
        if (jt < 31) { ldK(jt+1, cur^1); ldV(jt+1, cur^1); cp_commit(); cp_wait<1>(); }
        else cp_wait<0>();
        __syncthreads();

        // ---- QK^T (64 rows x 32 cols per block; 16x32 per warp) ----
        float s[4][4];
        #pragma unroll
        for (int g = 0; g < 4; g++)
            #pragma unroll
            for (int e = 0; e < 4; e++) s[g][e] = 0.f;
        const float* kb = ks + cur*2176;
        #pragma unroll
        for (int kk = 0; kk < 8; kk++) {
            const int k0 = kk*8;
            uint32_t a[4];
            a[0] = __float_as_uint(qs[(lr0  )*68 + k0 + cq    ]);
            a[1] = __float_as_uint(qs[(lr0+8)*68 + k0 + cq    ]);
            a[2] = __float_as_uint(qs[(lr0  )*68 + k0 + cq + 4]);
            a[3] = __float_as_uint(qs[(lr0+8)*68 + k0 + cq + 4]);
            #pragma unroll
            for (int g = 0; g < 4; g++) {
                uint32_t b[2];
                b[0] = __float_as_uint(kb[(g*8+r)*68 + k0 + cq    ]);
                b[1] = __float_as_uint(kb[(g*8+r)*68 + k0 + cq + 4]);
                mma8(s[g], a, b);
            }
        }
        // ---- bias + scale + band stash + row max ----
        float ml0 = -1e30f, ml1 = -1e30f;
        #pragma unroll
        for (int g = 0; g < 4; g++) {
            const int j0 = jt*32 + g*8 + 2*cq;
            const int t0 = j0 - ia0 + 63;
            const int t8 = t0 - 8;
            int c0 = t0 < 0 ? 0 : (t0 > 126 ? 126 : t0);
            int c1 = t0+1 < 0 ? 0 : (t0+1 > 126 ? 126 : t0+1);
            int c2 = t8 < 0 ? 0 : (t8 > 126 ? 126 : t8);
            int c3 = t8+1 < 0 ? 0 : (t8+1 > 126 ? 126 : t8+1);
            float v0 = (s[g][0] + qb[lr0*132 + c0]) * 0.125f;
            float v1 = (s[g][1] + qb[lr0*132 + c1]) * 0.125f;
            float v2 = (s[g][2] + qb[(lr0+8)*132 + c2]) * 0.125f;
            float v3 = (s[g][3] + qb[(lr0+8)*132 + c3]) * 0.125f;
            if (t0   >= 1 && t0   <= 125) band[lr0*128 + t0]       = __float2half(v0);
            if (t0+1 >= 1 && t0+1 <= 125) band[lr0*128 + t0+1]     = __float2half(v1);
            if (t8   >= 1 && t8   <= 125) band[(lr0+8)*128 + t8]   = __float2half(v2);
            if (t8+1 >= 1 && t8+1 <= 125) band[(lr0+8)*128 + t8+1] = __float2half(v3);
            s[g][0] = v0; s[g][1] = v1; s[g][2] = v2; s[g][3] = v3;
            ml0 = fmaxf(ml0, fmaxf(v0, v1));
            ml1 = fmaxf(ml1, fmaxf(v2, v3));
        }
        ml0 = fmaxf(ml0, __shfl_xor_sync(0xffffffffu, ml0, 1));
        ml0 = fmaxf(ml0, __shfl_xor_sync(0xffffffffu, ml0, 2));
        ml1 = fmaxf(ml1, __shfl_xor_sync(0xffffffffu, ml1, 1));
        ml1 = fmaxf(ml1, __shfl_xor_sync(0xffffffffu, ml1, 2));
        const float mn0 = fmaxf(m0v, ml0), mn1 = fmaxf(m1v, ml1);
        const float sc0 = __expf(m0v - mn0), sc1 = __expf(m1v - mn1);
        m0v = mn0; m1v = mn1;

        float su0 = 0.f, su1 = 0.f, pl0 = 0.f, pl1 = 0.f, pr0 = 0.f, pr1 = 0.f;
        #pragma unroll
        for (int g = 0; g < 4; g++) {
            const int j0 = jt*32 + g*8 + 2*cq;
            const int t0 = j0 - ia0 + 63;
            const int t8 = t0 - 8;
            float p0 = __expf(s[g][0] - mn0);
            float p1 = __expf(s[g][1] - mn0);
            float p2 = __expf(s[g][2] - mn1);
            float p3 = __expf(s[g][3] - mn1);
            su0 += p0 + p1; su1 += p2 + p3;
            if (t0   <= 0) pl0 += p0; else if (t0   >= 126) pr0 += p0;
            if (t0+1 <= 0) pl0 += p1; else if (t0+1 >= 126) pr0 += p1;
            if (t8   <= 0) pl1 += p2; else if (t8   >= 126) pr1 += p2;
            if (t8+1 <= 0) pl1 += p3; else if (t8+1 >= 126) pr1 += p3;
            s[g][0] = p0; s[g][1] = p1; s[g][2] = p2; s[g][3] = p3;
        }
        #pragma unroll
        for (int off = 1; off <= 2; off <<= 1) {
            su0 += __shfl_xor_sync(0xffffffffu, su0, off);
            su1 += __shfl_xor_sync(0xffffffffu, su1, off);
            pl0 += __shfl_xor_sync(0xffffffffu, pl0, off);
            pl1 += __shfl_xor_sync(0xffffffffu, pl1, off);
            pr0 += __shfl_xor_sync(0xffffffffu, pr0, off);
            pr1 += __shfl_xor_sync(0xffffffffu, pr1, off);
        }
        l0 = l0*sc0 + su0;  l1 = l1*sc1 + su1;
        ls0 = ls0*sc0 + pl0; ls1 = ls1*sc1 + pl1;
        rs0 = rs0*sc0 + pr0; rs1 = rs1*sc1 + pr1;
        #pragma unroll
        for (int g = 0; g < 8; g++) {
            o[g][0] *= sc0; o[g][1] *= sc0; o[g][2] *= sc1; o[g][3] *= sc1;
        }
        __syncthreads();
        #pragma unroll
        for (int g = 0; g < 4; g++) {
            const int jl = g*8 + 2*cq;
            *(float2*)&ps[lr0*36 + jl]     = make_float2(tf32r(s[g][0]), tf32r(s[g][1]));
            *(float2*)&ps[(lr0+8)*36 + jl] = make_float2(tf32r(s[g][2]), tf32r(s[g][3]));
        }
        __syncthreads();

        // ---- PV (k = 32 j) ----
        const float* vb = vs + cur*2304;
        #pragma unroll
        for (int kk = 0; kk < 4; kk++) {
            const int k0 = kk*8;
            uint32_t a[4];
            a[0] = __float_as_uint(ps[(lr0  )*36 + k0 + cq    ]);
            a[1] = __float_as_uint(ps[(lr0+8)*36 + k0 + cq    ]);
            a[2] = __float_as_uint(ps[(lr0  )*36 + k0 + cq + 4]);
            a[3] = __float_as_uint(ps[(lr0+8)*36 + k0 + cq + 4]);
            #pragma unroll
            for (int g = 0; g < 8; g++) {
                uint32_t b[2];
                b[0] = __float_as_uint(vb[(g*8+r)*36 + k0 + cq    ]);
                b[1] = __float_as_uint(vb[(g*8+r)*36 + k0 + cq + 4]);
                mma8(o[g], a, b);
            }
        }
    }

    // ---- epilogue ----
    const float inv0 = 1.f / l0, inv1 = 1.f / l1;
    #pragma unroll
    for (int g = 0; g < 8; g++) {
        o[g][0] *= inv0; o[g][1] *= inv0; o[g][2] *= inv1; o[g][3] *= inv1;
    }
    __syncthreads();

    // wb into qb (normalized, tf32)
    for (int t = cq; t < 128; t += 4) {
        float v0 = 0.f, v1 = 0.f;
        if (t == 0)        { v0 = ls0*inv0; v1 = ls1*inv1; }
        else if (t == 126) { v0 = rs0*inv0; v1 = rs1*inv1; }
        else if (t < 126) {
            int j0 = ia0 + t - 63;
            int j1 = j0 + 8;
            if (j0 >= 0 && j0 < NS) v0 = __expf(__half2float(band[lr0*128 + t]) - m0v) * inv0;
            if (j1 >= 0 && j1 < NS) v1 = __expf(__half2float(band[(lr0+8)*128 + t]) - m1v) * inv1;
        }
        qb[lr0*132 + t]     = tf32r(v0);
        qb[(lr0+8)*132 + t] = tf32r(v1);
    }
    __syncthreads();

    // two passes of 64 t-columns through the 2 x 32-wide V buffers
    for (int p = 0; p < 2; p++) {
        for (int e = tid; e < 64*16; e += 128) {
            int d = e >> 4, c = e & 15;
            int buf = c >> 3, cc = c & 7;
            cpa16(s2u(vs + buf*2304 + d*36 + cc*4),
                  g_rpvt + (size_t)d*NTABP + p*64 + buf*32 + cc*4);
        }
        cp_commit();
        cp_wait<0>();
        __syncthreads();
        #pragma unroll
        for (int kk = 0; kk < 8; kk++) {
            const float* vb = vs + (kk >> 2)*2304;
            const int k0 = (kk & 3)*8;
            const int tq = p*64 + kk*8;
            uint32_t a[4];
            a[0] = __float_as_uint(qb[(lr0  )*132 + tq + cq    ]);
            a[1] = __float_as_uint(qb[(lr0+8)*132 + tq + cq    ]);
            a[2] = __float_as_uint(qb[(lr0  )*132 + tq + cq + 4]);
            a[3] = __float_as_uint(qb[(lr0+8)*132 + tq + cq + 4]);
            #pragma unroll
            for (int g = 0; g < 8; g++) {
                uint32_t b[2];
                b[0] = __float_as_uint(vb[(g*8+r)*36 + k0 + cq    ]);
                b[1] = __float_as_uint(vb[(g*8+r)*36 + k0 + cq + 4]);
                mma8(o[g], a, b);
            }
        }
        __syncthreads();
    }

    const int b = bn >> 4, n = bn & 15;
    #pragma unroll
    for (int g = 0; g < 8; g++) {
        const int d = g*8 + 2*cq;
        float* p0 = g_ao + ((size_t)(b*NS + i0 + lr0))*NHID + n*NHD + d;
        float* p1 = g_ao + ((size_t)(b*NS + i0 + lr0 + 8))*NHID + n*NHD + d;
        *(float2*)p0 = make_float2(tf32r(o[g][0]), tf32r(o[g][1]));
        *(float2*)p1 = make_float2(tf32r(o[g][2]), tf32r(o[g][3]));
    }
}

// =============================================================================
// K5: final FC, 128x128 tiles.  grid (32, 8), 256 threads.
// =============================================================================
__global__ __launch_bounds__(256) void fc_mma(const float* __restrict__ bfc,
                                              float* __restrict__ out)
{
    extern __shared__ float sm[];
    float* As = sm;
    float* Bs = sm + 2*T_BUF;
    const int tid = threadIdx.x, lane = tid & 31, wid = tid >> 5;
    const int wm = wid & 1, wn = wid >> 1;
    const int m0 = blockIdx.x * 128, o0 = blockIdx.y * 128;

    const float* A0 = g_ao + (size_t)m0*NHID;
    const float* B0 = g_wfc + (size_t)o0*NHID;

    float acc[4][4][4];
    #pragma unroll
    for (int f = 0; f < 4; f++)
        #pragma unroll
        for (int g = 0; g < 4; g++)
            #pragma unroll
            for (int e = 0; e < 4; e++) acc[f][g][e] = 0.f;

    load_t(s2u(As), A0, NHID, tid);
    load_t(s2u(Bs), B0, NHID, tid);
    cp_commit();
    for (int kt = 0; kt < 32; kt++) {
        if (kt + 1 < 32) {
            int nb = (kt+1) & 1;
            load_t(s2u(As + nb*T_BUF), A0 + (kt+1)*32, NHID, tid);
            load_t(s2u(Bs + nb*T_BUF), B0 + (kt+1)*32, NHID, tid);
            cp_commit();
            cp_wait<1>();
        } else cp_wait<0>();
        __syncthreads();
        mma_tile(As + (kt&1)*T_BUF, Bs + (kt&1)*T_BUF, acc, wm, wn, lane);
        __syncthreads();
    }

    const int r = lane >> 2, cq = lane & 3;
    #pragma unroll
    for (int f = 0; f < 4; f++) {
        int m = m0 + wm*64 + f*16 + r;
        #pragma unroll
        for (int g = 0; g < 4; g++) {
            int o = o0 + wn*32 + g*8 + 2*cq;
            float b0 = bfc[o], b1 = bfc[o+1];
            *(float2*)&out[(size_t)m*NHID + o]     = make_float2(acc[f][g][0]+b0, acc[f][g][1]+b1);
            *(float2*)&out[(size_t)(m+8)*NHID + o] = make_float2(acc[f][g][2]+b0, acc[f][g][3]+b1);
        }
    }
}

// =============================================================================
extern "C" void kernel_launch(void* const* d_in, const int* in_sizes, int n_in,
                              void* d_out, int out_size)
{
    (void)in_sizes; (void)n_in; (void)out_size;
    const float* query = (const float*)d_in[0];
    const float* key   = (const float*)d_in[1];
    const float* value = (const float*)d_in[2];
    const float* Wq    = (const float*)d_in[3];
    const float* Wk    = (const float*)d_in[4];
    const float* Wv    = (const float*)d_in[5];
    const float* bq    = (const float*)d_in[6];
    const float* bk    = (const float*)d_in[7];
    const float* bv    = (const float*)d_in[8];
    const float* rpk   = (const float*)d_in[9];
    const float* rpv   = (const float*)d_in[10];
    const float* Wfc   = (const float*)d_in[11];
    const float* bfc   = (const float*)d_in[12];
    float* out = (float*)d_out;

    const int SMEM_FUSED = FTOT * 4;   // 112640 B -> 2 blocks/SM
    cudaFuncSetAttribute(proj_mma,   cudaFuncAttributeMaxDynamicSharedMemorySize, SMEM_GEMM);
    cudaFuncSetAttribute(fc_mma,     cudaFuncAttributeMaxDynamicSharedMemorySize, SMEM_GEMM);
    cudaFuncSetAttribute(attn_fused, cudaFuncAttributeMaxDynamicSharedMemorySize, SMEM_FUSED);

    // harness poison launch occupies slot #1 -> our 5th launch is global #6 (ncu -s 5)
    cvt_kernel<<<4096, 256>>>(query, 0, NM*NHID/4);                  // 2
    cvt_kernel<<<4096, 256>>>(key,   1, NM*NHID/4);                  // 3
    cvt_kernel<<<4096, 256>>>(value, 2, NM*NHID/4);                  // 4
    wt_kernel<<<dim3(16, 16, 3), 256>>>(Wq, Wk, Wv);                 // 5
    proj_mma<<<dim3(32, 8, 3), 256, SMEM_GEMM>>>(bq, bk, bv);        // 6 <- profiled
    rp_kernel<<<32, 256>>>(rpv, rpk);                                // 7
    cvt_kernel<<<1024, 256>>>(Wfc,   3, NHID*NHID/4);                // 8
    attn_fused<<<dim3(16, 64), 128, SMEM_FUSED>>>();                 // 9
    fc_mma<<<dim3(32, 8), 256, SMEM_GEMM>>>(bfc, out);               // 10
}

// round 7
// speedup vs baseline: 6.4297x; 1.6472x over previous
#include <cuda_runtime.h>
#include <cuda_fp16.h>
#include <cstdint>

#define NB    4
#define NS    1024
#define NHID  1024
#define NHEAD 16
#define NHD   64
#define NTAB  127
#define NTABP 128
#define BHS   (NB*NHEAD*NS)   // 65536
#define NM    (NB*NS)         // 4096

typedef __half h16;

// ---------------- scratch (device globals; no allocations allowed) ----------------
__device__ h16  g_x  [(size_t)3*NM*NHID];             // fp16 inputs (q,k,v)
__device__ h16  g_wt [(size_t)3*NHEAD*NHD*NHID];      // W^T per head fp16
__device__ h16  g_wfc[(size_t)NHID*NHID];             // Wfc fp16 ([o][k])
__device__ h16  g_q  [(size_t)BHS*NHD];               // q  [bn][s][d]
__device__ h16  g_k  [(size_t)BHS*NHD];               // k  [bn][s][d]
__device__ h16  g_vt [(size_t)BHS*NHD];               // v^T [bn][d][s]
__device__ h16  g_rpvt[NHD*NTABP];                    // rp_v^T (col 127 = 0)
__device__ h16  g_rpkp[NTABP*NHD];                    // rp_k padded [t][d]
__device__ h16  g_ao [(size_t)NM*NHID];               // attn out [b*s][hid]

// =============================== helpers =====================================
__device__ __forceinline__ uint32_t s2u(const void* p) {
    uint32_t a;
    asm("{ .reg .u64 t; cvta.to.shared.u64 t, %1; cvt.u32.u64 %0, t; }" : "=r"(a) : "l"(p));
    return a;
}
__device__ __forceinline__ void cpa16(uint32_t d, const void* s) {
    asm volatile("cp.async.cg.shared.global [%0], [%1], 16;" :: "r"(d), "l"(s));
}
__device__ __forceinline__ void cp_commit() { asm volatile("cp.async.commit_group;"); }
template<int N> __device__ __forceinline__ void cp_wait() {
    asm volatile("cp.async.wait_group %0;" :: "n"(N));
}
// fp16 MMA: D(16x8,f32) += A(16x16,f16) B(16x8,f16)
__device__ __forceinline__ void mma16(float* c, const uint32_t* a, const uint32_t* b) {
    asm volatile(
        "mma.sync.aligned.m16n8k16.row.col.f32.f16.f16.f32 "
        "{%0,%1,%2,%3}, {%4,%5,%6,%7}, {%8,%9}, {%0,%1,%2,%3};"
        : "+f"(c[0]), "+f"(c[1]), "+f"(c[2]), "+f"(c[3])
        : "r"(a[0]), "r"(a[1]), "r"(a[2]), "r"(a[3]), "r"(b[0]), "r"(b[1]));
}
__device__ __forceinline__ uint32_t ldh2(const h16* p) { return *(const uint32_t*)p; }

#define TS 72            // halfs per smem tile row (72/2=36 == 4 mod 32 -> conflict-free)
#define T_BUF (128*TS)   // halfs per buffer
#define SMEM_GEMM (4*T_BUF*2)   // 73728 B

// 128x64-half tile from global (ld halfs), 256 threads
__device__ __forceinline__ void load_t(uint32_t ts, const h16* __restrict__ G, int ld, int tid) {
    #pragma unroll
    for (int i = 0; i < 4; i++) {
        int idx = tid + i*256;
        int m = idx >> 3, ch = idx & 7;
        cpa16(ts + (uint32_t)(m*TS + ch*8)*2, G + (size_t)m*ld + ch*8);
    }
}

// warp tile 64x32 over K=64: 4 k-steps x 4 m-frags x 4 n-frags
__device__ __forceinline__ void mma_tile(const h16* __restrict__ As, const h16* __restrict__ Bs,
                                         float acc[4][4][4], int wm, int wn, int lane) {
    const int r = lane >> 2, cq2 = (lane & 3)*2;
    #pragma unroll
    for (int ks = 0; ks < 4; ks++) {
        const int k0 = ks*16;
        uint32_t a[4][4], b[4][2];
        #pragma unroll
        for (int f = 0; f < 4; f++) {
            const int bm = wm*64 + f*16;
            a[f][0] = ldh2(&As[(bm + r    )*TS + k0 + cq2    ]);
            a[f][1] = ldh2(&As[(bm + r + 8)*TS + k0 + cq2    ]);
            a[f][2] = ldh2(&As[(bm + r    )*TS + k0 + cq2 + 8]);
            a[f][3] = ldh2(&As[(bm + r + 8)*TS + k0 + cq2 + 8]);
        }
        #pragma unroll
        for (int g = 0; g < 4; g++) {
            const int bn = wn*32 + g*8;
            b[g][0] = ldh2(&Bs[(bn + r)*TS + k0 + cq2    ]);
            b[g][1] = ldh2(&Bs[(bn + r)*TS + k0 + cq2 + 8]);
        }
        #pragma unroll
        for (int f = 0; f < 4; f++)
            #pragma unroll
            for (int g = 0; g < 4; g++) mma16(acc[f][g], a[f], b[g]);
    }
}

// =============================================================================
// C0: fp32 -> fp16 copy
__global__ __launch_bounds__(256) void cvt_kernel(const float* __restrict__ in, int mode, int n4)
{
    int i = blockIdx.x * 256 + threadIdx.x;
    if (i >= n4) return;
    h16* dst = (mode < 3) ? (g_x + (size_t)mode*NM*NHID) : g_wfc;
    float4 v = ((const float4*)in)[i];
    __half2 h0 = __floats2half2_rn(v.x, v.y);
    __half2 h1 = __floats2half2_rn(v.z, v.w);
    uint2 u; u.x = *(uint32_t*)&h0; u.y = *(uint32_t*)&h1;
    ((uint2*)dst)[i] = u;
}

// C1: transpose + convert per-head weights  W[op][n][h][d] -> Wt[op][n][d][h]
__global__ __launch_bounds__(256) void wt_kernel(const float* __restrict__ wq,
                                                 const float* __restrict__ wk,
                                                 const float* __restrict__ wv)
{
    __shared__ float tile[64*65];
    const int hb = blockIdx.x, n = blockIdx.y, op = blockIdx.z;
    const float* W = (op==0 ? wq : (op==1 ? wk : wv)) + ((size_t)n*NHID + hb*64)*NHD;
    for (int e = threadIdx.x; e < 64*64; e += 256) {
        int h = e >> 6, d = e & 63;
        tile[h*65 + d] = W[(size_t)h*NHD + d];
    }
    __syncthreads();
    size_t ob = ((size_t)(op*NHEAD + n)*NHD)*NHID + hb*64;
    for (int e = threadIdx.x; e < 64*64; e += 256) {
        int d = e >> 6, h = e & 63;
        g_wt[ob + (size_t)d*NHID + h] = __float2half(tile[h*65 + d]);
    }
}

// C2: rp_v^T + padded rp_k, fp16
__global__ __launch_bounds__(256) void rp_kernel(const float* __restrict__ rpv,
                                                 const float* __restrict__ rpk)
{
    int e = blockIdx.x * 256 + threadIdx.x;
    if (e < NHD*NTABP) {
        int d = e >> 7, t = e & 127;
        float v = (t < NTAB) ? rpv[(size_t)t*NHD + d] : 0.f;
        g_rpvt[(size_t)d*NTABP + t] = __float2half(v);
    }
    if (e < NTABP*NHD) {
        int t = e >> 6, d = e & 63;
        float v = (t < NTAB) ? rpk[(size_t)t*NHD + d] : 0.f;
        g_rpkp[e] = __float2half(v);
    }
}

// =============================================================================
// K1: QKV projection, 128x128 tiles, fp16 MMA.  grid (32, 8, 3), 256 thr.
// =============================================================================
__global__ __launch_bounds__(256) void proj_mma(const float* __restrict__ bq_,
                                                const float* __restrict__ bk_,
                                                const float* __restrict__ bv_)
{
    extern __shared__ char smc[];
    h16* As = (h16*)smc;
    h16* Bs = (h16*)(smc + 2*T_BUF*2);
    const int tid = threadIdx.x, lane = tid & 31, wid = tid >> 5;
    const int wm = wid & 1, wn = wid >> 1;
    const int m0 = blockIdx.x * 128, ny = blockIdx.y, op = blockIdx.z;

    const h16* A0 = g_x + (size_t)op*NM*NHID + (size_t)m0*NHID;
    const h16* B0 = g_wt + (size_t)(op*NHEAD + ny*2)*NHD*NHID;

    float acc[4][4][4];
    #pragma unroll
    for (int f = 0; f < 4; f++)
        #pragma unroll
        for (int g = 0; g < 4; g++)
            #pragma unroll
            for (int e = 0; e < 4; e++) acc[f][g][e] = 0.f;

    load_t(s2u(As), A0, NHID, tid);
    load_t(s2u(Bs), B0, NHID, tid);
    cp_commit();
    for (int kt = 0; kt < 16; kt++) {
        if (kt + 1 < 16) {
            int nb = (kt+1) & 1;
            load_t(s2u(As + nb*T_BUF), A0 + (kt+1)*64, NHID, tid);
            load_t(s2u(Bs + nb*T_BUF), B0 + (kt+1)*64, NHID, tid);
            cp_commit();
            cp_wait<1>();
        } else cp_wait<0>();
        __syncthreads();
        mma_tile(As + (kt&1)*T_BUF, Bs + (kt&1)*T_BUF, acc, wm, wn, lane);
        __syncthreads();
    }

    const int b = m0 >> 10, s0 = m0 & 1023;
    const int r = lane >> 2, cq = lane & 3;
    const float* bias = (op == 0) ? bq_ : ((op == 1) ? bk_ : bv_);

    if (op < 2) {
        h16* outb = op ? g_k : g_q;
        #pragma unroll
        for (int f = 0; f < 4; f++) {
            int ml = wm*64 + f*16 + r;
            #pragma unroll
            for (int g = 0; g < 4; g++) {
                int dp = wn*32 + g*8 + 2*cq;
                int nh = ny*2 + (dp >> 6), d = dp & 63;
                float b0 = bias[nh*NHD + d], b1 = bias[nh*NHD + d + 1];
                h16* out = outb + ((size_t)(b*NHEAD + nh)*NS + s0)*NHD;
                *(__half2*)&out[(size_t)ml*NHD + d] =
                    __floats2half2_rn(acc[f][g][0]+b0, acc[f][g][1]+b1);
                *(__half2*)&out[(size_t)(ml+8)*NHD + d] =
                    __floats2half2_rn(acc[f][g][2]+b0, acc[f][g][3]+b1);
            }
        }
    } else {
        h16* stage = (h16*)smc;                   // [128 dp][136]  34816B
        #pragma unroll
        for (int f = 0; f < 4; f++) {
            int ml = wm*64 + f*16 + r;
            #pragma unroll
            for (int g = 0; g < 4; g++) {
                int dp = wn*32 + g*8 + 2*cq;
                int nh = ny*2 + (dp >> 6), d = dp & 63;
                float b0 = bias[nh*NHD + d], b1 = bias[nh*NHD + d + 1];
                stage[(dp  )*136 + ml    ] = __float2half(acc[f][g][0] + b0);
                stage[(dp+1)*136 + ml    ] = __float2half(acc[f][g][1] + b1);
                stage[(dp  )*136 + ml + 8] = __float2half(acc[f][g][2] + b0);
                stage[(dp+1)*136 + ml + 8] = __float2half(acc[f][g][3] + b1);
            }
        }
        __syncthreads();
        const int dp = tid >> 1, half_ = tid & 1;
        const int nh = ny*2 + (dp >> 6), d = dp & 63;
        h16* dst = g_vt + ((size_t)(b*NHEAD + nh)*NHD + d)*NS + s0 + half_*64;
        const uint4* src = (const uint4*)(stage + dp*136 + half_*64);
        #pragma unroll
        for (int j = 0; j < 8; j++) ((uint4*)dst)[j] = src[j];
    }
}

// =============================================================================
// K3: fused flash attention, fp16 MMA.
// smem (bytes): qs[64][72]h @0 | ks 2x[32][72]h @9216 | vs 2x[64][40]h @18432
//   ps[64][40]h @28672 | wbh[64][136]h @33792 | band[64][128]h @51200
//   qb[64][132]f @67584 | total 101376
// =============================================================================
#define ATTN_SMEM 101376
#define KBUF (32*72)
#define VBUF (64*40)

__global__ __launch_bounds__(128) void attn_fused()
{
    extern __shared__ char smc[];
    h16*  qs   = (h16*)(smc);
    h16*  ks   = (h16*)(smc + 9216);
    h16*  vs   = (h16*)(smc + 18432);
    h16*  ps   = (h16*)(smc + 28672);
    h16*  wbh  = (h16*)(smc + 33792);
    h16*  band = (h16*)(smc + 51200);
    float* qb  = (float*)(smc + 67584);

    const int tid = threadIdx.x, lane = tid & 31, w = tid >> 5;
    const int i0 = blockIdx.x * 64, bn = blockIdx.y;
    const int r = lane >> 2, cq = lane & 3;
    const int cq2 = cq*2;
    const int lr0 = w*16 + r;
    const int ia0 = i0 + lr0;

    // q tile + rp_k [128 t][64 d] (overlay on ks+vs)
    const h16* qg = g_q + ((size_t)bn*NS + i0)*NHD;
    for (int e = tid; e < 64*8; e += 128) {
        int row = e >> 3, ch = e & 7;
        cpa16(s2u(qs + row*72 + ch*8), qg + (size_t)row*NHD + ch*8);
    }
    h16* rkp = ks;                       // [128][72] halfs = 18432B
    for (int e = tid; e < 128*8; e += 128) {
        int row = e >> 3, ch = e & 7;
        cpa16(s2u(rkp + row*72 + ch*8), g_rpkp + (size_t)row*NHD + ch*8);
    }
    cp_commit();
    cp_wait<0>();
    __syncthreads();

    // ---- prologue: qb[row][t] = q . rp_k[t] ----
    {
        float qacc[16][4];
        #pragma unroll
        for (int g = 0; g < 16; g++)
            #pragma unroll
            for (int e = 0; e < 4; e++) qacc[g][e] = 0.f;
        #pragma unroll
        for (int kk = 0; kk < 4; kk++) {
            const int k0 = kk*16;
            uint32_t a[4];
            a[0] = ldh2(&qs[(lr0  )*72 + k0 + cq2    ]);
            a[1] = ldh2(&qs[(lr0+8)*72 + k0 + cq2    ]);
            a[2] = ldh2(&qs[(lr0  )*72 + k0 + cq2 + 8]);
            a[3] = ldh2(&qs[(lr0+8)*72 + k0 + cq2 + 8]);
            #pragma unroll
            for (int g = 0; g < 16; g++) {
                uint32_t b[2];
                b[0] = ldh2(&rkp[(g*8+r)*72 + k0 + cq2    ]);
                b[1] = ldh2(&rkp[(g*8+r)*72 + k0 + cq2 + 8]);
                mma16(qacc[g], a, b);
            }
        }
        #pragma unroll
        for (int g = 0; g < 16; g++) {
            const int t = g*8 + cq2;
            *(float2*)&qb[lr0*132 + t]     = make_float2(qacc[g][0], qacc[g][1]);
            *(float2*)&qb[(lr0+8)*132 + t] = make_float2(qacc[g][2], qacc[g][3]);
        }
    }
    __syncthreads();

    const h16* kg = g_k + (size_t)bn*NS*NHD;
    const h16* vg = g_vt + (size_t)bn*NHD*NS;

    auto ldK = [&](int jt, int buf) {
        for (int e = tid; e < 32*8; e += 128) {
            int row = e >> 3, ch = e & 7;
            cpa16(s2u(ks + buf*KBUF + row*72 + ch*8), kg + (size_t)(jt*32+row)*NHD + ch*8);
        }
    };
    auto ldV = [&](int jt, int buf) {
        for (int e = tid; e < 64*4; e += 128) {
            int d = e >> 2, ch = e & 3;
            cpa16(s2u(vs + buf*VBUF + d*40 + ch*8), vg + (size_t)d*NS + jt*32 + ch*8);
        }
    };
    ldK(0, 0); ldV(0, 0); cp_commit();

    float o[8][4];
    #pragma unroll
    for (int g = 0; g < 8; g++)
        #pragma unroll
        for (int e = 0; e < 4; e++) o[g][e] = 0.f;
    float m0v = -1e30f, m1v = -1e30f, l0 = 0.f, l1 = 0.f;
    float ls0 = 0.f, ls1 = 0.f, rs0 = 0.f, rs1 = 0.f;

    for (int jt = 0; jt < 32; jt++) {
        const int cur = jt & 1;
        __syncthreads();   // protect buf cur^1 (still prefetch target) & prior PV reads
        if (jt < 31) { ldK(jt+1, cur^1); ldV(jt+1, cur^1); cp_commit(); cp_wait<1>(); }
        else cp_wait<0>();
        __syncthreads();

        // ---- QK^T (64 x 32) ----
        float s[4][4];
        #pragma unroll
        for (int g = 0; g < 4; g++)
            #pragma unroll
            for (int e = 0; e < 4; e++) s[g][e] = 0.f;
        const h16* kb = ks + cur*KBUF;
        #pragma unroll
        for (int kk = 0; kk < 4; kk++) {
            const int k0 = kk*16;
            uint32_t a[4];
            a[0] = ldh2(&qs[(lr0  )*72 + k0 + cq2    ]);
            a[1] = ldh2(&qs[(lr0+8)*72 + k0 + cq2    ]);
            a[2] = ldh2(&qs[(lr0  )*72 + k0 + cq2 + 8]);
            a[3] = ldh2(&qs[(lr0+8)*72 + k0 + cq2 + 8]);
            #pragma unroll
            for (int g = 0; g < 4; g++) {
                uint32_t b[2];
                b[0] = ldh2(&kb[(g*8+r)*72 + k0 + cq2    ]);
                b[1] = ldh2(&kb[(g*8+r)*72 + k0 + cq2 + 8]);
                mma16(s[g], a, b);
            }
        }
        // ---- bias + scale + band stash + row max ----
        float ml0 = -1e30f, ml1 = -1e30f;
        #pragma unroll
        for (int g = 0; g < 4; g++) {
            const int j0 = jt*32 + g*8 + cq2;
            const int t0 = j0 - ia0 + 63;
            const int t8 = t0 - 8;
            int c0 = t0 < 0 ? 0 : (t0 > 126 ? 126 : t0);
            int c1 = t0+1 < 0 ? 0 : (t0+1 > 126 ? 126 : t0+1);
            int c2 = t8 < 0 ? 0 : (t8 > 126 ? 126 : t8);
            int c3 = t8+1 < 0 ? 0 : (t8+1 > 126 ? 126 : t8+1);
            float v0 = (s[g][0] + qb[lr0*132 + c0]) * 0.125f;
            float v1 = (s[g][1] + qb[lr0*132 + c1]) * 0.125f;
            float v2 = (s[g][2] + qb[(lr0+8)*132 + c2]) * 0.125f;
            float v3 = (s[g][3] + qb[(lr0+8)*132 + c3]) * 0.125f;
            if (t0   >= 1 && t0   <= 125) band[lr0*128 + t0]       = __float2half(v0);
            if (t0+1 >= 1 && t0+1 <= 125) band[lr0*128 + t0+1]     = __float2half(v1);
            if (t8   >= 1 && t8   <= 125) band[(lr0+8)*128 + t8]   = __float2half(v2);
            if (t8+1 >= 1 && t8+1 <= 125) band[(lr0+8)*128 + t8+1] = __float2half(v3);
            s[g][0] = v0; s[g][1] = v1; s[g][2] = v2; s[g][3] = v3;
            ml0 = fmaxf(ml0, fmaxf(v0, v1));
            ml1 = fmaxf(ml1, fmaxf(v2, v3));
        }
        ml0 = fmaxf(ml0, __shfl_xor_sync(0xffffffffu, ml0, 1));
        ml0 = fmaxf(ml0, __shfl_xor_sync(0xffffffffu, ml0, 2));
        ml1 = fmaxf(ml1, __shfl_xor_sync(0xffffffffu, ml1, 1));
        ml1 = fmaxf(ml1, __shfl_xor_sync(0xffffffffu, ml1, 2));
        const float mn0 = fmaxf(m0v, ml0), mn1 = fmaxf(m1v, ml1);
        const float sc0 = __expf(m0v - mn0), sc1 = __expf(m1v - mn1);
        m0v = mn0; m1v = mn1;

        float su0 = 0.f, su1 = 0.f, pl0 = 0.f, pl1 = 0.f, pr0 = 0.f, pr1 = 0.f;
        #pragma unroll
        for (int g = 0; g < 4; g++) {
            const int j0 = jt*32 + g*8 + cq2;
            const int t0 = j0 - ia0 + 63;
            const int t8 = t0 - 8;
            float p0 = __expf(s[g][0] - mn0);
            float p1 = __expf(s[g][1] - mn0);
            float p2 = __expf(s[g][2] - mn1);
            float p3 = __expf(s[g][3] - mn1);
            su0 += p0 + p1; su1 += p2 + p3;
            if (t0   <= 0) pl0 += p0; else if (t0   >= 126) pr0 += p0;
            if (t0+1 <= 0) pl0 += p1; else if (t0+1 >= 126) pr0 += p1;
            if (t8   <= 0) pl1 += p2; else if (t8   >= 126) pr1 += p2;
            if (t8+1 <= 0) pl1 += p3; else if (t8+1 >= 126) pr1 += p3;
            s[g][0] = p0; s[g][1] = p1; s[g][2] = p2; s[g][3] = p3;
        }
        #pragma unroll
        for (int off = 1; off <= 2; off <<= 1) {
            su0 += __shfl_xor_sync(0xffffffffu, su0, off);
            su1 += __shfl_xor_sync(0xffffffffu, su1, off);
            pl0 += __shfl_xor_sync(0xffffffffu, pl0, off);
            pl1 += __shfl_xor_sync(0xffffffffu, pl1, off);
            pr0 += __shfl_xor_sync(0xffffffffu, pr0, off);
            pr1 += __shfl_xor_sync(0xffffffffu, pr1, off);
        }
        l0 = l0*sc0 + su0;  l1 = l1*sc1 + su1;
        ls0 = ls0*sc0 + pl0; ls1 = ls1*sc1 + pl1;
        rs0 = rs0*sc0 + pr0; rs1 = rs1*sc1 + pr1;
        #pragma unroll
        for (int g = 0; g < 8; g++) {
            o[g][0] *= sc0; o[g][1] *= sc0; o[g][2] *= sc1; o[g][3] *= sc1;
        }
        __syncthreads();
        #pragma unroll
        for (int g = 0; g < 4; g++) {
            const int jl = g*8 + cq2;
            *(__half2*)&ps[lr0*40 + jl]     = __floats2half2_rn(s[g][0], s[g][1]);
            *(__half2*)&ps[(lr0+8)*40 + jl] = __floats2half2_rn(s[g][2], s[g][3]);
        }
        __syncthreads();

        // ---- PV (k = 32 j, 2 k-steps) ----
        const h16* vb = vs + cur*VBUF;
        #pragma unroll
        for (int kk = 0; kk < 2; kk++) {
            const int k0 = kk*16;
            uint32_t a[4];
            a[0] = ldh2(&ps[(lr0  )*40 + k0 + cq2    ]);
            a[1] = ldh2(&ps[(lr0+8)*40 + k0 + cq2    ]);
            a[2] = ldh2(&ps[(lr0  )*40 + k0 + cq2 + 8]);
            a[3] = ldh2(&ps[(lr0+8)*40 + k0 + cq2 + 8]);
            #pragma unroll
            for (int g = 0; g < 8; g++) {
                uint32_t b[2];
                b[0] = ldh2(&vb[(g*8+r)*40 + k0 + cq2    ]);
                b[1] = ldh2(&vb[(g*8+r)*40 + k0 + cq2 + 8]);
                mma16(o[g], a, b);
            }
        }
    }

    // ---- epilogue ----
    const float inv0 = 1.f / l0, inv1 = 1.f / l1;
    #pragma unroll
    for (int g = 0; g < 8; g++) {
        o[g][0] *= inv0; o[g][1] *= inv0; o[g][2] *= inv1; o[g][3] *= inv1;
    }
    __syncthreads();

    // wb (fp16) into wbh
    for (int t = cq; t < 128; t += 4) {
        float v0 = 0.f, v1 = 0.f;
        if (t == 0)        { v0 = ls0*inv0; v1 = ls1*inv1; }
        else if (t == 126) { v0 = rs0*inv0; v1 = rs1*inv1; }
        else if (t < 126) {
            int j0 = ia0 + t - 63;
            int j1 = j0 + 8;
            if (j0 >= 0 && j0 < NS) v0 = __expf(__half2float(band[lr0*128 + t]) - m0v) * inv0;
            if (j1 >= 0 && j1 < NS) v1 = __expf(__half2float(band[(lr0+8)*128 + t]) - m1v) * inv1;
        }
        wbh[lr0*136 + t]     = __float2half(v0);
        wbh[(lr0+8)*136 + t] = __float2half(v1);
    }
    __syncthreads();

    // two passes of 64 t-columns: rp_v^T into vs region [64 d][72]
    for (int p = 0; p < 2; p++) {
        h16* rvs = vs;
        for (int e = tid; e < 64*8; e += 128) {
            int d = e >> 3, ch = e & 7;
            cpa16(s2u(rvs + d*72 + ch*8), g_rpvt + (size_t)d*NTABP + p*64 + ch*8);
        }
        cp_commit();
        cp_wait<0>();
        __syncthreads();
        #pragma unroll
        for (int kk = 0; kk < 4; kk++) {
            const int k0 = kk*16;
            const int tq = p*64 + k0;
            uint32_t a[4];
            a[0] = ldh2(&wbh[(lr0  )*136 + tq + cq2    ]);
            a[1] = ldh2(&wbh[(lr0+8)*136 + tq + cq2    ]);
            a[2] = ldh2(&wbh[(lr0  )*136 + tq + cq2 + 8]);
            a[3] = ldh2(&wbh[(lr0+8)*136 + tq + cq2 + 8]);
            #pragma unroll
            for (int g = 0; g < 8; g++) {
                uint32_t b[2];
                b[0] = ldh2(&rvs[(g*8+r)*72 + k0 + cq2    ]);
                b[1] = ldh2(&rvs[(g*8+r)*72 + k0 + cq2 + 8]);
                mma16(o[g], a, b);
            }
        }
        __syncthreads();
    }

    const int b = bn >> 4, n = bn & 15;
    #pragma unroll
    for (int g = 0; g < 8; g++) {
        const int d = g*8 + cq2;
        h16* p0 = g_ao + ((size_t)(b*NS + i0 + lr0))*NHID + n*NHD + d;
        h16* p1 = g_ao + ((size_t)(b*NS + i0 + lr0 + 8))*NHID + n*NHD + d;
        *(__half2*)p0 = __floats2half2_rn(o[g][0], o[g][1]);
        *(__half2*)p1 = __floats2half2_rn(o[g][2], o[g][3]);
    }
}

// =============================================================================
// K5: final FC, 128x128 tiles, fp16 MMA.  grid (32, 8), 256 threads.
// =============================================================================
__global__ __launch_bounds__(256) void fc_mma(const float* __restrict__ bfc,
                                              float* __restrict__ out)
{
    extern __shared__ char smc[];
    h16* As = (h16*)smc;
    h16* Bs = (h16*)(smc + 2*T_BUF*2);
    const int tid = threadIdx.x, lane = tid & 31, wid = tid >> 5;
    const int wm = wid & 1, wn = wid >> 1;
    const int m0 = blockIdx.x * 128, o0 = blockIdx.y * 128;

    const h16* A0 = g_ao + (size_t)m0*NHID;
    const h16* B0 = g_wfc + (size_t)o0*NHID;

    float acc[4][4][4];
    #pragma unroll
    for (int f = 0; f < 4; f++)
        #pragma unroll
        for (int g = 0; g < 4; g++)
            #pragma unroll
            for (int e = 0; e < 4; e++) acc[f][g][e] = 0.f;

    load_t(s2u(As), A0, NHID, tid);
    load_t(s2u(Bs), B0, NHID, tid);
    cp_commit();
    for (int kt = 0; kt < 16; kt++) {
        if (kt + 1 < 16) {
            int nb = (kt+1) & 1;
            load_t(s2u(As + nb*T_BUF), A0 + (kt+1)*64, NHID, tid);
            load_t(s2u(Bs + nb*T_BUF), B0 + (kt+1)*64, NHID, tid);
            cp_commit();
            cp_wait<1>();
        } else cp_wait<0>();
        __syncthreads();
        mma_tile(As + (kt&1)*T_BUF, Bs + (kt&1)*T_BUF, acc, wm, wn, lane);
        __syncthreads();
    }

    const int r = lane >> 2, cq = lane & 3;
    #pragma unroll
    for (int f = 0; f < 4; f++) {
        int m = m0 + wm*64 + f*16 + r;
        #pragma unroll
        for (int g = 0; g < 4; g++) {
            int o = o0 + wn*32 + g*8 + 2*cq;
            float b0 = bfc[o], b1 = bfc[o+1];
            *(float2*)&out[(size_t)m*NHID + o]     = make_float2(acc[f][g][0]+b0, acc[f][g][1]+b1);
            *(float2*)&out[(size_t)(m+8)*NHID + o] = make_float2(acc[f][g][2]+b0, acc[f][g][3]+b1);
        }
    }
}

// =============================================================================
extern "C" void kernel_launch(void* const* d_in, const int* in_sizes, int n_in,
                              void* d_out, int out_size)
{
    (void)in_sizes; (void)n_in; (void)out_size;
    const float* query = (const float*)d_in[0];
    const float* key   = (const float*)d_in[1];
    const float* value = (const float*)d_in[2];
    const float* Wq    = (const float*)d_in[3];
    const float* Wk    = (const float*)d_in[4];
    const float* Wv    = (const float*)d_in[5];
    const float* bq    = (const float*)d_in[6];
    const float* bk    = (const float*)d_in[7];
    const float* bv    = (const float*)d_in[8];
    const float* rpk   = (const float*)d_in[9];
    const float* rpv   = (const float*)d_in[10];
    const float* Wfc   = (const float*)d_in[11];
    const float* bfc   = (const float*)d_in[12];
    float* out = (float*)d_out;

    cudaFuncSetAttribute(proj_mma,   cudaFuncAttributeMaxDynamicSharedMemorySize, SMEM_GEMM);
    cudaFuncSetAttribute(fc_mma,     cudaFuncAttributeMaxDynamicSharedMemorySize, SMEM_GEMM);
    cudaFuncSetAttribute(attn_fused, cudaFuncAttributeMaxDynamicSharedMemorySize, ATTN_SMEM);

    // harness poison launch occupies slot #1 -> proj_mma lands on global #6 (ncu -s 5)
    cvt_kernel<<<4096, 256>>>(query, 0, NM*NHID/4);                  // 2
    cvt_kernel<<<4096, 256>>>(key,   1, NM*NHID/4);                  // 3
    cvt_kernel<<<4096, 256>>>(value, 2, NM*NHID/4);                  // 4
    wt_kernel<<<dim3(16, 16, 3), 256>>>(Wq, Wk, Wv);                 // 5
    proj_mma<<<dim3(32, 8, 3), 256, SMEM_GEMM>>>(bq, bk, bv);        // 6 <- profiled
    rp_kernel<<<32, 256>>>(rpv, rpk);                                // 7
    cvt_kernel<<<1024, 256>>>(Wfc,   3, NHID*NHID/4);                // 8
    attn_fused<<<dim3(16, 64), 128, ATTN_SMEM>>>();                  // 9
    fc_mma<<<dim3(32, 8), 256, SMEM_GEMM>>>(bfc, out);               // 10
}

// round 8
// speedup vs baseline: 7.4247x; 1.1547x over previous
#include <cuda_runtime.h>
#include <cuda_fp16.h>
#include <cstdint>

#define NB    4
#define NS    1024
#define NHID  1024
#define NHEAD 16
#define NHD   64
#define NTAB  127
#define NTABP 128
#define BHS   (NB*NHEAD*NS)   // 65536
#define NM    (NB*NS)         // 4096

typedef __half h16;

// ---------------- scratch (device globals; no allocations allowed) ----------------
__device__ h16  g_x  [(size_t)3*NM*NHID];             // fp16 inputs (q,k,v)
__device__ h16  g_wt [(size_t)3*NHEAD*NHD*NHID];      // W^T per head fp16
__device__ h16  g_wfc[(size_t)NHID*NHID];             // Wfc fp16 ([o][k])
__device__ h16  g_q  [(size_t)BHS*NHD];               // q  [bn][s][d]
__device__ h16  g_k  [(size_t)BHS*NHD];               // k  [bn][s][d]
__device__ h16  g_vt [(size_t)BHS*NHD];               // v^T [bn][d][s]
__device__ h16  g_rpvt[NHD*NTABP];                    // rp_v^T (col 127 = 0)
__device__ h16  g_rpkp[NTABP*NHD];                    // rp_k padded [t][d]
__device__ h16  g_ao [(size_t)NM*NHID];               // attn out [b*s][hid]

// =============================== helpers =====================================
__device__ __forceinline__ uint32_t s2u(const void* p) {
    uint32_t a;
    asm("{ .reg .u64 t; cvta.to.shared.u64 t, %1; cvt.u32.u64 %0, t; }" : "=r"(a) : "l"(p));
    return a;
}
__device__ __forceinline__ void cpa16(uint32_t d, const void* s) {
    asm volatile("cp.async.cg.shared.global [%0], [%1], 16;" :: "r"(d), "l"(s));
}
__device__ __forceinline__ void cp_commit() { asm volatile("cp.async.commit_group;"); }
template<int N> __device__ __forceinline__ void cp_wait() {
    asm volatile("cp.async.wait_group %0;" :: "n"(N));
}
__device__ __forceinline__ void mma16(float* c, const uint32_t* a, const uint32_t* b) {
    asm volatile(
        "mma.sync.aligned.m16n8k16.row.col.f32.f16.f16.f32 "
        "{%0,%1,%2,%3}, {%4,%5,%6,%7}, {%8,%9}, {%0,%1,%2,%3};"
        : "+f"(c[0]), "+f"(c[1]), "+f"(c[2]), "+f"(c[3])
        : "r"(a[0]), "r"(a[1]), "r"(a[2]), "r"(a[3]), "r"(b[0]), "r"(b[1]));
}
__device__ __forceinline__ uint32_t ldh2(const h16* p) { return *(const uint32_t*)p; }

#define TS 72            // halfs per smem tile row (36 words == 4 mod 32 -> conflict-free)
#define T_BUF (128*TS)
#define SMEM_GEMM (4*T_BUF*2)   // 73728 B

__device__ __forceinline__ void load_t(uint32_t ts, const h16* __restrict__ G, int ld, int tid) {
    #pragma unroll
    for (int i = 0; i < 4; i++) {
        int idx = tid + i*256;
        int m = idx >> 3, ch = idx & 7;
        cpa16(ts + (uint32_t)(m*TS + ch*8)*2, G + (size_t)m*ld + ch*8);
    }
}

__device__ __forceinline__ void mma_tile(const h16* __restrict__ As, const h16* __restrict__ Bs,
                                         float acc[4][4][4], int wm, int wn, int lane) {
    const int r = lane >> 2, cq2 = (lane & 3)*2;
    #pragma unroll
    for (int ks = 0; ks < 4; ks++) {
        const int k0 = ks*16;
        uint32_t a[4][4], b[4][2];
        #pragma unroll
        for (int f = 0; f < 4; f++) {
            const int bm = wm*64 + f*16;
            a[f][0] = ldh2(&As[(bm + r    )*TS + k0 + cq2    ]);
            a[f][1] = ldh2(&As[(bm + r + 8)*TS + k0 + cq2    ]);
            a[f][2] = ldh2(&As[(bm + r    )*TS + k0 + cq2 + 8]);
            a[f][3] = ldh2(&As[(bm + r + 8)*TS + k0 + cq2 + 8]);
        }
        #pragma unroll
        for (int g = 0; g < 4; g++) {
            const int bn = wn*32 + g*8;
            b[g][0] = ldh2(&Bs[(bn + r)*TS + k0 + cq2    ]);
            b[g][1] = ldh2(&Bs[(bn + r)*TS + k0 + cq2 + 8]);
        }
        #pragma unroll
        for (int f = 0; f < 4; f++)
            #pragma unroll
            for (int g = 0; g < 4; g++) mma16(acc[f][g], a[f], b[g]);
    }
}

// =============================================================================
// C0a: q/k/v fp32 -> fp16 in one launch.  grid (4096, 3)
__global__ __launch_bounds__(256) void cvt3_kernel(const float* __restrict__ q,
                                                   const float* __restrict__ k,
                                                   const float* __restrict__ v)
{
    int i = blockIdx.x * 256 + threadIdx.x;
    int mode = blockIdx.y;
    const float* in = (mode == 0) ? q : ((mode == 1) ? k : v);
    h16* dst = g_x + (size_t)mode*NM*NHID;
    float4 val = ((const float4*)in)[i];
    __half2 h0 = __floats2half2_rn(val.x, val.y);
    __half2 h1 = __floats2half2_rn(val.z, val.w);
    uint2 u; u.x = *(uint32_t*)&h0; u.y = *(uint32_t*)&h1;
    ((uint2*)dst)[i] = u;
}

// C0b: Wfc fp32 -> fp16
__global__ __launch_bounds__(256) void cvtw_kernel(const float* __restrict__ in)
{
    int i = blockIdx.x * 256 + threadIdx.x;
    float4 v = ((const float4*)in)[i];
    __half2 h0 = __floats2half2_rn(v.x, v.y);
    __half2 h1 = __floats2half2_rn(v.z, v.w);
    uint2 u; u.x = *(uint32_t*)&h0; u.y = *(uint32_t*)&h1;
    ((uint2*)g_wfc)[i] = u;
}

// C1: weights transpose + rp tables, merged.  grid (16, 16, 3)
__global__ __launch_bounds__(256) void prep_kernel(const float* __restrict__ wq,
                                                   const float* __restrict__ wk,
                                                   const float* __restrict__ wv,
                                                   const float* __restrict__ rpv,
                                                   const float* __restrict__ rpk)
{
    __shared__ float tile[64*65];
    const int hb = blockIdx.x, n = blockIdx.y, op = blockIdx.z;
    const float* W = (op==0 ? wq : (op==1 ? wk : wv)) + ((size_t)n*NHID + hb*64)*NHD;
    for (int e = threadIdx.x; e < 64*64; e += 256) {
        int h = e >> 6, d = e & 63;
        tile[h*65 + d] = W[(size_t)h*NHD + d];
    }
    __syncthreads();
    size_t ob = ((size_t)(op*NHEAD + n)*NHD)*NHID + hb*64;
    for (int e = threadIdx.x; e < 64*64; e += 256) {
        int d = e >> 6, h = e & 63;
        g_wt[ob + (size_t)d*NHID + h] = __float2half(tile[h*65 + d]);
    }
    if (op == 0 && n == 0 && hb == 0) {
        for (int e = threadIdx.x; e < NHD*NTABP; e += 256) {
            int d = e >> 7, t = e & 127;
            float v = (t < NTAB) ? rpv[(size_t)t*NHD + d] : 0.f;
            g_rpvt[(size_t)d*NTABP + t] = __float2half(v);
        }
    }
    if (op == 0 && n == 0 && hb == 1) {
        for (int e = threadIdx.x; e < NTABP*NHD; e += 256) {
            int t = e >> 6, d = e & 63;
            float v = (t < NTAB) ? rpk[(size_t)t*NHD + d] : 0.f;
            g_rpkp[e] = __float2half(v);
        }
    }
}

// =============================================================================
// K1: QKV projection, 128x128 tiles, fp16 MMA.  grid (32, 8, 3), 256 thr.
// =============================================================================
__global__ __launch_bounds__(256) void proj_mma(const float* __restrict__ bq_,
                                                const float* __restrict__ bk_,
                                                const float* __restrict__ bv_)
{
    extern __shared__ char smc[];
    h16* As = (h16*)smc;
    h16* Bs = (h16*)(smc + 2*T_BUF*2);
    const int tid = threadIdx.x, lane = tid & 31, wid = tid >> 5;
    const int wm = wid & 1, wn = wid >> 1;
    const int m0 = blockIdx.x * 128, ny = blockIdx.y, op = blockIdx.z;

    const h16* A0 = g_x + (size_t)op*NM*NHID + (size_t)m0*NHID;
    const h16* B0 = g_wt + (size_t)(op*NHEAD + ny*2)*NHD*NHID;

    float acc[4][4][4];
    #pragma unroll
    for (int f = 0; f < 4; f++)
        #pragma unroll
        for (int g = 0; g < 4; g++)
            #pragma unroll
            for (int e = 0; e < 4; e++) acc[f][g][e] = 0.f;

    load_t(s2u(As), A0, NHID, tid);
    load_t(s2u(Bs), B0, NHID, tid);
    cp_commit();
    for (int kt = 0; kt < 16; kt++) {
        if (kt + 1 < 16) {
            int nb = (kt+1) & 1;
            load_t(s2u(As + nb*T_BUF), A0 + (kt+1)*64, NHID, tid);
            load_t(s2u(Bs + nb*T_BUF), B0 + (kt+1)*64, NHID, tid);
            cp_commit();
            cp_wait<1>();
        } else cp_wait<0>();
        __syncthreads();
        mma_tile(As + (kt&1)*T_BUF, Bs + (kt&1)*T_BUF, acc, wm, wn, lane);
        __syncthreads();
    }

    const int b = m0 >> 10, s0 = m0 & 1023;
    const int r = lane >> 2, cq = lane & 3;
    const float* bias = (op == 0) ? bq_ : ((op == 1) ? bk_ : bv_);

    if (op < 2) {
        h16* outb = op ? g_k : g_q;
        #pragma unroll
        for (int f = 0; f < 4; f++) {
            int ml = wm*64 + f*16 + r;
            #pragma unroll
            for (int g = 0; g < 4; g++) {
                int dp = wn*32 + g*8 + 2*cq;
                int nh = ny*2 + (dp >> 6), d = dp & 63;
                float b0 = bias[nh*NHD + d], b1 = bias[nh*NHD + d + 1];
                h16* out = outb + ((size_t)(b*NHEAD + nh)*NS + s0)*NHD;
                *(__half2*)&out[(size_t)ml*NHD + d] =
                    __floats2half2_rn(acc[f][g][0]+b0, acc[f][g][1]+b1);
                *(__half2*)&out[(size_t)(ml+8)*NHD + d] =
                    __floats2half2_rn(acc[f][g][2]+b0, acc[f][g][3]+b1);
            }
        }
    } else {
        h16* stage = (h16*)smc;                   // [128 dp][136]
        #pragma unroll
        for (int f = 0; f < 4; f++) {
            int ml = wm*64 + f*16 + r;
            #pragma unroll
            for (int g = 0; g < 4; g++) {
                int dp = wn*32 + g*8 + 2*cq;
                int nh = ny*2 + (dp >> 6), d = dp & 63;
                float b0 = bias[nh*NHD + d], b1 = bias[nh*NHD + d + 1];
                stage[(dp  )*136 + ml    ] = __float2half(acc[f][g][0] + b0);
                stage[(dp+1)*136 + ml    ] = __float2half(acc[f][g][1] + b1);
                stage[(dp  )*136 + ml + 8] = __float2half(acc[f][g][2] + b0);
                stage[(dp+1)*136 + ml + 8] = __float2half(acc[f][g][3] + b1);
            }
        }
        __syncthreads();
        const int dp = tid >> 1, half_ = tid & 1;
        const int nh = ny*2 + (dp >> 6), d = dp & 63;
        h16* dst = g_vt + ((size_t)(b*NHEAD + nh)*NHD + d)*NS + s0 + half_*64;
        const uint4* src = (const uint4*)(stage + dp*136 + half_*64);
        #pragma unroll
        for (int j = 0; j < 8; j++) ((uint4*)dst)[j] = src[j];
    }
}

// =============================================================================
// K3: fused flash attention, fp16 MMA, no-max softmax, deferred reductions.
// smem bytes: qs[64][72]h @0 | ks 2x[64][72]h @9216 | vs 2x[64][72]h @27648
//   ps[64][72]h @46080 | band[64][128]h @55296 | qb[64][132]f @71680  = 105472
// =============================================================================
#define ATTN_SMEM 105472
#define KBUF (64*72)

__global__ __launch_bounds__(128) void attn_fused()
{
    extern __shared__ char smc[];
    h16*  qs   = (h16*)(smc);
    h16*  ks   = (h16*)(smc + 9216);
    h16*  vs   = (h16*)(smc + 27648);
    h16*  ps   = (h16*)(smc + 46080);
    h16*  band = (h16*)(smc + 55296);
    float* qb  = (float*)(smc + 71680);
    h16*  wbh  = (h16*)(smc + 71680);    // epilogue overlay on qb: [64][136]h

    const int tid = threadIdx.x, lane = tid & 31, w = tid >> 5;
    const int i0 = blockIdx.x * 64, bn = blockIdx.y;
    const int r = lane >> 2, cq = lane & 3;
    const int cq2 = cq*2;
    const int lr0 = w*16 + r;
    const int ia0 = i0 + lr0;

    // q tile + rp_k [128 t][64 d] overlay on ks (2 bufs = 18432B exactly)
    const h16* qg = g_q + ((size_t)bn*NS + i0)*NHD;
    for (int e = tid; e < 64*8; e += 128) {
        int row = e >> 3, ch = e & 7;
        cpa16(s2u(qs + row*72 + ch*8), qg + (size_t)row*NHD + ch*8);
    }
    h16* rkp = ks;
    for (int e = tid; e < 128*8; e += 128) {
        int row = e >> 3, ch = e & 7;
        cpa16(s2u(rkp + row*72 + ch*8), g_rpkp + (size_t)row*NHD + ch*8);
    }
    cp_commit();
    cp_wait<0>();
    __syncthreads();

    // ---- prologue: qb[row][t] = q . rp_k[t] ----
    {
        float qacc[16][4];
        #pragma unroll
        for (int g = 0; g < 16; g++)
            #pragma unroll
            for (int e = 0; e < 4; e++) qacc[g][e] = 0.f;
        #pragma unroll
        for (int kk = 0; kk < 4; kk++) {
            const int k0 = kk*16;
            uint32_t a[4];
            a[0] = ldh2(&qs[(lr0  )*72 + k0 + cq2    ]);
            a[1] = ldh2(&qs[(lr0+8)*72 + k0 + cq2    ]);
            a[2] = ldh2(&qs[(lr0  )*72 + k0 + cq2 + 8]);
            a[3] = ldh2(&qs[(lr0+8)*72 + k0 + cq2 + 8]);
            #pragma unroll
            for (int g = 0; g < 16; g++) {
                uint32_t b[2];
                b[0] = ldh2(&rkp[(g*8+r)*72 + k0 + cq2    ]);
                b[1] = ldh2(&rkp[(g*8+r)*72 + k0 + cq2 + 8]);
                mma16(qacc[g], a, b);
            }
        }
        #pragma unroll
        for (int g = 0; g < 16; g++) {
            const int t = g*8 + cq2;
            *(float2*)&qb[lr0*132 + t]     = make_float2(qacc[g][0], qacc[g][1]);
            *(float2*)&qb[(lr0+8)*132 + t] = make_float2(qacc[g][2], qacc[g][3]);
        }
    }
    __syncthreads();

    const h16* kg = g_k + (size_t)bn*NS*NHD;
    const h16* vg = g_vt + (size_t)bn*NHD*NS;

    auto ldK = [&](int jt, int buf) {
        for (int e = tid; e < 64*8; e += 128) {
            int row = e >> 3, ch = e & 7;
            cpa16(s2u(ks + buf*KBUF + row*72 + ch*8), kg + (size_t)(jt*64+row)*NHD + ch*8);
        }
    };
    auto ldV = [&](int jt, int buf) {
        for (int e = tid; e < 64*8; e += 128) {
            int d = e >> 3, ch = e & 7;
            cpa16(s2u(vs + buf*KBUF + d*72 + ch*8), vg + (size_t)d*NS + jt*64 + ch*8);
        }
    };
    ldK(0, 0); ldV(0, 0); cp_commit();

    float o[8][4];
    #pragma unroll
    for (int g = 0; g < 8; g++)
        #pragma unroll
        for (int e = 0; e < 4; e++) o[g][e] = 0.f;
    float l0 = 0.f, l1 = 0.f;          // per-thread partial row sums
    float ls0 = 0.f, ls1 = 0.f, rs0 = 0.f, rs1 = 0.f;

    for (int jt = 0; jt < 16; jt++) {
        const int cur = jt & 1;
        __syncthreads();   // prior MMA reads of buf cur^1 + prior PV reads of ps done
        if (jt < 15) { ldK(jt+1, cur^1); ldV(jt+1, cur^1); cp_commit(); cp_wait<1>(); }
        else cp_wait<0>();
        __syncthreads();

        // ---- QK^T (64 x 64) ----
        float s[8][4];
        #pragma unroll
        for (int g = 0; g < 8; g++)
            #pragma unroll
            for (int e = 0; e < 4; e++) s[g][e] = 0.f;
        const h16* kb = ks + cur*KBUF;
        #pragma unroll
        for (int kk = 0; kk < 4; kk++) {
            const int k0 = kk*16;
            uint32_t a[4];
            a[0] = ldh2(&qs[(lr0  )*72 + k0 + cq2    ]);
            a[1] = ldh2(&qs[(lr0+8)*72 + k0 + cq2    ]);
            a[2] = ldh2(&qs[(lr0  )*72 + k0 + cq2 + 8]);
            a[3] = ldh2(&qs[(lr0+8)*72 + k0 + cq2 + 8]);
            #pragma unroll
            for (int g = 0; g < 8; g++) {
                uint32_t b[2];
                b[0] = ldh2(&kb[(g*8+r)*72 + k0 + cq2    ]);
                b[1] = ldh2(&kb[(g*8+r)*72 + k0 + cq2 + 8]);
                mma16(s[g], a, b);
            }
        }
        // ---- bias + exp (no max shift) + band stash + partial sums ----
        #pragma unroll
        for (int g = 0; g < 8; g++) {
            const int j0 = jt*64 + g*8 + cq2;
            const int t0 = j0 - ia0 + 63;
            const int t8 = t0 - 8;
            int c0 = t0 < 0 ? 0 : (t0 > 126 ? 126 : t0);
            int c1 = t0+1 < 0 ? 0 : (t0+1 > 126 ? 126 : t0+1);
            int c2 = t8 < 0 ? 0 : (t8 > 126 ? 126 : t8);
            int c3 = t8+1 < 0 ? 0 : (t8+1 > 126 ? 126 : t8+1);
            float p0 = __expf((s[g][0] + qb[lr0*132 + c0]) * 0.125f);
            float p1 = __expf((s[g][1] + qb[lr0*132 + c1]) * 0.125f);
            float p2 = __expf((s[g][2] + qb[(lr0+8)*132 + c2]) * 0.125f);
            float p3 = __expf((s[g][3] + qb[(lr0+8)*132 + c3]) * 0.125f);
            if (t0   >= 1 && t0   <= 125) band[lr0*128 + t0]       = __float2half(p0);
            if (t0+1 >= 1 && t0+1 <= 125) band[lr0*128 + t0+1]     = __float2half(p1);
            if (t8   >= 1 && t8   <= 125) band[(lr0+8)*128 + t8]   = __float2half(p2);
            if (t8+1 >= 1 && t8+1 <= 125) band[(lr0+8)*128 + t8+1] = __float2half(p3);
            l0 += p0 + p1; l1 += p2 + p3;
            if (t0   <= 0) ls0 += p0; else if (t0   >= 126) rs0 += p0;
            if (t0+1 <= 0) ls0 += p1; else if (t0+1 >= 126) rs0 += p1;
            if (t8   <= 0) ls1 += p2; else if (t8   >= 126) rs1 += p2;
            if (t8+1 <= 0) ls1 += p3; else if (t8+1 >= 126) rs1 += p3;
            s[g][0] = p0; s[g][1] = p1; s[g][2] = p2; s[g][3] = p3;
        }
        __syncthreads();     // safe: loop-top sync already separated prior PV reads
        #pragma unroll
        for (int g = 0; g < 8; g++) {
            const int jl = g*8 + cq2;
            *(__half2*)&ps[lr0*72 + jl]     = __floats2half2_rn(s[g][0], s[g][1]);
            *(__half2*)&ps[(lr0+8)*72 + jl] = __floats2half2_rn(s[g][2], s[g][3]);
        }
        __syncthreads();

        // ---- PV (k = 64 j, 4 k-steps) ----
        const h16* vb = vs + cur*KBUF;
        #pragma unroll
        for (int kk = 0; kk < 4; kk++) {
            const int k0 = kk*16;
            uint32_t a[4];
            a[0] = ldh2(&ps[(lr0  )*72 + k0 + cq2    ]);
            a[1] = ldh2(&ps[(lr0+8)*72 + k0 + cq2    ]);
            a[2] = ldh2(&ps[(lr0  )*72 + k0 + cq2 + 8]);
            a[3] = ldh2(&ps[(lr0+8)*72 + k0 + cq2 + 8]);
            #pragma unroll
            for (int g = 0; g < 8; g++) {
                uint32_t b[2];
                b[0] = ldh2(&vb[(g*8+r)*72 + k0 + cq2    ]);
                b[1] = ldh2(&vb[(g*8+r)*72 + k0 + cq2 + 8]);
                mma16(o[g], a, b);
            }
        }
    }

    // ---- epilogue: single reduction, normalize, wb MMA ----
    #pragma unroll
    for (int off = 1; off <= 2; off <<= 1) {
        l0  += __shfl_xor_sync(0xffffffffu, l0,  off);
        l1  += __shfl_xor_sync(0xffffffffu, l1,  off);
        ls0 += __shfl_xor_sync(0xffffffffu, ls0, off);
        ls1 += __shfl_xor_sync(0xffffffffu, ls1, off);
        rs0 += __shfl_xor_sync(0xffffffffu, rs0, off);
        rs1 += __shfl_xor_sync(0xffffffffu, rs1, off);
    }
    const float inv0 = 1.f / l0, inv1 = 1.f / l1;
    #pragma unroll
    for (int g = 0; g < 8; g++) {
        o[g][0] *= inv0; o[g][1] *= inv0; o[g][2] *= inv1; o[g][3] *= inv1;
    }
    __syncthreads();       // all PV + qb reads done; vs and qb reusable

    // rp_v^T [64 d][128 t] into vs region; wb (normalized) into wbh overlay
    for (int e = tid; e < 64*16; e += 128) {
        int d = e >> 4, ch = e & 15;
        cpa16(s2u(vs + d*136 + ch*8), g_rpvt + (size_t)d*NTABP + ch*8);
    }
    cp_commit();
    for (int t = cq; t < 128; t += 4) {
        float v0 = 0.f, v1 = 0.f;
        if (t == 0)        { v0 = ls0*inv0; v1 = ls1*inv1; }
        else if (t == 126) { v0 = rs0*inv0; v1 = rs1*inv1; }
        else if (t < 126) {
            int j0 = ia0 + t - 63;
            int j1 = j0 + 8;
            if (j0 >= 0 && j0 < NS) v0 = __half2float(band[lr0*128 + t]) * inv0;
            if (j1 >= 0 && j1 < NS) v1 = __half2float(band[(lr0+8)*128 + t]) * inv1;
        }
        wbh[lr0*136 + t]     = __float2half(v0);
        wbh[(lr0+8)*136 + t] = __float2half(v1);
    }
    cp_wait<0>();
    __syncthreads();

    #pragma unroll
    for (int kk = 0; kk < 8; kk++) {
        const int k0 = kk*16;
        uint32_t a[4];
        a[0] = ldh2(&wbh[(lr0  )*136 + k0 + cq2    ]);
        a[1] = ldh2(&wbh[(lr0+8)*136 + k0 + cq2    ]);
        a[2] = ldh2(&wbh[(lr0  )*136 + k0 + cq2 + 8]);
        a[3] = ldh2(&wbh[(lr0+8)*136 + k0 + cq2 + 8]);
        #pragma unroll
        for (int g = 0; g < 8; g++) {
            uint32_t b[2];
            b[0] = ldh2(&vs[(g*8+r)*136 + k0 + cq2    ]);
            b[1] = ldh2(&vs[(g*8+r)*136 + k0 + cq2 + 8]);
            mma16(o[g], a, b);
        }
    }

    const int b = bn >> 4, n = bn & 15;
    #pragma unroll
    for (int g = 0; g < 8; g++) {
        const int d = g*8 + cq2;
        h16* p0 = g_ao + ((size_t)(b*NS + i0 + lr0))*NHID + n*NHD + d;
        h16* p1 = g_ao + ((size_t)(b*NS + i0 + lr0 + 8))*NHID + n*NHD + d;
        *(__half2*)p0 = __floats2half2_rn(o[g][0], o[g][1]);
        *(__half2*)p1 = __floats2half2_rn(o[g][2], o[g][3]);
    }
}

// =============================================================================
// K5: final FC, 128x128 tiles, fp16 MMA.  grid (32, 8), 256 threads.
// =============================================================================
__global__ __launch_bounds__(256) void fc_mma(const float* __restrict__ bfc,
                                              float* __restrict__ out)
{
    extern __shared__ char smc[];
    h16* As = (h16*)smc;
    h16* Bs = (h16*)(smc + 2*T_BUF*2);
    const int tid = threadIdx.x, lane = tid & 31, wid = tid >> 5;
    const int wm = wid & 1, wn = wid >> 1;
    const int m0 = blockIdx.x * 128, o0 = blockIdx.y * 128;

    const h16* A0 = g_ao + (size_t)m0*NHID;
    const h16* B0 = g_wfc + (size_t)o0*NHID;

    float acc[4][4][4];
    #pragma unroll
    for (int f = 0; f < 4; f++)
        #pragma unroll
        for (int g = 0; g < 4; g++)
            #pragma unroll
            for (int e = 0; e < 4; e++) acc[f][g][e] = 0.f;

    load_t(s2u(As), A0, NHID, tid);
    load_t(s2u(Bs), B0, NHID, tid);
    cp_commit();
    for (int kt = 0; kt < 16; kt++) {
        if (kt + 1 < 16) {
            int nb = (kt+1) & 1;
            load_t(s2u(As + nb*T_BUF), A0 + (kt+1)*64, NHID, tid);
            load_t(s2u(Bs + nb*T_BUF), B0 + (kt+1)*64, NHID, tid);
            cp_commit();
            cp_wait<1>();
        } else cp_wait<0>();
        __syncthreads();
        mma_tile(As + (kt&1)*T_BUF, Bs + (kt&1)*T_BUF, acc, wm, wn, lane);
        __syncthreads();
    }

    const int r = lane >> 2, cq = lane & 3;
    #pragma unroll
    for (int f = 0; f < 4; f++) {
        int m = m0 + wm*64 + f*16 + r;
        #pragma unroll
        for (int g = 0; g < 4; g++) {
            int o = o0 + wn*32 + g*8 + 2*cq;
            float b0 = bfc[o], b1 = bfc[o+1];
            *(float2*)&out[(size_t)m*NHID + o]     = make_float2(acc[f][g][0]+b0, acc[f][g][1]+b1);
            *(float2*)&out[(size_t)(m+8)*NHID + o] = make_float2(acc[f][g][2]+b0, acc[f][g][3]+b1);
        }
    }
}

// =============================================================================
extern "C" void kernel_launch(void* const* d_in, const int* in_sizes, int n_in,
                              void* d_out, int out_size)
{
    (void)in_sizes; (void)n_in; (void)out_size;
    const float* query = (const float*)d_in[0];
    const float* key   = (const float*)d_in[1];
    const float* value = (const float*)d_in[2];
    const float* Wq    = (const float*)d_in[3];
    const float* Wk    = (const float*)d_in[4];
    const float* Wv    = (const float*)d_in[5];
    const float* bq    = (const float*)d_in[6];
    const float* bk    = (const float*)d_in[7];
    const float* bv    = (const float*)d_in[8];
    const float* rpk   = (const float*)d_in[9];
    const float* rpv   = (const float*)d_in[10];
    const float* Wfc   = (const float*)d_in[11];
    const float* bfc   = (const float*)d_in[12];
    float* out = (float*)d_out;

    cudaFuncSetAttribute(proj_mma,   cudaFuncAttributeMaxDynamicSharedMemorySize, SMEM_GEMM);
    cudaFuncSetAttribute(fc_mma,     cudaFuncAttributeMaxDynamicSharedMemorySize, SMEM_GEMM);
    cudaFuncSetAttribute(attn_fused, cudaFuncAttributeMaxDynamicSharedMemorySize, ATTN_SMEM);

    cvt3_kernel<<<dim3(4096, 3), 256>>>(query, key, value);          // 1
    prep_kernel<<<dim3(16, 16, 3), 256>>>(Wq, Wk, Wv, rpv, rpk);     // 2
    proj_mma<<<dim3(32, 8, 3), 256, SMEM_GEMM>>>(bq, bk, bv);        // 3
    attn_fused<<<dim3(16, 64), 128, ATTN_SMEM>>>();                  // 4 <- profiled
    cvtw_kernel<<<1024, 256>>>(Wfc);                                 // 5
    fc_mma<<<dim3(32, 8), 256, SMEM_GEMM>>>(bfc, out);               // 6
}

// round 9
// speedup vs baseline: 7.7235x; 1.0402x over previous
#include <cuda_runtime.h>
#include <cuda_fp16.h>
#include <cstdint>

#define NB    4
#define NS    1024
#define NHID  1024
#define NHEAD 16
#define NHD   64
#define NTAB  127
#define NTABP 128
#define BHS   (NB*NHEAD*NS)   // 65536
#define NM    (NB*NS)         // 4096

typedef __half h16;

// ---------------- scratch (device globals; no allocations allowed) ----------------
__device__ h16  g_x  [(size_t)3*NM*NHID];             // fp16 inputs (q,k,v)
__device__ h16  g_wt [(size_t)3*NHEAD*NHD*NHID];      // W^T per head fp16
__device__ h16  g_wfc[(size_t)NHID*NHID];             // Wfc fp16 ([o][k])
__device__ h16  g_q  [(size_t)BHS*NHD];               // q  [bn][s][d]
__device__ h16  g_k  [(size_t)BHS*NHD];               // k  [bn][s][d]
__device__ h16  g_vt [(size_t)BHS*NHD];               // v^T [bn][d][s]
__device__ h16  g_rpvt[NHD*NTABP];                    // rp_v^T (col 127 = 0)
__device__ h16  g_rpkp[NTABP*NHD];                    // rp_k padded [t][d]
__device__ h16  g_ao [(size_t)NM*NHID];               // attn out [b*s][hid]

// =============================== helpers =====================================
__device__ __forceinline__ uint32_t s2u(const void* p) {
    uint32_t a;
    asm("{ .reg .u64 t; cvta.to.shared.u64 t, %1; cvt.u32.u64 %0, t; }" : "=r"(a) : "l"(p));
    return a;
}
__device__ __forceinline__ void cpa16(uint32_t d, const void* s) {
    asm volatile("cp.async.cg.shared.global [%0], [%1], 16;" :: "r"(d), "l"(s));
}
__device__ __forceinline__ void cp_commit() { asm volatile("cp.async.commit_group;"); }
template<int N> __device__ __forceinline__ void cp_wait() {
    asm volatile("cp.async.wait_group %0;" :: "n"(N));
}
__device__ __forceinline__ void mma16(float* c, const uint32_t* a, const uint32_t* b) {
    asm volatile(
        "mma.sync.aligned.m16n8k16.row.col.f32.f16.f16.f32 "
        "{%0,%1,%2,%3}, {%4,%5,%6,%7}, {%8,%9}, {%0,%1,%2,%3};"
        : "+f"(c[0]), "+f"(c[1]), "+f"(c[2]), "+f"(c[3])
        : "r"(a[0]), "r"(a[1]), "r"(a[2]), "r"(a[3]), "r"(b[0]), "r"(b[1]));
}
__device__ __forceinline__ uint32_t ldh2(const h16* p) { return *(const uint32_t*)p; }

#define TS 72
#define T_BUF (128*TS)
#define SMEM_GEMM (4*T_BUF*2)   // 73728 B

__device__ __forceinline__ void load_t(uint32_t ts, const h16* __restrict__ G, int ld, int tid) {
    #pragma unroll
    for (int i = 0; i < 4; i++) {
        int idx = tid + i*256;
        int m = idx >> 3, ch = idx & 7;
        cpa16(ts + (uint32_t)(m*TS + ch*8)*2, G + (size_t)m*ld + ch*8);
    }
}

__device__ __forceinline__ void mma_tile(const h16* __restrict__ As, const h16* __restrict__ Bs,
                                         float acc[4][4][4], int wm, int wn, int lane) {
    const int r = lane >> 2, cq2 = (lane & 3)*2;
    #pragma unroll
    for (int ks = 0; ks < 4; ks++) {
        const int k0 = ks*16;
        uint32_t a[4][4], b[4][2];
        #pragma unroll
        for (int f = 0; f < 4; f++) {
            const int bm = wm*64 + f*16;
            a[f][0] = ldh2(&As[(bm + r    )*TS + k0 + cq2    ]);
            a[f][1] = ldh2(&As[(bm + r + 8)*TS + k0 + cq2    ]);
            a[f][2] = ldh2(&As[(bm + r    )*TS + k0 + cq2 + 8]);
            a[f][3] = ldh2(&As[(bm + r + 8)*TS + k0 + cq2 + 8]);
        }
        #pragma unroll
        for (int g = 0; g < 4; g++) {
            const int bn = wn*32 + g*8;
            b[g][0] = ldh2(&Bs[(bn + r)*TS + k0 + cq2    ]);
            b[g][1] = ldh2(&Bs[(bn + r)*TS + k0 + cq2 + 8]);
        }
        #pragma unroll
        for (int f = 0; f < 4; f++)
            #pragma unroll
            for (int g = 0; g < 4; g++) mma16(acc[f][g], a[f], b[g]);
    }
}

// =============================================================================
__global__ __launch_bounds__(256) void cvt3_kernel(const float* __restrict__ q,
                                                   const float* __restrict__ k,
                                                   const float* __restrict__ v)
{
    int i = blockIdx.x * 256 + threadIdx.x;
    int mode = blockIdx.y;
    const float* in = (mode == 0) ? q : ((mode == 1) ? k : v);
    h16* dst = g_x + (size_t)mode*NM*NHID;
    float4 val = ((const float4*)in)[i];
    __half2 h0 = __floats2half2_rn(val.x, val.y);
    __half2 h1 = __floats2half2_rn(val.z, val.w);
    uint2 u; u.x = *(uint32_t*)&h0; u.y = *(uint32_t*)&h1;
    ((uint2*)dst)[i] = u;
}

__global__ __launch_bounds__(256) void cvtw_kernel(const float* __restrict__ in)
{
    int i = blockIdx.x * 256 + threadIdx.x;
    float4 v = ((const float4*)in)[i];
    __half2 h0 = __floats2half2_rn(v.x, v.y);
    __half2 h1 = __floats2half2_rn(v.z, v.w);
    uint2 u; u.x = *(uint32_t*)&h0; u.y = *(uint32_t*)&h1;
    ((uint2*)g_wfc)[i] = u;
}

__global__ __launch_bounds__(256) void prep_kernel(const float* __restrict__ wq,
                                                   const float* __restrict__ wk,
                                                   const float* __restrict__ wv,
                                                   const float* __restrict__ rpv,
                                                   const float* __restrict__ rpk)
{
    __shared__ float tile[64*65];
    const int hb = blockIdx.x, n = blockIdx.y, op = blockIdx.z;
    const float* W = (op==0 ? wq : (op==1 ? wk : wv)) + ((size_t)n*NHID + hb*64)*NHD;
    for (int e = threadIdx.x; e < 64*64; e += 256) {
        int h = e >> 6, d = e & 63;
        tile[h*65 + d] = W[(size_t)h*NHD + d];
    }
    __syncthreads();
    size_t ob = ((size_t)(op*NHEAD + n)*NHD)*NHID + hb*64;
    for (int e = threadIdx.x; e < 64*64; e += 256) {
        int d = e >> 6, h = e & 63;
        g_wt[ob + (size_t)d*NHID + h] = __float2half(tile[h*65 + d]);
    }
    if (op == 0 && n == 0 && hb == 0) {
        for (int e = threadIdx.x; e < NHD*NTABP; e += 256) {
            int d = e >> 7, t = e & 127;
            float v = (t < NTAB) ? rpv[(size_t)t*NHD + d] : 0.f;
            g_rpvt[(size_t)d*NTABP + t] = __float2half(v);
        }
    }
    if (op == 0 && n == 0 && hb == 1) {
        for (int e = threadIdx.x; e < NTABP*NHD; e += 256) {
            int t = e >> 6, d = e & 63;
            float v = (t < NTAB) ? rpk[(size_t)t*NHD + d] : 0.f;
            g_rpkp[e] = __float2half(v);
        }
    }
}

// =============================================================================
// K1: QKV projection, 128x128 tiles, fp16 MMA.  grid (32, 8, 3), 256 thr.
// =============================================================================
__global__ __launch_bounds__(256) void proj_mma(const float* __restrict__ bq_,
                                                const float* __restrict__ bk_,
                                                const float* __restrict__ bv_)
{
    extern __shared__ char smc[];
    h16* As = (h16*)smc;
    h16* Bs = (h16*)(smc + 2*T_BUF*2);
    const int tid = threadIdx.x, lane = tid & 31, wid = tid >> 5;
    const int wm = wid & 1, wn = wid >> 1;
    const int m0 = blockIdx.x * 128, ny = blockIdx.y, op = blockIdx.z;

    const h16* A0 = g_x + (size_t)op*NM*NHID + (size_t)m0*NHID;
    const h16* B0 = g_wt + (size_t)(op*NHEAD + ny*2)*NHD*NHID;

    float acc[4][4][4];
    #pragma unroll
    for (int f = 0; f < 4; f++)
        #pragma unroll
        for (int g = 0; g < 4; g++)
            #pragma unroll
            for (int e = 0; e < 4; e++) acc[f][g][e] = 0.f;

    load_t(s2u(As), A0, NHID, tid);
    load_t(s2u(Bs), B0, NHID, tid);
    cp_commit();
    for (int kt = 0; kt < 16; kt++) {
        if (kt + 1 < 16) {
            int nb = (kt+1) & 1;
            load_t(s2u(As + nb*T_BUF), A0 + (kt+1)*64, NHID, tid);
            load_t(s2u(Bs + nb*T_BUF), B0 + (kt+1)*64, NHID, tid);
            cp_commit();
            cp_wait<1>();
        } else cp_wait<0>();
        __syncthreads();
        mma_tile(As + (kt&1)*T_BUF, Bs + (kt&1)*T_BUF, acc, wm, wn, lane);
        __syncthreads();
    }

    const int b = m0 >> 10, s0 = m0 & 1023;
    const int r = lane >> 2, cq = lane & 3;
    const float* bias = (op == 0) ? bq_ : ((op == 1) ? bk_ : bv_);

    if (op < 2) {
        h16* outb = op ? g_k : g_q;
        #pragma unroll
        for (int f = 0; f < 4; f++) {
            int ml = wm*64 + f*16 + r;
            #pragma unroll
            for (int g = 0; g < 4; g++) {
                int dp = wn*32 + g*8 + 2*cq;
                int nh = ny*2 + (dp >> 6), d = dp & 63;
                float b0 = bias[nh*NHD + d], b1 = bias[nh*NHD + d + 1];
                h16* out = outb + ((size_t)(b*NHEAD + nh)*NS + s0)*NHD;
                *(__half2*)&out[(size_t)ml*NHD + d] =
                    __floats2half2_rn(acc[f][g][0]+b0, acc[f][g][1]+b1);
                *(__half2*)&out[(size_t)(ml+8)*NHD + d] =
                    __floats2half2_rn(acc[f][g][2]+b0, acc[f][g][3]+b1);
            }
        }
    } else {
        h16* stage = (h16*)smc;                   // [128 dp][136]
        #pragma unroll
        for (int f = 0; f < 4; f++) {
            int ml = wm*64 + f*16 + r;
            #pragma unroll
            for (int g = 0; g < 4; g++) {
                int dp = wn*32 + g*8 + 2*cq;
                int nh = ny*2 + (dp >> 6), d = dp & 63;
                float b0 = bias[nh*NHD + d], b1 = bias[nh*NHD + d + 1];
                stage[(dp  )*136 + ml    ] = __float2half(acc[f][g][0] + b0);
                stage[(dp+1)*136 + ml    ] = __float2half(acc[f][g][1] + b1);
                stage[(dp  )*136 + ml + 8] = __float2half(acc[f][g][2] + b0);
                stage[(dp+1)*136 + ml + 8] = __float2half(acc[f][g][3] + b1);
            }
        }
        __syncthreads();
        const int dp = tid >> 1, half_ = tid & 1;
        const int nh = ny*2 + (dp >> 6), d = dp & 63;
        h16* dst = g_vt + ((size_t)(b*NHEAD + nh)*NHD + d)*NS + s0 + half_*64;
        const uint4* src = (const uint4*)(stage + dp*136 + half_*64);
        #pragma unroll
        for (int j = 0; j < 8; j++) ((uint4*)dst)[j] = src[j];
    }
}

// =============================================================================
// K3: fused flash attention, fp16 MMA, no-max softmax, band-tile specialization.
// smem bytes: qs[64][72]h @0 | ks 2x[64][72]h @9216 | vs 2x[64][72]h @27648
//   ps[64][72]h @46080 | band[64][128]h @55296 | qb[64][132]f @71680  = 105472
// =============================================================================
#define ATTN_SMEM 105472
#define KBUF (64*72)

__global__ __launch_bounds__(128) void attn_fused()
{
    extern __shared__ char smc[];
    h16*  qs   = (h16*)(smc);
    h16*  ks   = (h16*)(smc + 9216);
    h16*  vs   = (h16*)(smc + 27648);
    h16*  ps   = (h16*)(smc + 46080);
    h16*  band = (h16*)(smc + 55296);
    float* qb  = (float*)(smc + 71680);
    h16*  wbh  = (h16*)(smc + 71680);    // epilogue overlay on qb: [64][136]h

    const int tid = threadIdx.x, lane = tid & 31, w = tid >> 5;
    const int i0 = blockIdx.x * 64, bn = blockIdx.y;
    const int r = lane >> 2, cq = lane & 3;
    const int cq2 = cq*2;
    const int lr0 = w*16 + r;
    const int ia0 = i0 + lr0;

    // q tile + rp_k overlay on ks
    const h16* qg = g_q + ((size_t)bn*NS + i0)*NHD;
    for (int e = tid; e < 64*8; e += 128) {
        int row = e >> 3, ch = e & 7;
        cpa16(s2u(qs + row*72 + ch*8), qg + (size_t)row*NHD + ch*8);
    }
    h16* rkp = ks;
    for (int e = tid; e < 128*8; e += 128) {
        int row = e >> 3, ch = e & 7;
        cpa16(s2u(rkp + row*72 + ch*8), g_rpkp + (size_t)row*NHD + ch*8);
    }
    // zero band (garbage-tolerant slots 0/126; rows with unvisited t stay 0)
    for (int e = tid; e < 64*128/8; e += 128)
        ((uint4*)band)[e] = make_uint4(0,0,0,0);
    cp_commit();
    cp_wait<0>();
    __syncthreads();

    // ---- prologue: qb[row][t] = q . rp_k[t] ----
    {
        float qacc[16][4];
        #pragma unroll
        for (int g = 0; g < 16; g++)
            #pragma unroll
            for (int e = 0; e < 4; e++) qacc[g][e] = 0.f;
        #pragma unroll
        for (int kk = 0; kk < 4; kk++) {
            const int k0 = kk*16;
            uint32_t a[4];
            a[0] = ldh2(&qs[(lr0  )*72 + k0 + cq2    ]);
            a[1] = ldh2(&qs[(lr0+8)*72 + k0 + cq2    ]);
            a[2] = ldh2(&qs[(lr0  )*72 + k0 + cq2 + 8]);
            a[3] = ldh2(&qs[(lr0+8)*72 + k0 + cq2 + 8]);
            #pragma unroll
            for (int g = 0; g < 16; g++) {
                uint32_t b[2];
                b[0] = ldh2(&rkp[(g*8+r)*72 + k0 + cq2    ]);
                b[1] = ldh2(&rkp[(g*8+r)*72 + k0 + cq2 + 8]);
                mma16(qacc[g], a, b);
            }
        }
        #pragma unroll
        for (int g = 0; g < 16; g++) {
            const int t = g*8 + cq2;
            *(float2*)&qb[lr0*132 + t]     = make_float2(qacc[g][0], qacc[g][1]);
            *(float2*)&qb[(lr0+8)*132 + t] = make_float2(qacc[g][2], qacc[g][3]);
        }
    }
    __syncthreads();

    // per-row far-region multipliers
    const float el0 = __expf(qb[lr0*132 +   0] * 0.125f);
    const float er0 = __expf(qb[lr0*132 + 126] * 0.125f);
    const float el1 = __expf(qb[(lr0+8)*132 +   0] * 0.125f);
    const float er1 = __expf(qb[(lr0+8)*132 + 126] * 0.125f);

    const h16* kg = g_k + (size_t)bn*NS*NHD;
    const h16* vg = g_vt + (size_t)bn*NHD*NS;

    auto ldK = [&](int jt, int buf) {
        for (int e = tid; e < 64*8; e += 128) {
            int row = e >> 3, ch = e & 7;
            cpa16(s2u(ks + buf*KBUF + row*72 + ch*8), kg + (size_t)(jt*64+row)*NHD + ch*8);
        }
    };
    auto ldV = [&](int jt, int buf) {
        for (int e = tid; e < 64*8; e += 128) {
            int d = e >> 3, ch = e & 7;
            cpa16(s2u(vs + buf*KBUF + d*72 + ch*8), vg + (size_t)d*NS + jt*64 + ch*8);
        }
    };
    ldK(0, 0); ldV(0, 0); cp_commit();

    float o[8][4];
    #pragma unroll
    for (int g = 0; g < 8; g++)
        #pragma unroll
        for (int e = 0; e < 4; e++) o[g][e] = 0.f;
    float l0 = 0.f, l1 = 0.f;            // total row sums (partial per thread)
    float rs0 = 0.f, rs1 = 0.f;          // right-far sums (t>=126)

    for (int jt = 0; jt < 16; jt++) {
        const int cur = jt & 1;
        __syncthreads();
        if (jt < 15) { ldK(jt+1, cur^1); ldV(jt+1, cur^1); cp_commit(); cp_wait<1>(); }
        else cp_wait<0>();
        __syncthreads();

        // ---- QK^T (64 x 64) ----
        float s[8][4];
        #pragma unroll
        for (int g = 0; g < 8; g++)
            #pragma unroll
            for (int e = 0; e < 4; e++) s[g][e] = 0.f;
        const h16* kb = ks + cur*KBUF;
        #pragma unroll
        for (int kk = 0; kk < 4; kk++) {
            const int k0 = kk*16;
            uint32_t a[4];
            a[0] = ldh2(&qs[(lr0  )*72 + k0 + cq2    ]);
            a[1] = ldh2(&qs[(lr0+8)*72 + k0 + cq2    ]);
            a[2] = ldh2(&qs[(lr0  )*72 + k0 + cq2 + 8]);
            a[3] = ldh2(&qs[(lr0+8)*72 + k0 + cq2 + 8]);
            #pragma unroll
            for (int g = 0; g < 8; g++) {
                uint32_t b[2];
                b[0] = ldh2(&kb[(g*8+r)*72 + k0 + cq2    ]);
                b[1] = ldh2(&kb[(g*8+r)*72 + k0 + cq2 + 8]);
                mma16(s[g], a, b);
            }
        }

        // ---- softmax numerators: specialized by tile/band relation ----
        const int d64 = jt*64 - i0;
        if (d64 <= -128) {                     // fully left-far: bias qb[0]
            #pragma unroll
            for (int g = 0; g < 8; g++) {
                float p0 = __expf(s[g][0]*0.125f)*el0;
                float p1 = __expf(s[g][1]*0.125f)*el0;
                float p2 = __expf(s[g][2]*0.125f)*el1;
                float p3 = __expf(s[g][3]*0.125f)*el1;
                l0 += p0 + p1; l1 += p2 + p3;
                s[g][0]=p0; s[g][1]=p1; s[g][2]=p2; s[g][3]=p3;
            }
        } else if (d64 >= 128) {               // fully right-far: bias qb[126]
            #pragma unroll
            for (int g = 0; g < 8; g++) {
                float p0 = __expf(s[g][0]*0.125f)*er0;
                float p1 = __expf(s[g][1]*0.125f)*er0;
                float p2 = __expf(s[g][2]*0.125f)*er1;
                float p3 = __expf(s[g][3]*0.125f)*er1;
                l0 += p0 + p1; l1 += p2 + p3;
                rs0 += p0 + p1; rs1 += p2 + p3;
                s[g][0]=p0; s[g][1]=p1; s[g][2]=p2; s[g][3]=p3;
            }
        } else {                               // mixed tile (3 of 16)
            #pragma unroll
            for (int g = 0; g < 8; g++) {
                const int j0 = jt*64 + g*8 + cq2;
                const int t0 = j0 - ia0 + 63;
                const int t8 = t0 - 8;
                int c0 = t0 < 0 ? 0 : (t0 > 126 ? 126 : t0);
                int c1 = t0+1 < 0 ? 0 : (t0+1 > 126 ? 126 : t0+1);
                int c2 = t8 < 0 ? 0 : (t8 > 126 ? 126 : t8);
                int c3 = t8+1 < 0 ? 0 : (t8+1 > 126 ? 126 : t8+1);
                float p0 = __expf((s[g][0] + qb[lr0*132 + c0]) * 0.125f);
                float p1 = __expf((s[g][1] + qb[lr0*132 + c1]) * 0.125f);
                float p2 = __expf((s[g][2] + qb[(lr0+8)*132 + c2]) * 0.125f);
                float p3 = __expf((s[g][3] + qb[(lr0+8)*132 + c3]) * 0.125f);
                band[lr0*128 + c0]     = __float2half(p0);   // slots 0/126 = ignored garbage
                band[lr0*128 + c1]     = __float2half(p1);
                band[(lr0+8)*128 + c2] = __float2half(p2);
                band[(lr0+8)*128 + c3] = __float2half(p3);
                l0 += p0 + p1; l1 += p2 + p3;
                if (t0   >= 126) rs0 += p0;
                if (t0+1 >= 126) rs0 += p1;
                if (t8   >= 126) rs1 += p2;
                if (t8+1 >= 126) rs1 += p3;
                s[g][0]=p0; s[g][1]=p1; s[g][2]=p2; s[g][3]=p3;
            }
        }
        __syncthreads();
        #pragma unroll
        for (int g = 0; g < 8; g++) {
            const int jl = g*8 + cq2;
            *(__half2*)&ps[lr0*72 + jl]     = __floats2half2_rn(s[g][0], s[g][1]);
            *(__half2*)&ps[(lr0+8)*72 + jl] = __floats2half2_rn(s[g][2], s[g][3]);
        }
        __syncthreads();

        // ---- PV ----
        const h16* vb = vs + cur*KBUF;
        #pragma unroll
        for (int kk = 0; kk < 4; kk++) {
            const int k0 = kk*16;
            uint32_t a[4];
            a[0] = ldh2(&ps[(lr0  )*72 + k0 + cq2    ]);
            a[1] = ldh2(&ps[(lr0+8)*72 + k0 + cq2    ]);
            a[2] = ldh2(&ps[(lr0  )*72 + k0 + cq2 + 8]);
            a[3] = ldh2(&ps[(lr0+8)*72 + k0 + cq2 + 8]);
            #pragma unroll
            for (int g = 0; g < 8; g++) {
                uint32_t b[2];
                b[0] = ldh2(&vb[(g*8+r)*72 + k0 + cq2    ]);
                b[1] = ldh2(&vb[(g*8+r)*72 + k0 + cq2 + 8]);
                mma16(o[g], a, b);
            }
        }
    }

    // ---- epilogue ----
    // band in-band sums (t = 1..125), per thread strided by cq
    float bs0 = 0.f, bs1 = 0.f;
    for (int t = 1 + cq; t <= 125; t += 4) {
        bs0 += __half2float(band[lr0*128 + t]);
        bs1 += __half2float(band[(lr0+8)*128 + t]);
    }
    #pragma unroll
    for (int off = 1; off <= 2; off <<= 1) {
        l0  += __shfl_xor_sync(0xffffffffu, l0,  off);
        l1  += __shfl_xor_sync(0xffffffffu, l1,  off);
        rs0 += __shfl_xor_sync(0xffffffffu, rs0, off);
        rs1 += __shfl_xor_sync(0xffffffffu, rs1, off);
        bs0 += __shfl_xor_sync(0xffffffffu, bs0, off);
        bs1 += __shfl_xor_sync(0xffffffffu, bs1, off);
    }
    const float ls0 = l0 - rs0 - bs0;
    const float ls1 = l1 - rs1 - bs1;
    const float inv0 = 1.f / l0, inv1 = 1.f / l1;
    #pragma unroll
    for (int g = 0; g < 8; g++) {
        o[g][0] *= inv0; o[g][1] *= inv0; o[g][2] *= inv1; o[g][3] *= inv1;
    }
    __syncthreads();

    // rp_v^T [64 d][128 t] into vs region; wb (normalized) into wbh overlay
    for (int e = tid; e < 64*16; e += 128) {
        int d = e >> 4, ch = e & 15;
        cpa16(s2u(vs + d*136 + ch*8), g_rpvt + (size_t)d*NTABP + ch*8);
    }
    cp_commit();
    for (int t = cq; t < 128; t += 4) {
        float v0 = 0.f, v1 = 0.f;
        if (t == 0)        { v0 = ls0*inv0; v1 = ls1*inv1; }
        else if (t == 126) { v0 = rs0*inv0; v1 = rs1*inv1; }
        else if (t < 126) {
            int j0 = ia0 + t - 63;
            int j1 = j0 + 8;
            if (j0 >= 0 && j0 < NS) v0 = __half2float(band[lr0*128 + t]) * inv0;
            if (j1 >= 0 && j1 < NS) v1 = __half2float(band[(lr0+8)*128 + t]) * inv1;
        }
        wbh[lr0*136 + t]     = __float2half(v0);
        wbh[(lr0+8)*136 + t] = __float2half(v1);
    }
    cp_wait<0>();
    __syncthreads();

    #pragma unroll
    for (int kk = 0; kk < 8; kk++) {
        const int k0 = kk*16;
        uint32_t a[4];
        a[0] = ldh2(&wbh[(lr0  )*136 + k0 + cq2    ]);
        a[1] = ldh2(&wbh[(lr0+8)*136 + k0 + cq2    ]);
        a[2] = ldh2(&wbh[(lr0  )*136 + k0 + cq2 + 8]);
        a[3] = ldh2(&wbh[(lr0+8)*136 + k0 + cq2 + 8]);
        #pragma unroll
        for (int g = 0; g < 8; g++) {
            uint32_t b[2];
            b[0] = ldh2(&vs[(g*8+r)*136 + k0 + cq2    ]);
            b[1] = ldh2(&vs[(g*8+r)*136 + k0 + cq2 + 8]);
            mma16(o[g], a, b);
        }
    }

    const int b = bn >> 4, n = bn & 15;
    #pragma unroll
    for (int g = 0; g < 8; g++) {
        const int d = g*8 + cq2;
        h16* p0 = g_ao + ((size_t)(b*NS + i0 + lr0))*NHID + n*NHD + d;
        h16* p1 = g_ao + ((size_t)(b*NS + i0 + lr0 + 8))*NHID + n*NHD + d;
        *(__half2*)p0 = __floats2half2_rn(o[g][0], o[g][1]);
        *(__half2*)p1 = __floats2half2_rn(o[g][2], o[g][3]);
    }
}

// =============================================================================
// K5: final FC, 128x128 tiles, fp16 MMA.  grid (32, 8), 256 threads.
// =============================================================================
__global__ __launch_bounds__(256) void fc_mma(const float* __restrict__ bfc,
                                              float* __restrict__ out)
{
    extern __shared__ char smc[];
    h16* As = (h16*)smc;
    h16* Bs = (h16*)(smc + 2*T_BUF*2);
    const int tid = threadIdx.x, lane = tid & 31, wid = tid >> 5;
    const int wm = wid & 1, wn = wid >> 1;
    const int m0 = blockIdx.x * 128, o0 = blockIdx.y * 128;

    const h16* A0 = g_ao + (size_t)m0*NHID;
    const h16* B0 = g_wfc + (size_t)o0*NHID;

    float acc[4][4][4];
    #pragma unroll
    for (int f = 0; f < 4; f++)
        #pragma unroll
        for (int g = 0; g < 4; g++)
            #pragma unroll
            for (int e = 0; e < 4; e++) acc[f][g][e] = 0.f;

    load_t(s2u(As), A0, NHID, tid);
    load_t(s2u(Bs), B0, NHID, tid);
    cp_commit();
    for (int kt = 0; kt < 16; kt++) {
        if (kt + 1 < 16) {
            int nb = (kt+1) & 1;
            load_t(s2u(As + nb*T_BUF), A0 + (kt+1)*64, NHID, tid);
            load_t(s2u(Bs + nb*T_BUF), B0 + (kt+1)*64, NHID, tid);
            cp_commit();
            cp_wait<1>();
        } else cp_wait<0>();
        __syncthreads();
        mma_tile(As + (kt&1)*T_BUF, Bs + (kt&1)*T_BUF, acc, wm, wn, lane);
        __syncthreads();
    }

    const int r = lane >> 2, cq = lane & 3;
    #pragma unroll
    for (int f = 0; f < 4; f++) {
        int m = m0 + wm*64 + f*16 + r;
        #pragma unroll
        for (int g = 0; g < 4; g++) {
            int o = o0 + wn*32 + g*8 + 2*cq;
            float b0 = bfc[o], b1 = bfc[o+1];
            *(float2*)&out[(size_t)m*NHID + o]     = make_float2(acc[f][g][0]+b0, acc[f][g][1]+b1);
            *(float2*)&out[(size_t)(m+8)*NHID + o] = make_float2(acc[f][g][2]+b0, acc[f][g][3]+b1);
        }
    }
}

// =============================================================================
extern "C" void kernel_launch(void* const* d_in, const int* in_sizes, int n_in,
                              void* d_out, int out_size)
{
    (void)in_sizes; (void)n_in; (void)out_size;
    const float* query = (const float*)d_in[0];
    const float* key   = (const float*)d_in[1];
    const float* value = (const float*)d_in[2];
    const float* Wq    = (const float*)d_in[3];
    const float* Wk    = (const float*)d_in[4];
    const float* Wv    = (const float*)d_in[5];
    const float* bq    = (const float*)d_in[6];
    const float* bk    = (const float*)d_in[7];
    const float* bv    = (const float*)d_in[8];
    const float* rpk   = (const float*)d_in[9];
    const float* rpv   = (const float*)d_in[10];
    const float* Wfc   = (const float*)d_in[11];
    const float* bfc   = (const float*)d_in[12];
    float* out = (float*)d_out;

    cudaFuncSetAttribute(proj_mma,   cudaFuncAttributeMaxDynamicSharedMemorySize, SMEM_GEMM);
    cudaFuncSetAttribute(fc_mma,     cudaFuncAttributeMaxDynamicSharedMemorySize, SMEM_GEMM);
    cudaFuncSetAttribute(attn_fused, cudaFuncAttributeMaxDynamicSharedMemorySize, ATTN_SMEM);

    cvt3_kernel<<<dim3(4096, 3), 256>>>(query, key, value);          // 1
    prep_kernel<<<dim3(16, 16, 3), 256>>>(Wq, Wk, Wv, rpv, rpk);     // 2
    proj_mma<<<dim3(32, 8, 3), 256, SMEM_GEMM>>>(bq, bk, bv);        // 3
    attn_fused<<<dim3(16, 64), 128, ATTN_SMEM>>>();                  // 4 <- profiled
    cvtw_kernel<<<1024, 256>>>(Wfc);                                 // 5
    fc_mma<<<dim3(32, 8), 256, SMEM_GEMM>>>(bfc, out);               // 6
}

// round 10
// speedup vs baseline: 7.9194x; 1.0254x over previous
#include <cuda_runtime.h>
#include <cuda_fp16.h>
#include <cstdint>

#define NB    4
#define NS    1024
#define NHID  1024
#define NHEAD 16
#define NHD   64
#define NTAB  127
#define NTABP 128
#define BHS   (NB*NHEAD*NS)   // 65536
#define NM    (NB*NS)         // 4096

typedef __half h16;

// ---------------- scratch (device globals; no allocations allowed) ----------------
__device__ h16  g_x  [(size_t)3*NM*NHID];             // fp16 inputs (q,k,v)
__device__ h16  g_wt [(size_t)3*NHEAD*NHD*NHID];      // W^T per head fp16
__device__ h16  g_wfc[(size_t)NHID*NHID];             // Wfc fp16 ([o][k])
__device__ h16  g_q  [(size_t)BHS*NHD];               // q  [bn][s][d]
__device__ h16  g_k  [(size_t)BHS*NHD];               // k  [bn][s][d]
__device__ h16  g_vt [(size_t)BHS*NHD];               // v^T [bn][d][s]
__device__ h16  g_rpvt[NHD*NTABP];                    // rp_v^T (col 127 = 0)
__device__ h16  g_rpkp[NTABP*NHD];                    // rp_k padded [t][d]
__device__ h16  g_ao [(size_t)NM*NHID];               // attn out [b*s][hid]

// =============================== helpers =====================================
__device__ __forceinline__ uint32_t s2u(const void* p) {
    uint32_t a;
    asm("{ .reg .u64 t; cvta.to.shared.u64 t, %1; cvt.u32.u64 %0, t; }" : "=r"(a) : "l"(p));
    return a;
}
__device__ __forceinline__ void cpa16(uint32_t d, const void* s) {
    asm volatile("cp.async.cg.shared.global [%0], [%1], 16;" :: "r"(d), "l"(s));
}
__device__ __forceinline__ void cp_commit() { asm volatile("cp.async.commit_group;"); }
template<int N> __device__ __forceinline__ void cp_wait() {
    asm volatile("cp.async.wait_group %0;" :: "n"(N));
}
__device__ __forceinline__ void mma16(float* c, const uint32_t* a, const uint32_t* b) {
    asm volatile(
        "mma.sync.aligned.m16n8k16.row.col.f32.f16.f16.f32 "
        "{%0,%1,%2,%3}, {%4,%5,%6,%7}, {%8,%9}, {%0,%1,%2,%3};"
        : "+f"(c[0]), "+f"(c[1]), "+f"(c[2]), "+f"(c[3])
        : "r"(a[0]), "r"(a[1]), "r"(a[2]), "r"(a[3]), "r"(b[0]), "r"(b[1]));
}
__device__ __forceinline__ uint32_t ldh2(const h16* p) { return *(const uint32_t*)p; }
__device__ __forceinline__ uint32_t pk2(float x, float y) {
    __half2 h = __floats2half2_rn(x, y);
    return *(uint32_t*)&h;
}

#define TS 72
#define T_BUF (128*TS)
#define SMEM_GEMM (4*T_BUF*2)   // 73728 B

__device__ __forceinline__ void load_t(uint32_t ts, const h16* __restrict__ G, int ld, int tid) {
    #pragma unroll
    for (int i = 0; i < 4; i++) {
        int idx = tid + i*256;
        int m = idx >> 3, ch = idx & 7;
        cpa16(ts + (uint32_t)(m*TS + ch*8)*2, G + (size_t)m*ld + ch*8);
    }
}

__device__ __forceinline__ void mma_tile(const h16* __restrict__ As, const h16* __restrict__ Bs,
                                         float acc[4][4][4], int wm, int wn, int lane) {
    const int r = lane >> 2, cq2 = (lane & 3)*2;
    #pragma unroll
    for (int ks = 0; ks < 4; ks++) {
        const int k0 = ks*16;
        uint32_t a[4][4], b[4][2];
        #pragma unroll
        for (int f = 0; f < 4; f++) {
            const int bm = wm*64 + f*16;
            a[f][0] = ldh2(&As[(bm + r    )*TS + k0 + cq2    ]);
            a[f][1] = ldh2(&As[(bm + r + 8)*TS + k0 + cq2    ]);
            a[f][2] = ldh2(&As[(bm + r    )*TS + k0 + cq2 + 8]);
            a[f][3] = ldh2(&As[(bm + r + 8)*TS + k0 + cq2 + 8]);
        }
        #pragma unroll
        for (int g = 0; g < 4; g++) {
            const int bn = wn*32 + g*8;
            b[g][0] = ldh2(&Bs[(bn + r)*TS + k0 + cq2    ]);
            b[g][1] = ldh2(&Bs[(bn + r)*TS + k0 + cq2 + 8]);
        }
        #pragma unroll
        for (int f = 0; f < 4; f++)
            #pragma unroll
            for (int g = 0; g < 4; g++) mma16(acc[f][g], a[f], b[g]);
    }
}

// =============================================================================
__global__ __launch_bounds__(256) void cvt3_kernel(const float* __restrict__ q,
                                                   const float* __restrict__ k,
                                                   const float* __restrict__ v)
{
    int i = blockIdx.x * 256 + threadIdx.x;
    int mode = blockIdx.y;
    const float* in = (mode == 0) ? q : ((mode == 1) ? k : v);
    h16* dst = g_x + (size_t)mode*NM*NHID;
    float4 val = ((const float4*)in)[i];
    __half2 h0 = __floats2half2_rn(val.x, val.y);
    __half2 h1 = __floats2half2_rn(val.z, val.w);
    uint2 u; u.x = *(uint32_t*)&h0; u.y = *(uint32_t*)&h1;
    ((uint2*)dst)[i] = u;
}

__global__ __launch_bounds__(256) void cvtw_kernel(const float* __restrict__ in)
{
    int i = blockIdx.x * 256 + threadIdx.x;
    float4 v = ((const float4*)in)[i];
    __half2 h0 = __floats2half2_rn(v.x, v.y);
    __half2 h1 = __floats2half2_rn(v.z, v.w);
    uint2 u; u.x = *(uint32_t*)&h0; u.y = *(uint32_t*)&h1;
    ((uint2*)g_wfc)[i] = u;
}

__global__ __launch_bounds__(256) void prep_kernel(const float* __restrict__ wq,
                                                   const float* __restrict__ wk,
                                                   const float* __restrict__ wv,
                                                   const float* __restrict__ rpv,
                                                   const float* __restrict__ rpk)
{
    __shared__ float tile[64*65];
    const int hb = blockIdx.x, n = blockIdx.y, op = blockIdx.z;
    const float* W = (op==0 ? wq : (op==1 ? wk : wv)) + ((size_t)n*NHID + hb*64)*NHD;
    for (int e = threadIdx.x; e < 64*64; e += 256) {
        int h = e >> 6, d = e & 63;
        tile[h*65 + d] = W[(size_t)h*NHD + d];
    }
    __syncthreads();
    size_t ob = ((size_t)(op*NHEAD + n)*NHD)*NHID + hb*64;
    for (int e = threadIdx.x; e < 64*64; e += 256) {
        int d = e >> 6, h = e & 63;
        g_wt[ob + (size_t)d*NHID + h] = __float2half(tile[h*65 + d]);
    }
    if (op == 0 && n == 0 && hb == 0) {
        for (int e = threadIdx.x; e < NHD*NTABP; e += 256) {
            int d = e >> 7, t = e & 127;
            float v = (t < NTAB) ? rpv[(size_t)t*NHD + d] : 0.f;
            g_rpvt[(size_t)d*NTABP + t] = __float2half(v);
        }
    }
    if (op == 0 && n == 0 && hb == 1) {
        for (int e = threadIdx.x; e < NTABP*NHD; e += 256) {
            int t = e >> 6, d = e & 63;
            float v = (t < NTAB) ? rpk[(size_t)t*NHD + d] : 0.f;
            g_rpkp[e] = __float2half(v);
        }
    }
}

// =============================================================================
// K1: QKV projection, 128x128 tiles, fp16 MMA.  grid (32, 8, 3), 256 thr.
// =============================================================================
__global__ __launch_bounds__(256) void proj_mma(const float* __restrict__ bq_,
                                                const float* __restrict__ bk_,
                                                const float* __restrict__ bv_)
{
    extern __shared__ char smc[];
    h16* As = (h16*)smc;
    h16* Bs = (h16*)(smc + 2*T_BUF*2);
    const int tid = threadIdx.x, lane = tid & 31, wid = tid >> 5;
    const int wm = wid & 1, wn = wid >> 1;
    const int m0 = blockIdx.x * 128, ny = blockIdx.y, op = blockIdx.z;

    const h16* A0 = g_x + (size_t)op*NM*NHID + (size_t)m0*NHID;
    const h16* B0 = g_wt + (size_t)(op*NHEAD + ny*2)*NHD*NHID;

    float acc[4][4][4];
    #pragma unroll
    for (int f = 0; f < 4; f++)
        #pragma unroll
        for (int g = 0; g < 4; g++)
            #pragma unroll
            for (int e = 0; e < 4; e++) acc[f][g][e] = 0.f;

    load_t(s2u(As), A0, NHID, tid);
    load_t(s2u(Bs), B0, NHID, tid);
    cp_commit();
    for (int kt = 0; kt < 16; kt++) {
        if (kt + 1 < 16) {
            int nb = (kt+1) & 1;
            load_t(s2u(As + nb*T_BUF), A0 + (kt+1)*64, NHID, tid);
            load_t(s2u(Bs + nb*T_BUF), B0 + (kt+1)*64, NHID, tid);
            cp_commit();
            cp_wait<1>();
        } else cp_wait<0>();
        __syncthreads();
        mma_tile(As + (kt&1)*T_BUF, Bs + (kt&1)*T_BUF, acc, wm, wn, lane);
        __syncthreads();
    }

    const int b = m0 >> 10, s0 = m0 & 1023;
    const int r = lane >> 2, cq = lane & 3;
    const float* bias = (op == 0) ? bq_ : ((op == 1) ? bk_ : bv_);

    if (op < 2) {
        h16* outb = op ? g_k : g_q;
        #pragma unroll
        for (int f = 0; f < 4; f++) {
            int ml = wm*64 + f*16 + r;
            #pragma unroll
            for (int g = 0; g < 4; g++) {
                int dp = wn*32 + g*8 + 2*cq;
                int nh = ny*2 + (dp >> 6), d = dp & 63;
                float b0 = bias[nh*NHD + d], b1 = bias[nh*NHD + d + 1];
                h16* out = outb + ((size_t)(b*NHEAD + nh)*NS + s0)*NHD;
                *(__half2*)&out[(size_t)ml*NHD + d] =
                    __floats2half2_rn(acc[f][g][0]+b0, acc[f][g][1]+b1);
                *(__half2*)&out[(size_t)(ml+8)*NHD + d] =
                    __floats2half2_rn(acc[f][g][2]+b0, acc[f][g][3]+b1);
            }
        }
    } else {
        h16* stage = (h16*)smc;                   // [128 dp][136]
        #pragma unroll
        for (int f = 0; f < 4; f++) {
            int ml = wm*64 + f*16 + r;
            #pragma unroll
            for (int g = 0; g < 4; g++) {
                int dp = wn*32 + g*8 + 2*cq;
                int nh = ny*2 + (dp >> 6), d = dp & 63;
                float b0 = bias[nh*NHD + d], b1 = bias[nh*NHD + d + 1];
                stage[(dp  )*136 + ml    ] = __float2half(acc[f][g][0] + b0);
                stage[(dp+1)*136 + ml    ] = __float2half(acc[f][g][1] + b1);
                stage[(dp  )*136 + ml + 8] = __float2half(acc[f][g][2] + b0);
                stage[(dp+1)*136 + ml + 8] = __float2half(acc[f][g][3] + b1);
            }
        }
        __syncthreads();
        const int dp = tid >> 1, half_ = tid & 1;
        const int nh = ny*2 + (dp >> 6), d = dp & 63;
        h16* dst = g_vt + ((size_t)(b*NHEAD + nh)*NHD + d)*NS + s0 + half_*64;
        const uint4* src = (const uint4*)(stage + dp*136 + half_*64);
        #pragma unroll
        for (int j = 0; j < 8; j++) ((uint4*)dst)[j] = src[j];
    }
}

// =============================================================================
// K3: fused flash attention, fp16 MMA, register P->PV pass (no ps smem).
// smem bytes: qs[64][72]h @0 | ks 2x[64][72]h @9216 | vs 2x[64][72]h @27648
//   band[64][128]h @46080 | qb[64][132]f @62464   = 96256
// =============================================================================
#define ATTN_SMEM 96256
#define KBUF (64*72)

__global__ __launch_bounds__(128) void attn_fused()
{
    extern __shared__ char smc[];
    h16*  qs   = (h16*)(smc);
    h16*  ks   = (h16*)(smc + 9216);
    h16*  vs   = (h16*)(smc + 27648);
    h16*  band = (h16*)(smc + 46080);
    float* qb  = (float*)(smc + 62464);
    h16*  wbh  = (h16*)(smc + 62464);    // epilogue overlay on qb: [64][136]h

    const int tid = threadIdx.x, lane = tid & 31, w = tid >> 5;
    const int i0 = blockIdx.x * 64, bn = blockIdx.y;
    const int r = lane >> 2, cq = lane & 3;
    const int cq2 = cq*2;
    const int lr0 = w*16 + r;
    const int ia0 = i0 + lr0;

    // q tile + rp_k overlay on ks
    const h16* qg = g_q + ((size_t)bn*NS + i0)*NHD;
    for (int e = tid; e < 64*8; e += 128) {
        int row = e >> 3, ch = e & 7;
        cpa16(s2u(qs + row*72 + ch*8), qg + (size_t)row*NHD + ch*8);
    }
    h16* rkp = ks;
    for (int e = tid; e < 128*8; e += 128) {
        int row = e >> 3, ch = e & 7;
        cpa16(s2u(rkp + row*72 + ch*8), g_rpkp + (size_t)row*NHD + ch*8);
    }
    // zero band
    for (int e = tid; e < 64*128/8; e += 128)
        ((uint4*)band)[e] = make_uint4(0,0,0,0);
    cp_commit();
    cp_wait<0>();
    __syncthreads();

    // ---- prologue: qb[row][t] = q . rp_k[t] ----
    {
        float qacc[16][4];
        #pragma unroll
        for (int g = 0; g < 16; g++)
            #pragma unroll
            for (int e = 0; e < 4; e++) qacc[g][e] = 0.f;
        #pragma unroll
        for (int kk = 0; kk < 4; kk++) {
            const int k0 = kk*16;
            uint32_t a[4];
            a[0] = ldh2(&qs[(lr0  )*72 + k0 + cq2    ]);
            a[1] = ldh2(&qs[(lr0+8)*72 + k0 + cq2    ]);
            a[2] = ldh2(&qs[(lr0  )*72 + k0 + cq2 + 8]);
            a[3] = ldh2(&qs[(lr0+8)*72 + k0 + cq2 + 8]);
            #pragma unroll
            for (int g = 0; g < 16; g++) {
                uint32_t b[2];
                b[0] = ldh2(&rkp[(g*8+r)*72 + k0 + cq2    ]);
                b[1] = ldh2(&rkp[(g*8+r)*72 + k0 + cq2 + 8]);
                mma16(qacc[g], a, b);
            }
        }
        #pragma unroll
        for (int g = 0; g < 16; g++) {
            const int t = g*8 + cq2;
            *(float2*)&qb[lr0*132 + t]     = make_float2(qacc[g][0], qacc[g][1]);
            *(float2*)&qb[(lr0+8)*132 + t] = make_float2(qacc[g][2], qacc[g][3]);
        }
    }
    __syncthreads();

    // per-row far-region multipliers
    const float el0 = __expf(qb[lr0*132 +   0] * 0.125f);
    const float er0 = __expf(qb[lr0*132 + 126] * 0.125f);
    const float el1 = __expf(qb[(lr0+8)*132 +   0] * 0.125f);
    const float er1 = __expf(qb[(lr0+8)*132 + 126] * 0.125f);

    const h16* kg = g_k + (size_t)bn*NS*NHD;
    const h16* vg = g_vt + (size_t)bn*NHD*NS;

    auto ldK = [&](int jt, int buf) {
        for (int e = tid; e < 64*8; e += 128) {
            int row = e >> 3, ch = e & 7;
            cpa16(s2u(ks + buf*KBUF + row*72 + ch*8), kg + (size_t)(jt*64+row)*NHD + ch*8);
        }
    };
    auto ldV = [&](int jt, int buf) {
        for (int e = tid; e < 64*8; e += 128) {
            int d = e >> 3, ch = e & 7;
            cpa16(s2u(vs + buf*KBUF + d*72 + ch*8), vg + (size_t)d*NS + jt*64 + ch*8);
        }
    };
    ldK(0, 0); ldV(0, 0); cp_commit();

    float o[8][4];
    #pragma unroll
    for (int g = 0; g < 8; g++)
        #pragma unroll
        for (int e = 0; e < 4; e++) o[g][e] = 0.f;
    float l0 = 0.f, l1 = 0.f;
    float rs0 = 0.f, rs1 = 0.f;

    for (int jt = 0; jt < 16; jt++) {
        const int cur = jt & 1;
        __syncthreads();      // prior MMA reads of buf cur^1 done -> safe to prefetch
        if (jt < 15) { ldK(jt+1, cur^1); ldV(jt+1, cur^1); cp_commit(); cp_wait<1>(); }
        else cp_wait<0>();
        __syncthreads();

        // ---- QK^T (64 x 64) ----
        float s[8][4];
        #pragma unroll
        for (int g = 0; g < 8; g++)
            #pragma unroll
            for (int e = 0; e < 4; e++) s[g][e] = 0.f;
        const h16* kb = ks + cur*KBUF;
        #pragma unroll
        for (int kk = 0; kk < 4; kk++) {
            const int k0 = kk*16;
            uint32_t a[4];
            a[0] = ldh2(&qs[(lr0  )*72 + k0 + cq2    ]);
            a[1] = ldh2(&qs[(lr0+8)*72 + k0 + cq2    ]);
            a[2] = ldh2(&qs[(lr0  )*72 + k0 + cq2 + 8]);
            a[3] = ldh2(&qs[(lr0+8)*72 + k0 + cq2 + 8]);
            #pragma unroll
            for (int g = 0; g < 8; g++) {
                uint32_t b[2];
                b[0] = ldh2(&kb[(g*8+r)*72 + k0 + cq2    ]);
                b[1] = ldh2(&kb[(g*8+r)*72 + k0 + cq2 + 8]);
                mma16(s[g], a, b);
            }
        }

        // ---- softmax numerators: specialized by tile/band relation ----
        const int d64 = jt*64 - i0;
        if (d64 <= -128) {
            #pragma unroll
            for (int g = 0; g < 8; g++) {
                float p0 = __expf(s[g][0]*0.125f)*el0;
                float p1 = __expf(s[g][1]*0.125f)*el0;
                float p2 = __expf(s[g][2]*0.125f)*el1;
                float p3 = __expf(s[g][3]*0.125f)*el1;
                l0 += p0 + p1; l1 += p2 + p3;
                s[g][0]=p0; s[g][1]=p1; s[g][2]=p2; s[g][3]=p3;
            }
        } else if (d64 >= 128) {
            #pragma unroll
            for (int g = 0; g < 8; g++) {
                float p0 = __expf(s[g][0]*0.125f)*er0;
                float p1 = __expf(s[g][1]*0.125f)*er0;
                float p2 = __expf(s[g][2]*0.125f)*er1;
                float p3 = __expf(s[g][3]*0.125f)*er1;
                l0 += p0 + p1; l1 += p2 + p3;
                rs0 += p0 + p1; rs1 += p2 + p3;
                s[g][0]=p0; s[g][1]=p1; s[g][2]=p2; s[g][3]=p3;
            }
        } else {
            #pragma unroll
            for (int g = 0; g < 8; g++) {
                const int j0 = jt*64 + g*8 + cq2;
                const int t0 = j0 - ia0 + 63;
                const int t8 = t0 - 8;
                int c0 = t0 < 0 ? 0 : (t0 > 126 ? 126 : t0);
                int c1 = t0+1 < 0 ? 0 : (t0+1 > 126 ? 126 : t0+1);
                int c2 = t8 < 0 ? 0 : (t8 > 126 ? 126 : t8);
                int c3 = t8+1 < 0 ? 0 : (t8+1 > 126 ? 126 : t8+1);
                float p0 = __expf((s[g][0] + qb[lr0*132 + c0]) * 0.125f);
                float p1 = __expf((s[g][1] + qb[lr0*132 + c1]) * 0.125f);
                float p2 = __expf((s[g][2] + qb[(lr0+8)*132 + c2]) * 0.125f);
                float p3 = __expf((s[g][3] + qb[(lr0+8)*132 + c3]) * 0.125f);
                band[lr0*128 + c0]     = __float2half(p0);
                band[lr0*128 + c1]     = __float2half(p1);
                band[(lr0+8)*128 + c2] = __float2half(p2);
                band[(lr0+8)*128 + c3] = __float2half(p3);
                l0 += p0 + p1; l1 += p2 + p3;
                if (t0   >= 126) rs0 += p0;
                if (t0+1 >= 126) rs0 += p1;
                if (t8   >= 126) rs1 += p2;
                if (t8+1 >= 126) rs1 += p3;
                s[g][0]=p0; s[g][1]=p1; s[g][2]=p2; s[g][3]=p3;
            }
        }

        // ---- PV directly from register fragments (no smem round trip) ----
        // A-frag for k-chunk kk: rows lr0/lr0+8, j-cols kk*16 + {cq2, cq2+8}
        //   a0 = s[2kk][0:1] (r,c) | a1 = s[2kk][2:3] (r+8,c)
        //   a2 = s[2kk+1][0:1] (r,c+8) | a3 = s[2kk+1][2:3] (r+8,c+8)
        const h16* vb = vs + cur*KBUF;
        #pragma unroll
        for (int kk = 0; kk < 4; kk++) {
            const int k0 = kk*16;
            uint32_t a[4];
            a[0] = pk2(s[2*kk  ][0], s[2*kk  ][1]);
            a[1] = pk2(s[2*kk  ][2], s[2*kk  ][3]);
            a[2] = pk2(s[2*kk+1][0], s[2*kk+1][1]);
            a[3] = pk2(s[2*kk+1][2], s[2*kk+1][3]);
            #pragma unroll
            for (int g = 0; g < 8; g++) {
                uint32_t b[2];
                b[0] = ldh2(&vb[(g*8+r)*72 + k0 + cq2    ]);
                b[1] = ldh2(&vb[(g*8+r)*72 + k0 + cq2 + 8]);
                mma16(o[g], a, b);
            }
        }
    }

    // ---- epilogue ----
    float bs0 = 0.f, bs1 = 0.f;
    for (int t = 1 + cq; t <= 125; t += 4) {
        bs0 += __half2float(band[lr0*128 + t]);
        bs1 += __half2float(band[(lr0+8)*128 + t]);
    }
    #pragma unroll
    for (int off = 1; off <= 2; off <<= 1) {
        l0  += __shfl_xor_sync(0xffffffffu, l0,  off);
        l1  += __shfl_xor_sync(0xffffffffu, l1,  off);
        rs0 += __shfl_xor_sync(0xffffffffu, rs0, off);
        rs1 += __shfl_xor_sync(0xffffffffu, rs1, off);
        bs0 += __shfl_xor_sync(0xffffffffu, bs0, off);
        bs1 += __shfl_xor_sync(0xffffffffu, bs1, off);
    }
    const float ls0 = l0 - rs0 - bs0;
    const float ls1 = l1 - rs1 - bs1;
    const float inv0 = 1.f / l0, inv1 = 1.f / l1;
    #pragma unroll
    for (int g = 0; g < 8; g++) {
        o[g][0] *= inv0; o[g][1] *= inv0; o[g][2] *= inv1; o[g][3] *= inv1;
    }
    __syncthreads();

    // rp_v^T [64 d][128 t] into vs region; wb (normalized) into wbh overlay
    for (int e = tid; e < 64*16; e += 128) {
        int d = e >> 4, ch = e & 15;
        cpa16(s2u(vs + d*136 + ch*8), g_rpvt + (size_t)d*NTABP + ch*8);
    }
    cp_commit();
    for (int t = cq; t < 128; t += 4) {
        float v0 = 0.f, v1 = 0.f;
        if (t == 0)        { v0 = ls0*inv0; v1 = ls1*inv1; }
        else if (t == 126) { v0 = rs0*inv0; v1 = rs1*inv1; }
        else if (t < 126) {
            int j0 = ia0 + t - 63;
            int j1 = j0 + 8;
            if (j0 >= 0 && j0 < NS) v0 = __half2float(band[lr0*128 + t]) * inv0;
            if (j1 >= 0 && j1 < NS) v1 = __half2float(band[(lr0+8)*128 + t]) * inv1;
        }
        wbh[lr0*136 + t]     = __float2half(v0);
        wbh[(lr0+8)*136 + t] = __float2half(v1);
    }
    cp_wait<0>();
    __syncthreads();

    #pragma unroll
    for (int kk = 0; kk < 8; kk++) {
        const int k0 = kk*16;
        uint32_t a[4];
        a[0] = ldh2(&wbh[(lr0  )*136 + k0 + cq2    ]);
        a[1] = ldh2(&wbh[(lr0+8)*136 + k0 + cq2    ]);
        a[2] = ldh2(&wbh[(lr0  )*136 + k0 + cq2 + 8]);
        a[3] = ldh2(&wbh[(lr0+8)*136 + k0 + cq2 + 8]);
        #pragma unroll
        for (int g = 0; g < 8; g++) {
            uint32_t b[2];
            b[0] = ldh2(&vs[(g*8+r)*136 + k0 + cq2    ]);
            b[1] = ldh2(&vs[(g*8+r)*136 + k0 + cq2 + 8]);
            mma16(o[g], a, b);
        }
    }

    const int b = bn >> 4, n = bn & 15;
    #pragma unroll
    for (int g = 0; g < 8; g++) {
        const int d = g*8 + cq2;
        h16* p0 = g_ao + ((size_t)(b*NS + i0 + lr0))*NHID + n*NHD + d;
        h16* p1 = g_ao + ((size_t)(b*NS + i0 + lr0 + 8))*NHID + n*NHD + d;
        *(__half2*)p0 = __floats2half2_rn(o[g][0], o[g][1]);
        *(__half2*)p1 = __floats2half2_rn(o[g][2], o[g][3]);
    }
}

// =============================================================================
// K5: final FC, 128x128 tiles, fp16 MMA.  grid (32, 8), 256 threads.
// =============================================================================
__global__ __launch_bounds__(256) void fc_mma(const float* __restrict__ bfc,
                                              float* __restrict__ out)
{
    extern __shared__ char smc[];
    h16* As = (h16*)smc;
    h16* Bs = (h16*)(smc + 2*T_BUF*2);
    const int tid = threadIdx.x, lane = tid & 31, wid = tid >> 5;
    const int wm = wid & 1, wn = wid >> 1;
    const int m0 = blockIdx.x * 128, o0 = blockIdx.y * 128;

    const h16* A0 = g_ao + (size_t)m0*NHID;
    const h16* B0 = g_wfc + (size_t)o0*NHID;

    float acc[4][4][4];
    #pragma unroll
    for (int f = 0; f < 4; f++)
        #pragma unroll
        for (int g = 0; g < 4; g++)
            #pragma unroll
            for (int e = 0; e < 4; e++) acc[f][g][e] = 0.f;

    load_t(s2u(As), A0, NHID, tid);
    load_t(s2u(Bs), B0, NHID, tid);
    cp_commit();
    for (int kt = 0; kt < 16; kt++) {
        if (kt + 1 < 16) {
            int nb = (kt+1) & 1;
            load_t(s2u(As + nb*T_BUF), A0 + (kt+1)*64, NHID, tid);
            load_t(s2u(Bs + nb*T_BUF), B0 + (kt+1)*64, NHID, tid);
            cp_commit();
            cp_wait<1>();
        } else cp_wait<0>();
        __syncthreads();
        mma_tile(As + (kt&1)*T_BUF, Bs + (kt&1)*T_BUF, acc, wm, wn, lane);
        __syncthreads();
    }

    const int r = lane >> 2, cq = lane & 3;
    #pragma unroll
    for (int f = 0; f < 4; f++) {
        int m = m0 + wm*64 + f*16 + r;
        #pragma unroll
        for (int g = 0; g < 4; g++) {
            int o = o0 + wn*32 + g*8 + 2*cq;
            float b0 = bfc[o], b1 = bfc[o+1];
            *(float2*)&out[(size_t)m*NHID + o]     = make_float2(acc[f][g][0]+b0, acc[f][g][1]+b1);
            *(float2*)&out[(size_t)(m+8)*NHID + o] = make_float2(acc[f][g][2]+b0, acc[f][g][3]+b1);
        }
    }
}

// =============================================================================
extern "C" void kernel_launch(void* const* d_in, const int* in_sizes, int n_in,
                              void* d_out, int out_size)
{
    (void)in_sizes; (void)n_in; (void)out_size;
    const float* query = (const float*)d_in[0];
    const float* key   = (const float*)d_in[1];
    const float* value = (const float*)d_in[2];
    const float* Wq    = (const float*)d_in[3];
    const float* Wk    = (const float*)d_in[4];
    const float* Wv    = (const float*)d_in[5];
    const float* bq    = (const float*)d_in[6];
    const float* bk    = (const float*)d_in[7];
    const float* bv    = (const float*)d_in[8];
    const float* rpk   = (const float*)d_in[9];
    const float* rpv   = (const float*)d_in[10];
    const float* Wfc   = (const float*)d_in[11];
    const float* bfc   = (const float*)d_in[12];
    float* out = (float*)d_out;

    cudaFuncSetAttribute(proj_mma,   cudaFuncAttributeMaxDynamicSharedMemorySize, SMEM_GEMM);
    cudaFuncSetAttribute(fc_mma,     cudaFuncAttributeMaxDynamicSharedMemorySize, SMEM_GEMM);
    cudaFuncSetAttribute(attn_fused, cudaFuncAttributeMaxDynamicSharedMemorySize, ATTN_SMEM);

    cvt3_kernel<<<dim3(4096, 3), 256>>>(query, key, value);          // 1
    prep_kernel<<<dim3(16, 16, 3), 256>>>(Wq, Wk, Wv, rpv, rpk);     // 2
    proj_mma<<<dim3(32, 8, 3), 256, SMEM_GEMM>>>(bq, bk, bv);        // 3
    attn_fused<<<dim3(16, 64), 128, ATTN_SMEM>>>();                  // 4 <- profiled
    cvtw_kernel<<<1024, 256>>>(Wfc);                                 // 5
    fc_mma<<<dim3(32, 8), 256, SMEM_GEMM>>>(bfc, out);               // 6
}